// round 2
// baseline (speedup 1.0000x reference)
#include <cuda_runtime.h>
#include <float.h>
#include <math.h>

// Problem constants
#define BB 8
#define NN 2048
#define NP (BB*NN)        // 16384 points
#define CIN 3
#define DD 64
#define KNB 8
#define LV 3
#define H1 256
#define H2 128

// ---------------- scratch (device globals; no allocation allowed) --------------
__device__ float g_feat [NP*DD];       // [16384,64]
__device__ float g_P    [NP*DD];       // feat @ W2[:64]
__device__ float g_Q    [NP*DD];       // feat @ W2[64:]
__device__ float g_fw   [NP*LV];       // sigmoid suppressor weights
__device__ int   g_idx  [NP*KNB];      // knn indices (within batch)
__device__ float g_multi[NP*LV*DD];    // [16384,192]
__device__ float g_G1   [NP*H1];       // [16384,256]
__device__ float g_G2   [NP*H2];       // [16384,128]

__device__ __forceinline__ float leaky(float v){ return v > 0.f ? v : 0.2f*v; }

// ---------------- kernel 1: per-point feature transform + suppressor -----------
__global__ void k_point(const float* __restrict__ x,
                        const float* __restrict__ W1, const float* __restrict__ b1,
                        const float* __restrict__ g1, const float* __restrict__ be1,
                        const float* __restrict__ Ws1, const float* __restrict__ bs1,
                        const float* __restrict__ Ws2, const float* __restrict__ bs2)
{
    int p = blockIdx.x;          // point id 0..16383
    int d = threadIdx.x;         // 0..63
    float x0 = x[p*3+0], x1 = x[p*3+1], x2 = x[p*3+2];

    __shared__ float hS[DD];

    // feature transform + eval BN affine + leaky
    float f = x0*W1[d] + x1*W1[DD+d] + x2*W1[2*DD+d] + b1[d];
    f = f*g1[d] + be1[d];
    g_feat[p*DD + d] = leaky(f);

    // suppressor hidden (relu)
    float h = x0*Ws1[d] + x1*Ws1[DD+d] + x2*Ws1[2*DD+d] + bs1[d];
    hS[d] = h > 0.f ? h : 0.f;
    __syncthreads();

    if (d < LV) {
        float s = bs2[d];
        #pragma unroll 16
        for (int e = 0; e < DD; e++) s += hS[e]*Ws2[e*LV + d];
        g_fw[p*LV + d] = 1.f/(1.f + expf(-s));
    }
}

// ---------------- kernel 2: brute force KNN (top-8 smallest d2) ----------------
__global__ void k_knn(const float* __restrict__ x)
{
    __shared__ float s0[NN], s1[NN], s2[NN], sn[NN];
    int b = blockIdx.y;
    int i = blockIdx.x*256 + threadIdx.x;

    for (int j = threadIdx.x; j < NN; j += 256) {
        float a = x[(b*NN + j)*3 + 0];
        float c = x[(b*NN + j)*3 + 1];
        float e = x[(b*NN + j)*3 + 2];
        s0[j] = a; s1[j] = c; s2[j] = e;
        sn[j] = a*a + c*c + e*e;
    }
    __syncthreads();

    float xi0 = s0[i], xi1 = s1[i], xi2 = s2[i], ni = sn[i];

    float bd[KNB]; int bi[KNB];
    #pragma unroll
    for (int t = 0; t < KNB; t++) { bd[t] = FLT_MAX; bi[t] = 0; }

    for (int j = 0; j < NN; j++) {
        float dot = xi0*s0[j] + xi1*s1[j] + xi2*s2[j];
        float d2  = ni + sn[j] - 2.f*dot;
        if (d2 < bd[KNB-1]) {
            bd[KNB-1] = d2; bi[KNB-1] = j;
            #pragma unroll
            for (int t = KNB-1; t > 0; t--) {
                if (bd[t] < bd[t-1]) {
                    float td = bd[t]; bd[t] = bd[t-1]; bd[t-1] = td;
                    int   ti = bi[t]; bi[t] = bi[t-1]; bi[t-1] = ti;
                }
            }
        }
    }
    int p = b*NN + i;
    #pragma unroll
    for (int t = 0; t < KNB; t++) g_idx[p*KNB + t] = bi[t];
}

// ---------------- generic 64x64-tile fp32 GEMM, optional affine+leaky epilogue -
// C[M,N] = op(A[M,K] @ B[K,N]); EPI: v=((v+bias)*gamma+beta), leaky
template<bool EPI>
__global__ void gemm64(const float* __restrict__ A, const float* __restrict__ Bw,
                       const float* __restrict__ bias, const float* __restrict__ gamma,
                       const float* __restrict__ beta, float* __restrict__ C,
                       int M, int Nn, int Kk)
{
    __shared__ float As[16][64];
    __shared__ float Bs[16][64];
    const int t  = threadIdx.x;
    const int tx = t & 15, ty = t >> 4;
    const int m0 = blockIdx.x*64, n0 = blockIdx.y*64;
    const int arow = t >> 2,  akq = (t & 3) * 4;
    const int brow = t >> 4,  bnq = (t & 15) * 4;

    float acc[4][4] = {};

    for (int k0 = 0; k0 < Kk; k0 += 16) {
        float4 av = *(const float4*)(A + (size_t)(m0 + arow)*Kk + k0 + akq);
        As[akq+0][arow] = av.x; As[akq+1][arow] = av.y;
        As[akq+2][arow] = av.z; As[akq+3][arow] = av.w;
        *(float4*)&Bs[brow][bnq] = *(const float4*)(Bw + (size_t)(k0 + brow)*Nn + n0 + bnq);
        __syncthreads();
        #pragma unroll
        for (int kk = 0; kk < 16; kk++) {
            float4 a = *(const float4*)&As[kk][ty*4];
            float4 b = *(const float4*)&Bs[kk][tx*4];
            float ar[4] = {a.x,a.y,a.z,a.w};
            float br[4] = {b.x,b.y,b.z,b.w};
            #pragma unroll
            for (int i = 0; i < 4; i++)
                #pragma unroll
                for (int j = 0; j < 4; j++)
                    acc[i][j] += ar[i]*br[j];
        }
        __syncthreads();
    }

    #pragma unroll
    for (int j = 0; j < 4; j++) {
        int n = n0 + tx*4 + j;
        float bsv = EPI ? bias[n]  : 0.f;
        float gm  = EPI ? gamma[n] : 1.f;
        float bt  = EPI ? beta[n]  : 0.f;
        #pragma unroll
        for (int i = 0; i < 4; i++) {
            float v = acc[i][j];
            if (EPI) { v = (v + bsv)*gm + bt; v = leaky(v); }
            C[(size_t)(m0 + ty*4 + i)*Nn + n] = v;
        }
    }
}

// ---------------- kernel 3: gather neighbors, conv, max-agg, build multi -------
__global__ void k_agg(const float* __restrict__ b2, const float* __restrict__ g2,
                      const float* __restrict__ be2)
{
    int p = blockIdx.x;      // 0..16383
    int d = threadIdx.x;     // 0..63
    int b = p >> 11;         // batch (N=2048)

    float pv = g_P[p*DD + d];
    float gg = g2[d];
    float cc = b2[d]*gg + be2[d];     // fold bias into affine

    const int* id = &g_idx[p*KNB];
    float m = -FLT_MAX;
    #pragma unroll
    for (int k = 0; k < KNB; k++) {
        int q = b*NN + id[k];
        float v = (pv + g_Q[q*DD + d])*gg + cc;
        v = leaky(v);
        m = fmaxf(m, v);
    }
    float f0 = g_fw[p*LV+0], f1 = g_fw[p*LV+1], f2 = g_fw[p*LV+2];
    g_multi[p*LV*DD + 0*DD + d] = m*f0;
    g_multi[p*LV*DD + 1*DD + d] = m*f1;
    g_multi[p*LV*DD + 2*DD + d] = m*f2;
}

// ---------------- kernel 4: final 128->3 + residual ----------------------------
__global__ void k_final(const float* __restrict__ x,
                        const float* __restrict__ Wf3, const float* __restrict__ bf3,
                        float* __restrict__ out)
{
    int p = blockIdx.x*128 + threadIdx.x;   // point id
    const float* row = &g_G2[p*H2];
    float s0 = bf3[0], s1 = bf3[1], s2 = bf3[2];
    #pragma unroll 8
    for (int e = 0; e < H2; e++) {
        float v = row[e];
        s0 += v*Wf3[e*3+0];
        s1 += v*Wf3[e*3+1];
        s2 += v*Wf3[e*3+2];
    }
    out[p*3+0] = x[p*3+0] + 0.1f*s0;
    out[p*3+1] = x[p*3+1] + 0.1f*s1;
    out[p*3+2] = x[p*3+2] + 0.1f*s2;
}

// ---------------- launch -------------------------------------------------------
extern "C" void kernel_launch(void* const* d_in, const int* in_sizes, int n_in,
                              void* d_out, int out_size)
{
    const float* x   = (const float*)d_in[0];
    const float* W1  = (const float*)d_in[1];
    const float* b1  = (const float*)d_in[2];
    const float* g1  = (const float*)d_in[3];
    const float* be1 = (const float*)d_in[4];
    const float* W2  = (const float*)d_in[5];
    const float* b2  = (const float*)d_in[6];
    const float* g2  = (const float*)d_in[7];
    const float* be2 = (const float*)d_in[8];
    const float* Ws1 = (const float*)d_in[9];
    const float* bs1 = (const float*)d_in[10];
    const float* Ws2 = (const float*)d_in[11];
    const float* bs2 = (const float*)d_in[12];
    const float* Wf1 = (const float*)d_in[13];
    const float* bf1 = (const float*)d_in[14];
    const float* gf1 = (const float*)d_in[15];
    const float* bef1= (const float*)d_in[16];
    const float* Wf2 = (const float*)d_in[17];
    const float* bf2 = (const float*)d_in[18];
    const float* gf2 = (const float*)d_in[19];
    const float* bef2= (const float*)d_in[20];
    const float* Wf3 = (const float*)d_in[21];
    const float* bf3 = (const float*)d_in[22];
    float* out = (float*)d_out;

    void *p_feat, *p_P, *p_Q, *p_multi, *p_G1, *p_G2;
    cudaGetSymbolAddress(&p_feat,  g_feat);
    cudaGetSymbolAddress(&p_P,     g_P);
    cudaGetSymbolAddress(&p_Q,     g_Q);
    cudaGetSymbolAddress(&p_multi, g_multi);
    cudaGetSymbolAddress(&p_G1,    g_G1);
    cudaGetSymbolAddress(&p_G2,    g_G2);

    // 1. per-point feature + suppressor
    k_point<<<NP, 64>>>(x, W1, b1, g1, be1, Ws1, bs1, Ws2, bs2);

    // 2. KNN
    k_knn<<<dim3(NN/256, BB), 256>>>(x);

    // 3. P = feat @ W2[:64], Q = feat @ W2[64:]   (raw, no epilogue)
    gemm64<false><<<dim3(NP/64, 1), 256>>>((const float*)p_feat, W2,
        nullptr, nullptr, nullptr, (float*)p_P, NP, DD, DD);
    gemm64<false><<<dim3(NP/64, 1), 256>>>((const float*)p_feat, W2 + DD*DD,
        nullptr, nullptr, nullptr, (float*)p_Q, NP, DD, DD);

    // 4. gather + conv + max + multi-scale weighting
    k_agg<<<NP, 64>>>(b2, g2, be2);

    // 5. fusion layer 1: [16384,192]@[192,256] + affine + leaky
    gemm64<true><<<dim3(NP/64, H1/64), 256>>>((const float*)p_multi, Wf1,
        bf1, gf1, bef1, (float*)p_G1, NP, H1, LV*DD);

    // 6. fusion layer 2: [16384,256]@[256,128] + affine + leaky
    gemm64<true><<<dim3(NP/64, H2/64), 256>>>((const float*)p_G1, Wf2,
        bf2, gf2, bef2, (float*)p_G2, NP, H2, H1);

    // 7. final 128->3 + residual
    k_final<<<NP/128, 128>>>(x, Wf3, bf3, out);
}

// round 3
// speedup vs baseline: 1.1497x; 1.1497x over previous
#include <cuda_runtime.h>
#include <float.h>
#include <math.h>

// Problem constants
#define BB 8
#define NN 2048
#define NP (BB*NN)        // 16384 points
#define DD 64
#define KNB 8
#define LV 3
#define H1 256
#define H2 128

// ---------------- scratch (device globals; no allocation allowed) --------------
__device__ float g_feat [NP*DD];
__device__ float g_P    [NP*DD];
__device__ float g_Q    [NP*DD];
__device__ float g_fw   [NP*LV];
__device__ int   g_idx  [NP*KNB];
__device__ float g_multi[NP*LV*DD];    // [16384,192]
__device__ float g_G1   [NP*H1];
__device__ float g_G2   [NP*H2];

__device__ __forceinline__ float leaky(float v){ return v > 0.f ? v : 0.2f*v; }

// ---------------- kernel 1: per-point feature transform + suppressor -----------
// 256 threads = 4 points x 64 lanes
__global__ void k_point(const float* __restrict__ x,
                        const float* __restrict__ W1, const float* __restrict__ b1,
                        const float* __restrict__ g1, const float* __restrict__ be1,
                        const float* __restrict__ Ws1, const float* __restrict__ bs1,
                        const float* __restrict__ Ws2, const float* __restrict__ bs2)
{
    int sub = threadIdx.x >> 6;            // 0..3
    int d   = threadIdx.x & 63;            // 0..63
    int p   = blockIdx.x*4 + sub;
    float x0 = x[p*3+0], x1 = x[p*3+1], x2 = x[p*3+2];

    __shared__ float hS[4][DD];

    float f = x0*W1[d] + x1*W1[DD+d] + x2*W1[2*DD+d] + b1[d];
    f = f*g1[d] + be1[d];
    g_feat[p*DD + d] = leaky(f);

    float h = x0*Ws1[d] + x1*Ws1[DD+d] + x2*Ws1[2*DD+d] + bs1[d];
    hS[sub][d] = h > 0.f ? h : 0.f;
    __syncthreads();

    if (d < LV) {
        float s = bs2[d];
        #pragma unroll 16
        for (int e = 0; e < DD; e++) s += hS[sub][e]*Ws2[e*LV + d];
        g_fw[p*LV + d] = 1.f/(1.f + expf(-s));
    }
}

// ---------------- kernel 2: brute force KNN (top-8 smallest d2) ----------------
// 128 threads/block, 1 query/thread, all 2048 candidates staged in smem
__global__ void k_knn(const float* __restrict__ x)
{
    __shared__ float s0[NN], s1[NN], s2[NN], sn[NN];
    int b = blockIdx.y;
    int i = blockIdx.x*128 + threadIdx.x;

    for (int j = threadIdx.x; j < NN; j += 128) {
        float a = x[(b*NN + j)*3 + 0];
        float c = x[(b*NN + j)*3 + 1];
        float e = x[(b*NN + j)*3 + 2];
        s0[j] = a; s1[j] = c; s2[j] = e;
        sn[j] = a*a + c*c + e*e;
    }
    __syncthreads();

    float xi0 = s0[i], xi1 = s1[i], xi2 = s2[i], ni = sn[i];

    float bd[KNB]; int bi[KNB];
    #pragma unroll
    for (int t = 0; t < KNB; t++) { bd[t] = FLT_MAX; bi[t] = 0; }

    #pragma unroll 4
    for (int j = 0; j < NN; j++) {
        float dot = xi0*s0[j] + xi1*s1[j] + xi2*s2[j];
        float d2  = ni + sn[j] - 2.f*dot;
        if (d2 < bd[KNB-1]) {
            bd[KNB-1] = d2; bi[KNB-1] = j;
            #pragma unroll
            for (int t = KNB-1; t > 0; t--) {
                if (bd[t] < bd[t-1]) {
                    float td = bd[t]; bd[t] = bd[t-1]; bd[t-1] = td;
                    int   ti = bi[t]; bi[t] = bi[t-1]; bi[t-1] = ti;
                }
            }
        }
    }
    int p = b*NN + i;
    #pragma unroll
    for (int t = 0; t < KNB; t++) g_idx[p*KNB + t] = bi[t];
}

// ---------------- high-ILP SGEMM: BM=128, BK=16, 8xTN per thread ---------------
// C[M,N] = op(A[M,K] @ B[K,N]); EPI: v = leaky((v+bias)*gamma+beta)
// BN=128 -> TN=8 (2 float4 B-frags); BN=64 -> TN=4
template<int BN, int TN, bool EPI>
__global__ void __launch_bounds__(256)
gemmT(const float* __restrict__ A, const float* __restrict__ Bw,
      const float* __restrict__ bias, const float* __restrict__ gamma,
      const float* __restrict__ beta, float* __restrict__ C,
      int M, int Nn, int Kk)
{
    constexpr int BM = 128, BK = 16, TM = 8;
    __shared__ float As[2][BK][BM];
    __shared__ float Bs[2][BK][BN];

    const int t  = threadIdx.x;
    const int tx = t % (BN/TN);     // 16 column groups
    const int ty = t / (BN/TN);     // 16 row groups
    const int m0 = blockIdx.x*BM, n0 = blockIdx.y*BN;

    // A tile load: 128 rows x 16 cols = 2048 floats; 8 floats (2xfloat4)/thread
    const int a_r = t >> 1;
    const int a_c = (t & 1) * 8;
    // B tile load: 16 rows x BN cols
    const int b_r = t >> 4;
    const int b_c = (BN == 128) ? (t & 15) * 8 : (t & 15) * 4;

    const float* Aptr = A + (size_t)(m0 + a_r)*Kk + a_c;
    const float* Bptr = Bw + (size_t)b_r*Nn + n0 + b_c;

    float acc[TM][TN] = {};

    float4 pa0 = *(const float4*)(Aptr);
    float4 pa1 = *(const float4*)(Aptr + 4);
    float4 pb0 = *(const float4*)(Bptr);
    float4 pb1 = (BN == 128) ? *(const float4*)(Bptr + 4) : make_float4(0,0,0,0);

    As[0][a_c+0][a_r] = pa0.x; As[0][a_c+1][a_r] = pa0.y;
    As[0][a_c+2][a_r] = pa0.z; As[0][a_c+3][a_r] = pa0.w;
    As[0][a_c+4][a_r] = pa1.x; As[0][a_c+5][a_r] = pa1.y;
    As[0][a_c+6][a_r] = pa1.z; As[0][a_c+7][a_r] = pa1.w;
    *(float4*)&Bs[0][b_r][b_c] = pb0;
    if (BN == 128) *(float4*)&Bs[0][b_r][b_c+4] = pb1;
    __syncthreads();

    const int ntiles = Kk / BK;
    int buf = 0;
    for (int tk = 0; tk < ntiles; tk++) {
        if (tk + 1 < ntiles) {
            const float* Ap = Aptr + (tk+1)*BK;
            const float* Bp = Bptr + (size_t)(tk+1)*BK*Nn;
            pa0 = *(const float4*)(Ap);
            pa1 = *(const float4*)(Ap + 4);
            pb0 = *(const float4*)(Bp);
            if (BN == 128) pb1 = *(const float4*)(Bp + 4);
        }
        #pragma unroll
        for (int kk = 0; kk < BK; kk++) {
            float a[TM], bfr[TN];
            *(float4*)&a[0] = *(const float4*)&As[buf][kk][ty*TM];
            *(float4*)&a[4] = *(const float4*)&As[buf][kk][ty*TM + 4];
            *(float4*)&bfr[0] = *(const float4*)&Bs[buf][kk][tx*TN];
            if (TN == 8) *(float4*)&bfr[4] = *(const float4*)&Bs[buf][kk][tx*TN + 4];
            #pragma unroll
            for (int i = 0; i < TM; i++)
                #pragma unroll
                for (int j = 0; j < TN; j++)
                    acc[i][j] += a[i]*bfr[j];
        }
        if (tk + 1 < ntiles) {
            buf ^= 1;
            As[buf][a_c+0][a_r] = pa0.x; As[buf][a_c+1][a_r] = pa0.y;
            As[buf][a_c+2][a_r] = pa0.z; As[buf][a_c+3][a_r] = pa0.w;
            As[buf][a_c+4][a_r] = pa1.x; As[buf][a_c+5][a_r] = pa1.y;
            As[buf][a_c+6][a_r] = pa1.z; As[buf][a_c+7][a_r] = pa1.w;
            *(float4*)&Bs[buf][b_r][b_c] = pb0;
            if (BN == 128) *(float4*)&Bs[buf][b_r][b_c+4] = pb1;
            __syncthreads();
        }
    }

    // epilogue
    float bs_[TN], gm_[TN], bt_[TN];
    #pragma unroll
    for (int j = 0; j < TN; j++) {
        int n = n0 + tx*TN + j;
        bs_[j] = EPI ? bias[n]  : 0.f;
        gm_[j] = EPI ? gamma[n] : 1.f;
        bt_[j] = EPI ? beta[n]  : 0.f;
    }
    #pragma unroll
    for (int i = 0; i < TM; i++) {
        int m = m0 + ty*TM + i;
        float v[TN];
        #pragma unroll
        for (int j = 0; j < TN; j++) {
            float w = acc[i][j];
            if (EPI) { w = (w + bs_[j])*gm_[j] + bt_[j]; w = leaky(w); }
            v[j] = w;
        }
        float* Crow = C + (size_t)m*Nn + n0 + tx*TN;
        *(float4*)&Crow[0] = *(float4*)&v[0];
        if (TN == 8) *(float4*)&Crow[4] = *(float4*)&v[4];
    }
}

// ---------------- kernel 3: gather neighbors, conv, max-agg, build multi -------
// 256 threads = 4 points x 64 lanes
__global__ void k_agg(const float* __restrict__ b2, const float* __restrict__ g2,
                      const float* __restrict__ be2)
{
    int sub = threadIdx.x >> 6;
    int d   = threadIdx.x & 63;
    int p   = blockIdx.x*4 + sub;
    int b   = p >> 11;

    float pv = g_P[p*DD + d];
    float gg = g2[d];
    float cc = b2[d]*gg + be2[d];

    const int* id = &g_idx[p*KNB];
    float m = -FLT_MAX;
    #pragma unroll
    for (int k = 0; k < KNB; k++) {
        int q = b*NN + id[k];
        float v = (pv + g_Q[q*DD + d])*gg + cc;
        v = leaky(v);
        m = fmaxf(m, v);
    }
    float f0 = g_fw[p*LV+0], f1 = g_fw[p*LV+1], f2 = g_fw[p*LV+2];
    g_multi[p*LV*DD + 0*DD + d] = m*f0;
    g_multi[p*LV*DD + 1*DD + d] = m*f1;
    g_multi[p*LV*DD + 2*DD + d] = m*f2;
}

// ---------------- kernel 4: final 128->3 + residual ----------------------------
__global__ void k_final(const float* __restrict__ x,
                        const float* __restrict__ Wf3, const float* __restrict__ bf3,
                        float* __restrict__ out)
{
    int p = blockIdx.x*128 + threadIdx.x;
    const float* row = &g_G2[p*H2];
    float s0 = bf3[0], s1 = bf3[1], s2 = bf3[2];
    #pragma unroll 8
    for (int e = 0; e < H2; e++) {
        float v = row[e];
        s0 += v*Wf3[e*3+0];
        s1 += v*Wf3[e*3+1];
        s2 += v*Wf3[e*3+2];
    }
    out[p*3+0] = x[p*3+0] + 0.1f*s0;
    out[p*3+1] = x[p*3+1] + 0.1f*s1;
    out[p*3+2] = x[p*3+2] + 0.1f*s2;
}

// ---------------- launch -------------------------------------------------------
extern "C" void kernel_launch(void* const* d_in, const int* in_sizes, int n_in,
                              void* d_out, int out_size)
{
    const float* x   = (const float*)d_in[0];
    const float* W1  = (const float*)d_in[1];
    const float* b1  = (const float*)d_in[2];
    const float* g1  = (const float*)d_in[3];
    const float* be1 = (const float*)d_in[4];
    const float* W2  = (const float*)d_in[5];
    const float* b2  = (const float*)d_in[6];
    const float* g2  = (const float*)d_in[7];
    const float* be2 = (const float*)d_in[8];
    const float* Ws1 = (const float*)d_in[9];
    const float* bs1 = (const float*)d_in[10];
    const float* Ws2 = (const float*)d_in[11];
    const float* bs2 = (const float*)d_in[12];
    const float* Wf1 = (const float*)d_in[13];
    const float* bf1 = (const float*)d_in[14];
    const float* gf1 = (const float*)d_in[15];
    const float* bef1= (const float*)d_in[16];
    const float* Wf2 = (const float*)d_in[17];
    const float* bf2 = (const float*)d_in[18];
    const float* gf2 = (const float*)d_in[19];
    const float* bef2= (const float*)d_in[20];
    const float* Wf3 = (const float*)d_in[21];
    const float* bf3 = (const float*)d_in[22];
    float* out = (float*)d_out;

    void *p_feat, *p_P, *p_Q, *p_multi, *p_G1, *p_G2;
    cudaGetSymbolAddress(&p_feat,  g_feat);
    cudaGetSymbolAddress(&p_P,     g_P);
    cudaGetSymbolAddress(&p_Q,     g_Q);
    cudaGetSymbolAddress(&p_multi, g_multi);
    cudaGetSymbolAddress(&p_G1,    g_G1);
    cudaGetSymbolAddress(&p_G2,    g_G2);

    // 1. per-point feature + suppressor
    k_point<<<NP/4, 256>>>(x, W1, b1, g1, be1, Ws1, bs1, Ws2, bs2);

    // 2. KNN
    k_knn<<<dim3(NN/128, BB), 128>>>(x);

    // 3. P = feat @ W2[:64], Q = feat @ W2[64:]
    gemmT<64,4,false><<<dim3(NP/128, 1), 256>>>((const float*)p_feat, W2,
        nullptr, nullptr, nullptr, (float*)p_P, NP, DD, DD);
    gemmT<64,4,false><<<dim3(NP/128, 1), 256>>>((const float*)p_feat, W2 + DD*DD,
        nullptr, nullptr, nullptr, (float*)p_Q, NP, DD, DD);

    // 4. gather + conv + max + multi-scale weighting
    k_agg<<<NP/4, 256>>>(b2, g2, be2);

    // 5. fusion layer 1: [16384,192]@[192,256]
    gemmT<128,8,true><<<dim3(NP/128, H1/128), 256>>>((const float*)p_multi, Wf1,
        bf1, gf1, bef1, (float*)p_G1, NP, H1, LV*DD);

    // 6. fusion layer 2: [16384,256]@[256,128]
    gemmT<128,8,true><<<dim3(NP/128, H2/128), 256>>>((const float*)p_G1, Wf2,
        bf2, gf2, bef2, (float*)p_G2, NP, H2, H1);

    // 7. final 128->3 + residual
    k_final<<<NP/128, 128>>>(x, Wf3, bf3, out);
}

// round 5
// speedup vs baseline: 1.4007x; 1.2184x over previous
#include <cuda_runtime.h>
#include <float.h>
#include <math.h>
#include <stdint.h>

// Problem constants
#define BB 8
#define NN 2048
#define NP (BB*NN)        // 16384 points
#define DD 64
#define KNB 8
#define LV 3
#define H1 256
#define H2 128

// ---------------- scratch (device globals; no allocation allowed) --------------
__device__ float g_feat [NP*DD];       // [16384,64]
__device__ float g_PQ   [NP*128];      // [16384,128]  cols 0-63 = P, 64-127 = Q
__device__ float g_fw   [NP*LV];
__device__ int   g_idx  [NP*KNB];
__device__ float g_multi[NP*LV*DD];    // [16384,192]
__device__ float g_G1   [NP*H1];
__device__ float g_G2   [NP*H2];
__device__ float g_Bt1  [H1*192];      // Wf1^T  [256][192]
__device__ float g_Bt2  [H2*H1];       // Wf2^T  [128][256]
__device__ float g_Btpq [128*DD];      // [P|Q] weight, [128][64]

__device__ __forceinline__ float leaky(float v){ return v > 0.f ? v : 0.2f*v; }

__device__ __forceinline__ uint32_t smem_u32(const void* p) {
    uint32_t a;
    asm("{ .reg .u64 t; cvta.to.shared.u64 t, %1; cvt.u32.u64 %0, t; }" : "=r"(a) : "l"(p));
    return a;
}

#define CP_ASYNC16(d, s) do { \
    size_t _gs = __cvta_generic_to_global(s); \
    asm volatile("cp.async.cg.shared.global [%0], [%1], 16;" :: "r"(d), "l"(_gs) : "memory"); \
} while (0)
#define CP_COMMIT()  asm volatile("cp.async.commit_group;" ::: "memory")
#define CP_WAIT(n)   asm volatile("cp.async.wait_group %0;" :: "n"(n) : "memory")

__device__ __forceinline__ void mma_tf32(float* c, const uint32_t* a, const uint32_t* b) {
    asm volatile(
        "mma.sync.aligned.m16n8k8.row.col.f32.tf32.tf32.f32 "
        "{%0,%1,%2,%3}, {%4,%5,%6,%7}, {%8,%9}, {%0,%1,%2,%3};"
        : "+f"(c[0]), "+f"(c[1]), "+f"(c[2]), "+f"(c[3])
        : "r"(a[0]), "r"(a[1]), "r"(a[2]), "r"(a[3]), "r"(b[0]), "r"(b[1]));
}

// ---------------- kernel 1: per-point feature transform + suppressor -----------
__global__ void k_point(const float* __restrict__ x,
                        const float* __restrict__ W1, const float* __restrict__ b1,
                        const float* __restrict__ g1, const float* __restrict__ be1,
                        const float* __restrict__ Ws1, const float* __restrict__ bs1,
                        const float* __restrict__ Ws2, const float* __restrict__ bs2)
{
    int sub = threadIdx.x >> 6;
    int d   = threadIdx.x & 63;
    int p   = blockIdx.x*4 + sub;
    float x0 = x[p*3+0], x1 = x[p*3+1], x2 = x[p*3+2];

    __shared__ float hS[4][DD];

    float f = x0*W1[d] + x1*W1[DD+d] + x2*W1[2*DD+d] + b1[d];
    f = f*g1[d] + be1[d];
    g_feat[p*DD + d] = leaky(f);

    float h = x0*Ws1[d] + x1*Ws1[DD+d] + x2*Ws1[2*DD+d] + bs1[d];
    hS[sub][d] = h > 0.f ? h : 0.f;
    __syncthreads();

    if (d < LV) {
        float s = bs2[d];
        #pragma unroll 16
        for (int e = 0; e < DD; e++) s += hS[sub][e]*Ws2[e*LV + d];
        g_fw[p*LV + d] = 1.f/(1.f + expf(-s));
    }
}

// ---------------- kernel: transpose small weights to [N][K] K-major ------------
__global__ void k_prep(const float* __restrict__ W2, const float* __restrict__ Wf1,
                       const float* __restrict__ Wf2)
{
    int i = blockIdx.x*256 + threadIdx.x;
    if (i < H1*192) { int n = i/192, k = i%192; g_Bt1[i] = Wf1[k*H1 + n]; }
    if (i < H2*H1)  { int n = i/H1,  k = i%H1;  g_Bt2[i] = Wf2[k*H2 + n]; }
    if (i < 128*DD) {
        int n = i/DD, k = i%DD;
        g_Btpq[i] = (n < 64) ? W2[k*DD + n] : W2[(64 + k)*DD + (n - 64)];
    }
}

// ---------------- kernel 2: brute force KNN (top-8 smallest d2) ----------------
__global__ void k_knn(const float* __restrict__ x)
{
    __shared__ float s0[NN], s1[NN], s2[NN], sn[NN];
    int b = blockIdx.y;
    int i = blockIdx.x*128 + threadIdx.x;

    for (int j = threadIdx.x; j < NN; j += 128) {
        float a = x[(b*NN + j)*3 + 0];
        float c = x[(b*NN + j)*3 + 1];
        float e = x[(b*NN + j)*3 + 2];
        s0[j] = a; s1[j] = c; s2[j] = e;
        sn[j] = a*a + c*c + e*e;
    }
    __syncthreads();

    float xi0 = s0[i], xi1 = s1[i], xi2 = s2[i], ni = sn[i];

    float bd[KNB]; int bi[KNB];
    #pragma unroll
    for (int t = 0; t < KNB; t++) { bd[t] = FLT_MAX; bi[t] = 0; }

    #pragma unroll 4
    for (int j = 0; j < NN; j++) {
        float dot = xi0*s0[j] + xi1*s1[j] + xi2*s2[j];
        float d2  = ni + sn[j] - 2.f*dot;
        if (d2 < bd[KNB-1]) {
            bd[KNB-1] = d2; bi[KNB-1] = j;
            #pragma unroll
            for (int t = KNB-1; t > 0; t--) {
                if (bd[t] < bd[t-1]) {
                    float td = bd[t]; bd[t] = bd[t-1]; bd[t-1] = td;
                    int   ti = bi[t]; bi[t] = bi[t-1]; bi[t-1] = ti;
                }
            }
        }
    }
    int p = b*NN + i;
    #pragma unroll
    for (int t = 0; t < KNB; t++) g_idx[p*KNB + t] = bi[t];
}

// ---------------- tf32 tensor-core GEMM (mma.sync, baseline PTX) ---------------
// C[M, n0:n0+128] = op(A[M,K] @ Bt[n0:n0+128, K]^T)
// 256 thr, block tile 128x128, warp tile 64x32, BK=32, cp.async double buffer.
// smem rows padded to 36 floats -> conflict-free tf32 fragment loads.
#define SROW 36
#define SBUF (128*SROW)          // floats per buffer
#define SMEM_GEMM (4*SBUF*4)     // bytes: 2 bufs A + 2 bufs B = 73728

template<bool EPI>
__global__ void __launch_bounds__(256)
mma_gemm(const float* __restrict__ A, const float* __restrict__ Bt,
         const float* __restrict__ bias, const float* __restrict__ gamma,
         const float* __restrict__ beta, float* __restrict__ C,
         int Ntot, int K)
{
    extern __shared__ float sm[];
    const int t = threadIdx.x, lane = t & 31, wid = t >> 5;
    const int gid = lane >> 2, tig = lane & 3;
    const int wm = (wid & 1) * 64, wn = (wid >> 1) * 32;
    const int m0 = blockIdx.x * 128, n0 = blockIdx.y * 128;

    // global->smem: thread t stages 16 A floats + 16 B floats per tile
    const int lr = t >> 1;            // row 0..127
    const int lk = (t & 1) * 16;      // k offset 0/16
    const float* Ag = A  + (size_t)(m0 + lr)*K + lk;
    const float* Bg = Bt + (size_t)(n0 + lr)*K + lk;

    const uint32_t sbase = smem_u32(sm);
    const uint32_t sA = sbase + (uint32_t)(lr*SROW + lk)*4u;
    const uint32_t sB = sbase + (uint32_t)(2*SBUF + lr*SROW + lk)*4u;

    const int nt = K >> 5;

    #pragma unroll
    for (int q = 0; q < 4; q++) {
        CP_ASYNC16(sA + q*16, Ag + q*4);
        CP_ASYNC16(sB + q*16, Bg + q*4);
    }
    CP_COMMIT();

    float acc[4][4][4] = {};
    int buf = 0;
    for (int kt = 0; kt < nt; kt++) {
        if (kt + 1 < nt) {
            uint32_t off = (uint32_t)((buf ^ 1)*SBUF)*4u;
            const float* Ap = Ag + (kt+1)*32;
            const float* Bp = Bg + (kt+1)*32;
            #pragma unroll
            for (int q = 0; q < 4; q++) {
                CP_ASYNC16(sA + off + q*16, Ap + q*4);
                CP_ASYNC16(sB + off + q*16, Bp + q*4);
            }
            CP_COMMIT();
            CP_WAIT(1);
        } else {
            CP_WAIT(0);
        }
        __syncthreads();

        const float* as = sm + buf*SBUF + wm*SROW;
        const float* bs = sm + 2*SBUF + buf*SBUF + wn*SROW;
        #pragma unroll
        for (int ks = 0; ks < 4; ks++) {
            const int kk = ks*8 + tig;
            uint32_t af[4][4], bf[4][2];
            #pragma unroll
            for (int mf = 0; mf < 4; mf++) {
                const float* ap = as + (mf*16 + gid)*SROW + kk;
                af[mf][0] = __float_as_uint(ap[0]);
                af[mf][1] = __float_as_uint(ap[8*SROW]);
                af[mf][2] = __float_as_uint(ap[4]);
                af[mf][3] = __float_as_uint(ap[8*SROW + 4]);
            }
            #pragma unroll
            for (int nf = 0; nf < 4; nf++) {
                const float* bp = bs + (nf*8 + gid)*SROW + kk;
                bf[nf][0] = __float_as_uint(bp[0]);
                bf[nf][1] = __float_as_uint(bp[4]);
            }
            #pragma unroll
            for (int mf = 0; mf < 4; mf++)
                #pragma unroll
                for (int nf = 0; nf < 4; nf++)
                    mma_tf32(acc[mf][nf], af[mf], bf[nf]);
        }
        __syncthreads();
        buf ^= 1;
    }

    // epilogue: c0,c1 -> (row, col..col+1); c2,c3 -> (row+8, col..col+1)
    #pragma unroll
    for (int mf = 0; mf < 4; mf++) {
        const int row = m0 + wm + mf*16 + gid;
        #pragma unroll
        for (int nf = 0; nf < 4; nf++) {
            const int col = n0 + wn + nf*8 + tig*2;
            float v0 = acc[mf][nf][0], v1 = acc[mf][nf][1];
            float v2 = acc[mf][nf][2], v3 = acc[mf][nf][3];
            if (EPI) {
                float e0 = __ldg(bias+col),  e1 = __ldg(bias+col+1);
                float q0 = __ldg(gamma+col), q1 = __ldg(gamma+col+1);
                float h0 = __ldg(beta+col),  h1 = __ldg(beta+col+1);
                v0 = leaky((v0 + e0)*q0 + h0);
                v1 = leaky((v1 + e1)*q1 + h1);
                v2 = leaky((v2 + e0)*q0 + h0);
                v3 = leaky((v3 + e1)*q1 + h1);
            }
            *(float2*)(C + (size_t)row*Ntot + col)     = make_float2(v0, v1);
            *(float2*)(C + (size_t)(row+8)*Ntot + col) = make_float2(v2, v3);
        }
    }
}

// ---------------- kernel 3: gather neighbors, conv, max-agg, build multi -------
__global__ void k_agg(const float* __restrict__ b2, const float* __restrict__ g2,
                      const float* __restrict__ be2)
{
    int sub = threadIdx.x >> 6;
    int d   = threadIdx.x & 63;
    int p   = blockIdx.x*4 + sub;
    int b   = p >> 11;

    float pv = g_PQ[(size_t)p*128 + d];
    float gg = g2[d];
    float cc = b2[d]*gg + be2[d];

    const int* id = &g_idx[p*KNB];
    float m = -FLT_MAX;
    #pragma unroll
    for (int k = 0; k < KNB; k++) {
        int q = b*NN + id[k];
        float v = (pv + g_PQ[(size_t)q*128 + 64 + d])*gg + cc;
        v = leaky(v);
        m = fmaxf(m, v);
    }
    float f0 = g_fw[p*LV+0], f1 = g_fw[p*LV+1], f2 = g_fw[p*LV+2];
    g_multi[p*LV*DD + 0*DD + d] = m*f0;
    g_multi[p*LV*DD + 1*DD + d] = m*f1;
    g_multi[p*LV*DD + 2*DD + d] = m*f2;
}

// ---------------- kernel 4: final 128->3 + residual ----------------------------
__global__ void k_final(const float* __restrict__ x,
                        const float* __restrict__ Wf3, const float* __restrict__ bf3,
                        float* __restrict__ out)
{
    int p = blockIdx.x*128 + threadIdx.x;
    const float* row = &g_G2[(size_t)p*H2];
    float s0 = bf3[0], s1 = bf3[1], s2 = bf3[2];
    #pragma unroll 8
    for (int e = 0; e < H2; e++) {
        float v = row[e];
        s0 += v*Wf3[e*3+0];
        s1 += v*Wf3[e*3+1];
        s2 += v*Wf3[e*3+2];
    }
    out[p*3+0] = x[p*3+0] + 0.1f*s0;
    out[p*3+1] = x[p*3+1] + 0.1f*s1;
    out[p*3+2] = x[p*3+2] + 0.1f*s2;
}

// ---------------- launch -------------------------------------------------------
extern "C" void kernel_launch(void* const* d_in, const int* in_sizes, int n_in,
                              void* d_out, int out_size)
{
    const float* x   = (const float*)d_in[0];
    const float* W1  = (const float*)d_in[1];
    const float* b1  = (const float*)d_in[2];
    const float* g1  = (const float*)d_in[3];
    const float* be1 = (const float*)d_in[4];
    const float* W2  = (const float*)d_in[5];
    const float* b2  = (const float*)d_in[6];
    const float* g2  = (const float*)d_in[7];
    const float* be2 = (const float*)d_in[8];
    const float* Ws1 = (const float*)d_in[9];
    const float* bs1 = (const float*)d_in[10];
    const float* Ws2 = (const float*)d_in[11];
    const float* bs2 = (const float*)d_in[12];
    const float* Wf1 = (const float*)d_in[13];
    const float* bf1 = (const float*)d_in[14];
    const float* gf1 = (const float*)d_in[15];
    const float* bef1= (const float*)d_in[16];
    const float* Wf2 = (const float*)d_in[17];
    const float* bf2 = (const float*)d_in[18];
    const float* gf2 = (const float*)d_in[19];
    const float* bef2= (const float*)d_in[20];
    const float* Wf3 = (const float*)d_in[21];
    const float* bf3 = (const float*)d_in[22];
    float* out = (float*)d_out;

    void *p_feat, *p_PQ, *p_multi, *p_G1, *p_G2, *p_Bt1, *p_Bt2, *p_Btpq;
    cudaGetSymbolAddress(&p_feat,  g_feat);
    cudaGetSymbolAddress(&p_PQ,    g_PQ);
    cudaGetSymbolAddress(&p_multi, g_multi);
    cudaGetSymbolAddress(&p_G1,    g_G1);
    cudaGetSymbolAddress(&p_G2,    g_G2);
    cudaGetSymbolAddress(&p_Bt1,   g_Bt1);
    cudaGetSymbolAddress(&p_Bt2,   g_Bt2);
    cudaGetSymbolAddress(&p_Btpq,  g_Btpq);

    cudaFuncSetAttribute(mma_gemm<false>, cudaFuncAttributeMaxDynamicSharedMemorySize, SMEM_GEMM);
    cudaFuncSetAttribute(mma_gemm<true>,  cudaFuncAttributeMaxDynamicSharedMemorySize, SMEM_GEMM);

    // 1. per-point feature + suppressor; weight transposes
    k_point<<<NP/4, 256>>>(x, W1, b1, g1, be1, Ws1, bs1, Ws2, bs2);
    k_prep<<<192, 256>>>(W2, Wf1, Wf2);

    // 2. KNN
    k_knn<<<dim3(NN/128, BB), 128>>>(x);

    // 3. [P|Q] = feat @ Btpq^T : [16384,64]@[64,128]
    mma_gemm<false><<<dim3(NP/128, 1), 256, SMEM_GEMM>>>(
        (const float*)p_feat, (const float*)p_Btpq,
        nullptr, nullptr, nullptr, (float*)p_PQ, 128, DD);

    // 4. gather + conv + max + multi-scale weighting
    k_agg<<<NP/4, 256>>>(b2, g2, be2);

    // 5. fusion layer 1: [16384,192]@[192,256]
    mma_gemm<true><<<dim3(NP/128, 2), 256, SMEM_GEMM>>>(
        (const float*)p_multi, (const float*)p_Bt1,
        bf1, gf1, bef1, (float*)p_G1, H1, 192);

    // 6. fusion layer 2: [16384,256]@[256,128]
    mma_gemm<true><<<dim3(NP/128, 1), 256, SMEM_GEMM>>>(
        (const float*)p_G1, (const float*)p_Bt2,
        bf2, gf2, bef2, (float*)p_G2, H2, H1);

    // 7. final 128->3 + residual
    k_final<<<NP/128, 128>>>(x, Wf3, bf3, out);
}

// round 6
// speedup vs baseline: 2.0080x; 1.4335x over previous
#include <cuda_runtime.h>
#include <float.h>
#include <math.h>
#include <stdint.h>

// Problem constants
#define BB 8
#define NN 2048
#define NP (BB*NN)        // 16384 points
#define DD 64
#define KNB 8
#define LV 3
#define H1 256
#define H2 128

// ---------------- scratch (device globals; no allocation allowed) --------------
__device__ float g_feat [NP*DD];       // [16384,64]
__device__ float g_PQ   [NP*128];      // [16384,128]  cols 0-63 = P, 64-127 = Q
__device__ float g_fw   [NP*LV];
__device__ int   g_idx  [NP*KNB];
__device__ float g_multi[NP*LV*DD];    // [16384,192]
__device__ float g_G1   [NP*H1];
__device__ float g_G2   [NP*H2];
__device__ float g_Bt1  [H1*192];      // Wf1^T  [256][192]
__device__ float g_Bt2  [H2*H1];       // Wf2^T  [128][256]
__device__ float g_Btpq [128*DD];      // [P|Q] weight, [128][64]

__device__ __forceinline__ float leaky(float v){ return v > 0.f ? v : 0.2f*v; }

__device__ __forceinline__ uint32_t smem_u32(const void* p) {
    uint32_t a;
    asm("{ .reg .u64 t; cvta.to.shared.u64 t, %1; cvt.u32.u64 %0, t; }" : "=r"(a) : "l"(p));
    return a;
}

#define CP_ASYNC16(d, s) do { \
    size_t _gs = __cvta_generic_to_global(s); \
    asm volatile("cp.async.cg.shared.global [%0], [%1], 16;" :: "r"(d), "l"(_gs) : "memory"); \
} while (0)
#define CP_COMMIT()  asm volatile("cp.async.commit_group;" ::: "memory")
#define CP_WAIT(n)   asm volatile("cp.async.wait_group %0;" :: "n"(n) : "memory")

__device__ __forceinline__ void mma_tf32(float* c, const uint32_t* a, const uint32_t* b) {
    asm volatile(
        "mma.sync.aligned.m16n8k8.row.col.f32.tf32.tf32.f32 "
        "{%0,%1,%2,%3}, {%4,%5,%6,%7}, {%8,%9}, {%0,%1,%2,%3};"
        : "+f"(c[0]), "+f"(c[1]), "+f"(c[2]), "+f"(c[3])
        : "r"(a[0]), "r"(a[1]), "r"(a[2]), "r"(a[3]), "r"(b[0]), "r"(b[1]));
}

// ---------------- kernel 1: point transform + suppressor + weight prep ---------
// blocks [0, NP/4): 4 points each. blocks [NP/4, NP/4+192): weight transposes.
__global__ void k_pp(const float* __restrict__ x,
                     const float* __restrict__ W1, const float* __restrict__ b1,
                     const float* __restrict__ g1, const float* __restrict__ be1,
                     const float* __restrict__ Ws1, const float* __restrict__ bs1,
                     const float* __restrict__ Ws2, const float* __restrict__ bs2,
                     const float* __restrict__ W2, const float* __restrict__ Wf1,
                     const float* __restrict__ Wf2)
{
    if (blockIdx.x >= NP/4) {
        int i = (blockIdx.x - NP/4)*256 + threadIdx.x;
        if (i < H1*192) { int n = i/192, k = i%192; g_Bt1[i] = Wf1[k*H1 + n]; }
        if (i < H2*H1)  { int n = i/H1,  k = i%H1;  g_Bt2[i] = Wf2[k*H2 + n]; }
        if (i < 128*DD) {
            int n = i/DD, k = i%DD;
            g_Btpq[i] = (n < 64) ? W2[k*DD + n] : W2[(64 + k)*DD + (n - 64)];
        }
        return;
    }
    int sub = threadIdx.x >> 6;
    int d   = threadIdx.x & 63;
    int p   = blockIdx.x*4 + sub;
    float x0 = x[p*3+0], x1 = x[p*3+1], x2 = x[p*3+2];

    __shared__ float hS[4][DD];

    float f = x0*W1[d] + x1*W1[DD+d] + x2*W1[2*DD+d] + b1[d];
    f = f*g1[d] + be1[d];
    g_feat[p*DD + d] = leaky(f);

    float h = x0*Ws1[d] + x1*Ws1[DD+d] + x2*Ws1[2*DD+d] + bs1[d];
    hS[sub][d] = h > 0.f ? h : 0.f;
    __syncthreads();

    if (d < LV) {
        float s = bs2[d];
        #pragma unroll 16
        for (int e = 0; e < DD; e++) s += hS[sub][e]*Ws2[e*LV + d];
        g_fw[p*LV + d] = 1.f/(1.f + expf(-s));
    }
}

// ---------------- kernel 2: KNN, 4-way candidate split --------------------------
// 512 threads: 128 queries x 4 range-halves. smem: float4 cands + merge lists.
#define KNN_SMEM (NN*16 + 384*KNB*4 + 384*KNB*4)   // 32768 + 12288 + 12288 = 57344
__global__ void __launch_bounds__(512)
k_knn(const float* __restrict__ x)
{
    extern __shared__ char ksm[];
    float4* sc   = (float4*)ksm;                       // [2048]
    float*  smd  = (float*)(ksm + NN*16);              // [384][8]
    int*    smi  = (int*)(ksm + NN*16 + 384*KNB*4);    // [384][8]

    const int tid = threadIdx.x;
    const int ql = tid & 127;       // query within block
    const int h  = tid >> 7;        // 0..3 range quarter
    const int b  = blockIdx.y;
    const int i  = blockIdx.x*128 + ql;

    for (int j = tid; j < NN; j += 512) {
        float a = x[(b*NN + j)*3 + 0];
        float c = x[(b*NN + j)*3 + 1];
        float e = x[(b*NN + j)*3 + 2];
        sc[j] = make_float4(a, c, e, a*a + c*c + e*e);
    }
    __syncthreads();

    float4 q4 = sc[i];
    float xi0 = q4.x, xi1 = q4.y, xi2 = q4.z, ni = q4.w;

    float bd[KNB]; int bi[KNB];
    #pragma unroll
    for (int t = 0; t < KNB; t++) { bd[t] = FLT_MAX; bi[t] = 0; }

    const int j0 = h*(NN/4), j1 = j0 + NN/4;
    #pragma unroll 4
    for (int j = j0; j < j1; j++) {
        float4 c4 = sc[j];
        float d2 = ni + c4.w - 2.f*(xi0*c4.x + xi1*c4.y + xi2*c4.z);
        if (d2 < bd[KNB-1]) {
            bd[KNB-1] = d2; bi[KNB-1] = j;
            #pragma unroll
            for (int t = KNB-1; t > 0; t--) {
                if (bd[t] < bd[t-1]) {
                    float td = bd[t]; bd[t] = bd[t-1]; bd[t-1] = td;
                    int   ti = bi[t]; bi[t] = bi[t-1]; bi[t-1] = ti;
                }
            }
        }
    }

    if (h > 0) {
        int s = ((h-1)*128 + ql)*KNB;
        #pragma unroll
        for (int t = 0; t < KNB; t++) { smd[s+t] = bd[t]; smi[s+t] = bi[t]; }
    }
    __syncthreads();

    if (h == 0) {
        #pragma unroll
        for (int hh = 0; hh < 3; hh++) {
            int s = (hh*128 + ql)*KNB;
            #pragma unroll
            for (int t = 0; t < KNB; t++) {
                float d2 = smd[s+t]; int jj = smi[s+t];
                if (d2 < bd[KNB-1]) {
                    bd[KNB-1] = d2; bi[KNB-1] = jj;
                    #pragma unroll
                    for (int u = KNB-1; u > 0; u--) {
                        if (bd[u] < bd[u-1]) {
                            float td = bd[u]; bd[u] = bd[u-1]; bd[u-1] = td;
                            int   ti = bi[u]; bi[u] = bi[u-1]; bi[u-1] = ti;
                        }
                    }
                }
            }
        }
        int p = b*NN + i;
        #pragma unroll
        for (int t = 0; t < KNB; t++) g_idx[p*KNB + t] = bi[t];
    }
}

// ---------------- tf32 tensor GEMM: block 64x128, BK=32, double buffered -------
// C[M, n0:n0+128] = op(A[M,K] @ Bt[n0:n0+128, K]^T)
#define SROW 36
#define ABUF (64*SROW)          // 2304 floats
#define BBUF (128*SROW)         // 4608 floats
#define SMEM_GEMM ((2*ABUF + 2*BBUF)*4)   // 55296 bytes

template<bool EPI>
__global__ void __launch_bounds__(256)
mma_gemm(const float* __restrict__ A, const float* __restrict__ Bt,
         const float* __restrict__ bias, const float* __restrict__ gamma,
         const float* __restrict__ beta, float* __restrict__ C,
         int Ntot, int K)
{
    extern __shared__ float sm[];
    const int t = threadIdx.x, lane = t & 31, wid = t >> 5;
    const int gid = lane >> 2, tig = lane & 3;
    const int wm = (wid & 1) * 32, wn = (wid >> 1) * 32;
    const int m0 = blockIdx.x * 64, n0 = blockIdx.y * 128;

    // staging: A 64x32 (2 float4/thr), B 128x32 (4 float4/thr)
    const int ar = t >> 2, ak = (t & 3) * 8;
    const float* Ag  = A  + (size_t)(m0 + ar)*K + ak;
    const float* Bg0 = Bt + (size_t)(n0 + ar)*K + ak;
    const float* Bg1 = Bt + (size_t)(n0 + 64 + ar)*K + ak;

    const uint32_t sbase = smem_u32(sm);
    const uint32_t sA  = sbase + (uint32_t)(ar*SROW + ak)*4u;
    const uint32_t sB0 = sbase + (uint32_t)(2*ABUF + ar*SROW + ak)*4u;
    const uint32_t sB1 = sB0 + 64*SROW*4u;

    const int nt = K >> 5;

    CP_ASYNC16(sA, Ag); CP_ASYNC16(sA + 16, Ag + 4);
    CP_ASYNC16(sB0, Bg0); CP_ASYNC16(sB0 + 16, Bg0 + 4);
    CP_ASYNC16(sB1, Bg1); CP_ASYNC16(sB1 + 16, Bg1 + 4);
    CP_COMMIT();

    float acc[2][4][4] = {};
    int buf = 0;
    for (int kt = 0; kt < nt; kt++) {
        if (kt + 1 < nt) {
            uint32_t oa = (uint32_t)((buf ^ 1)*ABUF)*4u;
            uint32_t ob = (uint32_t)((buf ^ 1)*BBUF)*4u;
            const float* Ap  = Ag  + (kt+1)*32;
            const float* Bp0 = Bg0 + (kt+1)*32;
            const float* Bp1 = Bg1 + (kt+1)*32;
            CP_ASYNC16(sA + oa, Ap); CP_ASYNC16(sA + oa + 16, Ap + 4);
            CP_ASYNC16(sB0 + ob, Bp0); CP_ASYNC16(sB0 + ob + 16, Bp0 + 4);
            CP_ASYNC16(sB1 + ob, Bp1); CP_ASYNC16(sB1 + ob + 16, Bp1 + 4);
            CP_COMMIT();
            CP_WAIT(1);
        } else {
            CP_WAIT(0);
        }
        __syncthreads();

        const float* as = sm + buf*ABUF + wm*SROW;
        const float* bs = sm + 2*ABUF + buf*BBUF + wn*SROW;
        #pragma unroll
        for (int ks = 0; ks < 4; ks++) {
            const int kk = ks*8 + tig;
            uint32_t af[2][4], bf[4][2];
            #pragma unroll
            for (int mf = 0; mf < 2; mf++) {
                const float* ap = as + (mf*16 + gid)*SROW + kk;
                af[mf][0] = __float_as_uint(ap[0]);
                af[mf][1] = __float_as_uint(ap[8*SROW]);
                af[mf][2] = __float_as_uint(ap[4]);
                af[mf][3] = __float_as_uint(ap[8*SROW + 4]);
            }
            #pragma unroll
            for (int nf = 0; nf < 4; nf++) {
                const float* bp = bs + (nf*8 + gid)*SROW + kk;
                bf[nf][0] = __float_as_uint(bp[0]);
                bf[nf][1] = __float_as_uint(bp[4]);
            }
            #pragma unroll
            for (int mf = 0; mf < 2; mf++)
                #pragma unroll
                for (int nf = 0; nf < 4; nf++)
                    mma_tf32(acc[mf][nf], af[mf], bf[nf]);
        }
        __syncthreads();
        buf ^= 1;
    }

    #pragma unroll
    for (int mf = 0; mf < 2; mf++) {
        const int row = m0 + wm + mf*16 + gid;
        #pragma unroll
        for (int nf = 0; nf < 4; nf++) {
            const int col = n0 + wn + nf*8 + tig*2;
            float v0 = acc[mf][nf][0], v1 = acc[mf][nf][1];
            float v2 = acc[mf][nf][2], v3 = acc[mf][nf][3];
            if (EPI) {
                float e0 = __ldg(bias+col),  e1 = __ldg(bias+col+1);
                float q0 = __ldg(gamma+col), q1 = __ldg(gamma+col+1);
                float h0 = __ldg(beta+col),  h1 = __ldg(beta+col+1);
                v0 = leaky((v0 + e0)*q0 + h0);
                v1 = leaky((v1 + e1)*q1 + h1);
                v2 = leaky((v2 + e0)*q0 + h0);
                v3 = leaky((v3 + e1)*q1 + h1);
            }
            *(float2*)(C + (size_t)row*Ntot + col)     = make_float2(v0, v1);
            *(float2*)(C + (size_t)(row+8)*Ntot + col) = make_float2(v2, v3);
        }
    }
}

// ---------------- kernel 3: gather neighbors, conv, max-agg, build multi -------
__global__ void k_agg(const float* __restrict__ b2, const float* __restrict__ g2,
                      const float* __restrict__ be2)
{
    int sub = threadIdx.x >> 6;
    int d   = threadIdx.x & 63;
    int p   = blockIdx.x*4 + sub;
    int b   = p >> 11;

    float pv = g_PQ[(size_t)p*128 + d];
    float gg = g2[d];
    float cc = b2[d]*gg + be2[d];

    const int* id = &g_idx[p*KNB];
    float m = -FLT_MAX;
    #pragma unroll
    for (int k = 0; k < KNB; k++) {
        int q = b*NN + id[k];
        float v = (pv + g_PQ[(size_t)q*128 + 64 + d])*gg + cc;
        v = leaky(v);
        m = fmaxf(m, v);
    }
    float f0 = g_fw[p*LV+0], f1 = g_fw[p*LV+1], f2 = g_fw[p*LV+2];
    g_multi[p*LV*DD + 0*DD + d] = m*f0;
    g_multi[p*LV*DD + 1*DD + d] = m*f1;
    g_multi[p*LV*DD + 2*DD + d] = m*f2;
}

// ---------------- kernel 4: final 128->3 + residual (warp per point) -----------
__global__ void k_final(const float* __restrict__ x,
                        const float* __restrict__ Wf3, const float* __restrict__ bf3,
                        float* __restrict__ out)
{
    int lane = threadIdx.x & 31;
    int p = blockIdx.x*8 + (threadIdx.x >> 5);
    float4 v = *(const float4*)(g_G2 + (size_t)p*H2 + lane*4);
    float s0 = 0.f, s1 = 0.f, s2 = 0.f;
    const float* w = Wf3 + lane*12;
    s0 += v.x*w[0]; s1 += v.x*w[1]; s2 += v.x*w[2];
    s0 += v.y*w[3]; s1 += v.y*w[4]; s2 += v.y*w[5];
    s0 += v.z*w[6]; s1 += v.z*w[7]; s2 += v.z*w[8];
    s0 += v.w*w[9]; s1 += v.w*w[10]; s2 += v.w*w[11];
    #pragma unroll
    for (int o = 16; o > 0; o >>= 1) {
        s0 += __shfl_down_sync(0xFFFFFFFF, s0, o);
        s1 += __shfl_down_sync(0xFFFFFFFF, s1, o);
        s2 += __shfl_down_sync(0xFFFFFFFF, s2, o);
    }
    if (lane == 0) {
        out[p*3+0] = x[p*3+0] + 0.1f*(s0 + bf3[0]);
        out[p*3+1] = x[p*3+1] + 0.1f*(s1 + bf3[1]);
        out[p*3+2] = x[p*3+2] + 0.1f*(s2 + bf3[2]);
    }
}

// ---------------- launch -------------------------------------------------------
extern "C" void kernel_launch(void* const* d_in, const int* in_sizes, int n_in,
                              void* d_out, int out_size)
{
    const float* x   = (const float*)d_in[0];
    const float* W1  = (const float*)d_in[1];
    const float* b1  = (const float*)d_in[2];
    const float* g1  = (const float*)d_in[3];
    const float* be1 = (const float*)d_in[4];
    const float* W2  = (const float*)d_in[5];
    const float* b2  = (const float*)d_in[6];
    const float* g2  = (const float*)d_in[7];
    const float* be2 = (const float*)d_in[8];
    const float* Ws1 = (const float*)d_in[9];
    const float* bs1 = (const float*)d_in[10];
    const float* Ws2 = (const float*)d_in[11];
    const float* bs2 = (const float*)d_in[12];
    const float* Wf1 = (const float*)d_in[13];
    const float* bf1 = (const float*)d_in[14];
    const float* gf1 = (const float*)d_in[15];
    const float* bef1= (const float*)d_in[16];
    const float* Wf2 = (const float*)d_in[17];
    const float* bf2 = (const float*)d_in[18];
    const float* gf2 = (const float*)d_in[19];
    const float* bef2= (const float*)d_in[20];
    const float* Wf3 = (const float*)d_in[21];
    const float* bf3 = (const float*)d_in[22];
    float* out = (float*)d_out;

    void *p_feat, *p_PQ, *p_multi, *p_G1, *p_G2, *p_Bt1, *p_Bt2, *p_Btpq;
    cudaGetSymbolAddress(&p_feat,  g_feat);
    cudaGetSymbolAddress(&p_PQ,    g_PQ);
    cudaGetSymbolAddress(&p_multi, g_multi);
    cudaGetSymbolAddress(&p_G1,    g_G1);
    cudaGetSymbolAddress(&p_G2,    g_G2);
    cudaGetSymbolAddress(&p_Bt1,   g_Bt1);
    cudaGetSymbolAddress(&p_Bt2,   g_Bt2);
    cudaGetSymbolAddress(&p_Btpq,  g_Btpq);

    cudaFuncSetAttribute(mma_gemm<false>, cudaFuncAttributeMaxDynamicSharedMemorySize, SMEM_GEMM);
    cudaFuncSetAttribute(mma_gemm<true>,  cudaFuncAttributeMaxDynamicSharedMemorySize, SMEM_GEMM);
    cudaFuncSetAttribute(k_knn, cudaFuncAttributeMaxDynamicSharedMemorySize, KNN_SMEM);

    // 1. KNN (independent of features)
    k_knn<<<dim3(NN/128, BB), 512, KNN_SMEM>>>(x);

    // 2. per-point feature + suppressor + weight transposes
    k_pp<<<NP/4 + 192, 256>>>(x, W1, b1, g1, be1, Ws1, bs1, Ws2, bs2, W2, Wf1, Wf2);

    // 3. [P|Q] = feat @ Btpq^T : [16384,64]@[64,128]
    mma_gemm<false><<<dim3(NP/64, 1), 256, SMEM_GEMM>>>(
        (const float*)p_feat, (const float*)p_Btpq,
        nullptr, nullptr, nullptr, (float*)p_PQ, 128, DD);

    // 4. gather + conv + max + multi-scale weighting
    k_agg<<<NP/4, 256>>>(b2, g2, be2);

    // 5. fusion layer 1: [16384,192]@[192,256]
    mma_gemm<true><<<dim3(NP/64, 2), 256, SMEM_GEMM>>>(
        (const float*)p_multi, (const float*)p_Bt1,
        bf1, gf1, bef1, (float*)p_G1, H1, 192);

    // 6. fusion layer 2: [16384,256]@[256,128]
    mma_gemm<true><<<dim3(NP/64, 1), 256, SMEM_GEMM>>>(
        (const float*)p_G1, (const float*)p_Bt2,
        bf2, gf2, bef2, (float*)p_G2, H2, H1);

    // 7. final 128->3 + residual
    k_final<<<NP/8, 256>>>(x, Wf3, bf3, out);
}

// round 7
// speedup vs baseline: 2.3637x; 1.1771x over previous
#include <cuda_runtime.h>
#include <cuda_bf16.h>
#include <float.h>
#include <math.h>
#include <stdint.h>

// Problem constants
#define BB 8
#define NN 2048
#define NP (BB*NN)        // 16384 points
#define DD 64
#define KNB 8
#define LV 3
#define H1 256
#define H2 128

typedef __nv_bfloat16 bf16;

// ---------------- scratch (device globals; no allocation allowed) --------------
__device__ bf16  g_featB [NP*DD];       // [16384,64] bf16
__device__ float g_PQ    [NP*128];      // [16384,128] fp32; cols 0-63 P, 64-127 Q
__device__ float g_fw    [NP*LV];
__device__ int   g_idx   [NP*KNB];
__device__ bf16  g_multiB[NP*LV*DD];    // [16384,192] bf16
__device__ bf16  g_G1B   [NP*H1];       // [16384,256] bf16
__device__ bf16  g_Bt1B  [H1*192];      // Wf1^T bf16
__device__ bf16  g_Bt2B  [H2*H1];       // Wf2^T bf16
__device__ bf16  g_BtpqB [128*DD];      // [P|Q] weight bf16

__device__ __forceinline__ float leaky(float v){ return v > 0.f ? v : 0.2f*v; }

__device__ __forceinline__ uint32_t smem_u32(const void* p) {
    uint32_t a;
    asm("{ .reg .u64 t; cvta.to.shared.u64 t, %1; cvt.u32.u64 %0, t; }" : "=r"(a) : "l"(p));
    return a;
}

#define CP_ASYNC16(d, s) do { \
    size_t _gs = __cvta_generic_to_global(s); \
    asm volatile("cp.async.cg.shared.global [%0], [%1], 16;" :: "r"(d), "l"(_gs) : "memory"); \
} while (0)
#define CP_COMMIT()  asm volatile("cp.async.commit_group;" ::: "memory")
#define CP_WAIT(n)   asm volatile("cp.async.wait_group %0;" :: "n"(n) : "memory")

__device__ __forceinline__ void mma_bf16(float* c, const uint32_t* a, const uint32_t* b) {
    asm volatile(
        "mma.sync.aligned.m16n8k16.row.col.f32.bf16.bf16.f32 "
        "{%0,%1,%2,%3}, {%4,%5,%6,%7}, {%8,%9}, {%0,%1,%2,%3};"
        : "+f"(c[0]), "+f"(c[1]), "+f"(c[2]), "+f"(c[3])
        : "r"(a[0]), "r"(a[1]), "r"(a[2]), "r"(a[3]), "r"(b[0]), "r"(b[1]));
}

// ---------------- kernel 1: point transform + suppressor + weight prep ---------
__global__ void k_pp(const float* __restrict__ x,
                     const float* __restrict__ W1, const float* __restrict__ b1,
                     const float* __restrict__ g1, const float* __restrict__ be1,
                     const float* __restrict__ Ws1, const float* __restrict__ bs1,
                     const float* __restrict__ Ws2, const float* __restrict__ bs2,
                     const float* __restrict__ W2, const float* __restrict__ Wf1,
                     const float* __restrict__ Wf2)
{
    if (blockIdx.x >= NP/4) {
        int i = (blockIdx.x - NP/4)*256 + threadIdx.x;
        if (i < H1*192) { int n = i/192, k = i%192; g_Bt1B[i] = __float2bfloat16_rn(Wf1[k*H1 + n]); }
        if (i < H2*H1)  { int n = i/H1,  k = i%H1;  g_Bt2B[i] = __float2bfloat16_rn(Wf2[k*H2 + n]); }
        if (i < 128*DD) {
            int n = i/DD, k = i%DD;
            float w = (n < 64) ? W2[k*DD + n] : W2[(64 + k)*DD + (n - 64)];
            g_BtpqB[i] = __float2bfloat16_rn(w);
        }
        return;
    }
    int sub = threadIdx.x >> 6;
    int d   = threadIdx.x & 63;
    int p   = blockIdx.x*4 + sub;
    float x0 = x[p*3+0], x1 = x[p*3+1], x2 = x[p*3+2];

    __shared__ float hS[4][DD];

    float f = x0*W1[d] + x1*W1[DD+d] + x2*W1[2*DD+d] + b1[d];
    f = f*g1[d] + be1[d];
    g_featB[p*DD + d] = __float2bfloat16_rn(leaky(f));

    float h = x0*Ws1[d] + x1*Ws1[DD+d] + x2*Ws1[2*DD+d] + bs1[d];
    hS[sub][d] = h > 0.f ? h : 0.f;
    __syncthreads();

    if (d < LV) {
        float s = bs2[d];
        #pragma unroll 16
        for (int e = 0; e < DD; e++) s += hS[sub][e]*Ws2[e*LV + d];
        g_fw[p*LV + d] = 1.f/(1.f + expf(-s));
    }
}

// ---------------- kernel 2: KNN, 4-way candidate split --------------------------
#define KNN_SMEM (NN*16 + 384*KNB*4 + 384*KNB*4)   // 57344
__global__ void __launch_bounds__(512)
k_knn(const float* __restrict__ x)
{
    extern __shared__ char ksm[];
    float4* sc   = (float4*)ksm;
    float*  smd  = (float*)(ksm + NN*16);
    int*    smi  = (int*)(ksm + NN*16 + 384*KNB*4);

    const int tid = threadIdx.x;
    const int ql = tid & 127;
    const int h  = tid >> 7;
    const int b  = blockIdx.y;
    const int i  = blockIdx.x*128 + ql;

    for (int j = tid; j < NN; j += 512) {
        float a = x[(b*NN + j)*3 + 0];
        float c = x[(b*NN + j)*3 + 1];
        float e = x[(b*NN + j)*3 + 2];
        sc[j] = make_float4(a, c, e, a*a + c*c + e*e);
    }
    __syncthreads();

    float4 q4 = sc[i];
    float xi0 = q4.x, xi1 = q4.y, xi2 = q4.z, ni = q4.w;

    float bd[KNB]; int bi[KNB];
    #pragma unroll
    for (int t = 0; t < KNB; t++) { bd[t] = FLT_MAX; bi[t] = 0; }

    const int j0 = h*(NN/4), j1 = j0 + NN/4;
    #pragma unroll 4
    for (int j = j0; j < j1; j++) {
        float4 c4 = sc[j];
        float d2 = ni + c4.w - 2.f*(xi0*c4.x + xi1*c4.y + xi2*c4.z);
        if (d2 < bd[KNB-1]) {
            bd[KNB-1] = d2; bi[KNB-1] = j;
            #pragma unroll
            for (int t = KNB-1; t > 0; t--) {
                if (bd[t] < bd[t-1]) {
                    float td = bd[t]; bd[t] = bd[t-1]; bd[t-1] = td;
                    int   ti = bi[t]; bi[t] = bi[t-1]; bi[t-1] = ti;
                }
            }
        }
    }

    if (h > 0) {
        int s = ((h-1)*128 + ql)*KNB;
        #pragma unroll
        for (int t = 0; t < KNB; t++) { smd[s+t] = bd[t]; smi[s+t] = bi[t]; }
    }
    __syncthreads();

    if (h == 0) {
        #pragma unroll
        for (int hh = 0; hh < 3; hh++) {
            int s = (hh*128 + ql)*KNB;
            #pragma unroll
            for (int t = 0; t < KNB; t++) {
                float d2 = smd[s+t]; int jj = smi[s+t];
                if (d2 < bd[KNB-1]) {
                    bd[KNB-1] = d2; bi[KNB-1] = jj;
                    #pragma unroll
                    for (int u = KNB-1; u > 0; u--) {
                        if (bd[u] < bd[u-1]) {
                            float td = bd[u]; bd[u] = bd[u-1]; bd[u-1] = td;
                            int   ti = bi[u]; bi[u] = bi[u-1]; bi[u-1] = ti;
                        }
                    }
                }
            }
        }
        int p = b*NN + i;
        #pragma unroll
        for (int t = 0; t < KNB; t++) g_idx[p*KNB + t] = bi[t];
    }
}

// ---------------- bf16 tensor GEMM: block 64x128, BK=32(bf16), dbl buffered ----
// A [M,K] bf16 row-major, Bt [N,K] bf16. MODE: 0 fp32 raw out; 1 bf16 affine+leaky;
// 2 affine+leaky then project 128->3 with Wf3/bf3, residual vs x, write out.
#define SR32 20                        // uint32 per smem row (80B)
#define ABUF32 (64*SR32)               // 1280
#define BBUF32 (128*SR32)              // 2560
#define SMEM_GEMM ((2*ABUF32 + 2*BBUF32)*4)   // 30720 bytes

template<int MODE>
__global__ void __launch_bounds__(256)
mma_gemm(const bf16* __restrict__ A, const bf16* __restrict__ Bt,
         const float* __restrict__ bias, const float* __restrict__ gamma,
         const float* __restrict__ beta, void* __restrict__ Cout,
         int Ntot, int K,
         const float* __restrict__ x, const float* __restrict__ Wf3,
         const float* __restrict__ bf3)
{
    extern __shared__ uint32_t sm32[];
    __shared__ float sAcc[64][3];

    const int t = threadIdx.x, lane = t & 31, wid = t >> 5;
    const int gid = lane >> 2, tig = lane & 3;
    const int wm = (wid & 1) * 32, wn = (wid >> 1) * 32;
    const int m0 = blockIdx.x * 64, n0 = blockIdx.y * 128;

    // staging: A 64 rows x 64B (1 cp/thr), B 128 rows x 64B (2 cp/thr)
    const int sr = t >> 2, seg = t & 3;
    const bf16* Ag  = A  + (size_t)(m0 + sr)*K + seg*8;
    const bf16* Bg0 = Bt + (size_t)(n0 + sr)*K + seg*8;
    const bf16* Bg1 = Bt + (size_t)(n0 + 64 + sr)*K + seg*8;

    const uint32_t sbase = smem_u32(sm32);
    const uint32_t sA  = sbase + (uint32_t)(sr*SR32 + seg*4)*4u;
    const uint32_t sB0 = sbase + (uint32_t)(2*ABUF32 + sr*SR32 + seg*4)*4u;
    const uint32_t sB1 = sB0 + 64*SR32*4u;

    const int nt = K >> 5;

    CP_ASYNC16(sA, Ag);
    CP_ASYNC16(sB0, Bg0);
    CP_ASYNC16(sB1, Bg1);
    CP_COMMIT();

    float acc[2][4][4] = {};
    int buf = 0;
    for (int kt = 0; kt < nt; kt++) {
        if (kt + 1 < nt) {
            uint32_t oa = (uint32_t)((buf ^ 1)*ABUF32)*4u;
            uint32_t ob = (uint32_t)((buf ^ 1)*BBUF32)*4u;
            CP_ASYNC16(sA + oa, Ag + (kt+1)*32);
            CP_ASYNC16(sB0 + ob, Bg0 + (kt+1)*32);
            CP_ASYNC16(sB1 + ob, Bg1 + (kt+1)*32);
            CP_COMMIT();
            CP_WAIT(1);
        } else {
            CP_WAIT(0);
        }
        __syncthreads();

        const uint32_t* as = sm32 + buf*ABUF32 + wm*SR32;
        const uint32_t* bs = sm32 + 2*ABUF32 + buf*BBUF32 + wn*SR32;
        #pragma unroll
        for (int ks = 0; ks < 2; ks++) {
            const int ko = ks*8;
            uint32_t af[2][4], bfr[4][2];
            #pragma unroll
            for (int mf = 0; mf < 2; mf++) {
                const uint32_t* ap = as + (mf*16 + gid)*SR32 + ko + tig;
                af[mf][0] = ap[0];
                af[mf][1] = ap[8*SR32];
                af[mf][2] = ap[4];
                af[mf][3] = ap[8*SR32 + 4];
            }
            #pragma unroll
            for (int nf = 0; nf < 4; nf++) {
                const uint32_t* bp = bs + (nf*8 + gid)*SR32 + ko + tig;
                bfr[nf][0] = bp[0];
                bfr[nf][1] = bp[4];
            }
            #pragma unroll
            for (int mf = 0; mf < 2; mf++)
                #pragma unroll
                for (int nf = 0; nf < 4; nf++)
                    mma_bf16(acc[mf][nf], af[mf], bfr[nf]);
        }
        __syncthreads();
        buf ^= 1;
    }

    if (MODE == 2) {
        // zero per-row accumulators
        if (t < 192) sAcc[t/3][t%3] = 0.f;
        __syncthreads();
    }

    #pragma unroll
    for (int mf = 0; mf < 2; mf++) {
        const int row = m0 + wm + mf*16 + gid;
        float sLo[3] = {0.f,0.f,0.f}, sHi[3] = {0.f,0.f,0.f};
        #pragma unroll
        for (int nf = 0; nf < 4; nf++) {
            const int col = n0 + wn + nf*8 + tig*2;
            float v0 = acc[mf][nf][0], v1 = acc[mf][nf][1];
            float v2 = acc[mf][nf][2], v3 = acc[mf][nf][3];
            if (MODE >= 1) {
                float e0 = __ldg(bias+col),  e1 = __ldg(bias+col+1);
                float q0 = __ldg(gamma+col), q1 = __ldg(gamma+col+1);
                float h0 = __ldg(beta+col),  h1 = __ldg(beta+col+1);
                v0 = leaky((v0 + e0)*q0 + h0);
                v1 = leaky((v1 + e1)*q1 + h1);
                v2 = leaky((v2 + e0)*q0 + h0);
                v3 = leaky((v3 + e1)*q1 + h1);
            }
            if (MODE == 0) {
                float* C = (float*)Cout;
                *(float2*)(C + (size_t)row*Ntot + col)     = make_float2(v0, v1);
                *(float2*)(C + (size_t)(row+8)*Ntot + col) = make_float2(v2, v3);
            } else if (MODE == 1) {
                bf16* C = (bf16*)Cout;
                __nv_bfloat162 lo; lo.x = __float2bfloat16_rn(v0); lo.y = __float2bfloat16_rn(v1);
                __nv_bfloat162 hi; hi.x = __float2bfloat16_rn(v2); hi.y = __float2bfloat16_rn(v3);
                *(__nv_bfloat162*)(C + (size_t)row*Ntot + col)     = lo;
                *(__nv_bfloat162*)(C + (size_t)(row+8)*Ntot + col) = hi;
            } else {
                #pragma unroll
                for (int j = 0; j < 3; j++) {
                    float w0 = __ldg(Wf3 + col*3 + j);
                    float w1 = __ldg(Wf3 + (col+1)*3 + j);
                    sLo[j] += v0*w0 + v1*w1;
                    sHi[j] += v2*w0 + v3*w1;
                }
            }
        }
        if (MODE == 2) {
            // reduce over the quad (tig 0..3 share the same rows)
            #pragma unroll
            for (int j = 0; j < 3; j++) {
                sLo[j] += __shfl_xor_sync(0xFFFFFFFF, sLo[j], 1);
                sLo[j] += __shfl_xor_sync(0xFFFFFFFF, sLo[j], 2);
                sHi[j] += __shfl_xor_sync(0xFFFFFFFF, sHi[j], 1);
                sHi[j] += __shfl_xor_sync(0xFFFFFFFF, sHi[j], 2);
            }
            if (tig == 0) {
                int rl = wm + mf*16 + gid;
                #pragma unroll
                for (int j = 0; j < 3; j++) {
                    atomicAdd(&sAcc[rl][j],     sLo[j]);
                    atomicAdd(&sAcc[rl + 8][j], sHi[j]);
                }
            }
        }
    }

    if (MODE == 2) {
        __syncthreads();
        if (t < 64) {
            int p = m0 + t;
            float* out = (float*)Cout;
            #pragma unroll
            for (int j = 0; j < 3; j++)
                out[p*3+j] = x[p*3+j] + 0.1f*(sAcc[t][j] + __ldg(bf3+j));
        }
    }
}

// ---------------- kernel 3: gather neighbors, conv, max-agg, build multi -------
__global__ void k_agg(const float* __restrict__ b2, const float* __restrict__ g2,
                      const float* __restrict__ be2)
{
    int sub = threadIdx.x >> 6;
    int d   = threadIdx.x & 63;
    int p   = blockIdx.x*4 + sub;
    int b   = p >> 11;

    float pv = g_PQ[(size_t)p*128 + d];
    float gg = g2[d];
    float cc = b2[d]*gg + be2[d];

    const int* id = &g_idx[p*KNB];
    float m = -FLT_MAX;
    #pragma unroll
    for (int k = 0; k < KNB; k++) {
        int q = b*NN + id[k];
        float v = (pv + g_PQ[(size_t)q*128 + 64 + d])*gg + cc;
        v = leaky(v);
        m = fmaxf(m, v);
    }
    float f0 = g_fw[p*LV+0], f1 = g_fw[p*LV+1], f2 = g_fw[p*LV+2];
    g_multiB[p*LV*DD + 0*DD + d] = __float2bfloat16_rn(m*f0);
    g_multiB[p*LV*DD + 1*DD + d] = __float2bfloat16_rn(m*f1);
    g_multiB[p*LV*DD + 2*DD + d] = __float2bfloat16_rn(m*f2);
}

// ---------------- launch -------------------------------------------------------
extern "C" void kernel_launch(void* const* d_in, const int* in_sizes, int n_in,
                              void* d_out, int out_size)
{
    const float* x   = (const float*)d_in[0];
    const float* W1  = (const float*)d_in[1];
    const float* b1  = (const float*)d_in[2];
    const float* g1  = (const float*)d_in[3];
    const float* be1 = (const float*)d_in[4];
    const float* W2  = (const float*)d_in[5];
    const float* b2  = (const float*)d_in[6];
    const float* g2  = (const float*)d_in[7];
    const float* be2 = (const float*)d_in[8];
    const float* Ws1 = (const float*)d_in[9];
    const float* bs1 = (const float*)d_in[10];
    const float* Ws2 = (const float*)d_in[11];
    const float* bs2 = (const float*)d_in[12];
    const float* Wf1 = (const float*)d_in[13];
    const float* bf1 = (const float*)d_in[14];
    const float* gf1 = (const float*)d_in[15];
    const float* bef1= (const float*)d_in[16];
    const float* Wf2 = (const float*)d_in[17];
    const float* bf2 = (const float*)d_in[18];
    const float* gf2 = (const float*)d_in[19];
    const float* bef2= (const float*)d_in[20];
    const float* Wf3 = (const float*)d_in[21];
    const float* bf3 = (const float*)d_in[22];
    float* out = (float*)d_out;

    void *p_featB, *p_PQ, *p_multiB, *p_G1B, *p_Bt1B, *p_Bt2B, *p_BtpqB;
    cudaGetSymbolAddress(&p_featB,  g_featB);
    cudaGetSymbolAddress(&p_PQ,     g_PQ);
    cudaGetSymbolAddress(&p_multiB, g_multiB);
    cudaGetSymbolAddress(&p_G1B,    g_G1B);
    cudaGetSymbolAddress(&p_Bt1B,   g_Bt1B);
    cudaGetSymbolAddress(&p_Bt2B,   g_Bt2B);
    cudaGetSymbolAddress(&p_BtpqB,  g_BtpqB);

    cudaFuncSetAttribute(k_knn, cudaFuncAttributeMaxDynamicSharedMemorySize, KNN_SMEM);

    // 1. KNN
    k_knn<<<dim3(NN/128, BB), 512, KNN_SMEM>>>(x);

    // 2. per-point feature + suppressor + weight prep (bf16)
    k_pp<<<NP/4 + 192, 256>>>(x, W1, b1, g1, be1, Ws1, bs1, Ws2, bs2, W2, Wf1, Wf2);

    // 3. [P|Q] = feat @ Btpq^T : [16384,64]@[64,128] -> fp32
    mma_gemm<0><<<dim3(NP/64, 1), 256, SMEM_GEMM>>>(
        (const bf16*)p_featB, (const bf16*)p_BtpqB,
        nullptr, nullptr, nullptr, p_PQ, 128, DD, nullptr, nullptr, nullptr);

    // 4. gather + conv + max + multi-scale weighting -> bf16
    k_agg<<<NP/4, 256>>>(b2, g2, be2);

    // 5. fusion layer 1: [16384,192]@[192,256] -> bf16 + affine + leaky
    mma_gemm<1><<<dim3(NP/64, 2), 256, SMEM_GEMM>>>(
        (const bf16*)p_multiB, (const bf16*)p_Bt1B,
        bf1, gf1, bef1, p_G1B, H1, 192, nullptr, nullptr, nullptr);

    // 6. fusion layer 2 + 128->3 projection + residual -> out
    mma_gemm<2><<<dim3(NP/64, 1), 256, SMEM_GEMM>>>(
        (const bf16*)p_G1B, (const bf16*)p_Bt2B,
        bf2, gf2, bef2, d_out, H2, H1, x, Wf3, bf3);
}

// round 8
// speedup vs baseline: 2.4042x; 1.0171x over previous
#include <cuda_runtime.h>
#include <cuda_bf16.h>
#include <float.h>
#include <math.h>
#include <stdint.h>

// Problem constants
#define BB 8
#define NN 2048
#define NP (BB*NN)        // 16384 points
#define DD 64
#define KNB 8
#define LV 3
#define H1 256
#define H2 128

typedef __nv_bfloat16 bf16;

// ---------------- scratch (device globals; no allocation allowed) --------------
__device__ bf16  g_PQb  [NP*128];      // [16384,128] bf16; cols 0-63 P, 64-127 Q
__device__ float g_fw   [NP*LV];
__device__ int   g_idx  [NP*KNB];
__device__ bf16  g_G1B  [NP*H1];       // [16384,256] bf16
__device__ bf16  g_Bt1B [H1*192];      // Wf1^T bf16 [256][192]
__device__ bf16  g_Bt2B [H2*H1];       // Wf2^T bf16 [128][256]

__device__ __forceinline__ float leaky(float v){ return v > 0.f ? v : 0.2f*v; }

__device__ __forceinline__ uint32_t smem_u32(const void* p) {
    uint32_t a;
    asm("{ .reg .u64 t; cvta.to.shared.u64 t, %1; cvt.u32.u64 %0, t; }" : "=r"(a) : "l"(p));
    return a;
}

#define CP_ASYNC16(d, s) do { \
    size_t _gs = __cvta_generic_to_global(s); \
    asm volatile("cp.async.cg.shared.global [%0], [%1], 16;" :: "r"(d), "l"(_gs) : "memory"); \
} while (0)
#define CP_COMMIT()  asm volatile("cp.async.commit_group;" ::: "memory")
#define CP_WAIT(n)   asm volatile("cp.async.wait_group %0;" :: "n"(n) : "memory")

__device__ __forceinline__ void mma_bf16(float* c, const uint32_t* a, const uint32_t* b) {
    asm volatile(
        "mma.sync.aligned.m16n8k16.row.col.f32.bf16.bf16.f32 "
        "{%0,%1,%2,%3}, {%4,%5,%6,%7}, {%8,%9}, {%0,%1,%2,%3};"
        : "+f"(c[0]), "+f"(c[1]), "+f"(c[2]), "+f"(c[3])
        : "r"(a[0]), "r"(a[1]), "r"(a[2]), "r"(a[3]), "r"(b[0]), "r"(b[1]));
}

__device__ __forceinline__ float bf2f(uint32_t u, int hi) {
    __nv_bfloat162 v = *(__nv_bfloat162*)&u;
    return hi ? __bfloat162float(v.y) : __bfloat162float(v.x);
}

// ================= kernel 1: KNN, 8-way candidate split ========================
#define KNN_SMEM (NN*16 + 7*128*KNB*4 + 7*128*KNB*4)   // 90112 bytes
__global__ void __launch_bounds__(1024)
k_knn(const float* __restrict__ x)
{
    extern __shared__ char ksm[];
    float4* sc   = (float4*)ksm;
    float*  smd  = (float*)(ksm + NN*16);
    int*    smi  = (int*)(ksm + NN*16 + 7*128*KNB*4);

    const int tid = threadIdx.x;
    const int ql = tid & 127;
    const int h  = tid >> 7;          // 0..7
    const int b  = blockIdx.y;
    const int i  = blockIdx.x*128 + ql;

    for (int j = tid; j < NN; j += 1024) {
        float a = x[(b*NN + j)*3 + 0];
        float c = x[(b*NN + j)*3 + 1];
        float e = x[(b*NN + j)*3 + 2];
        sc[j] = make_float4(a, c, e, a*a + c*c + e*e);
    }
    __syncthreads();

    float4 q4 = sc[i];
    float xi0 = q4.x, xi1 = q4.y, xi2 = q4.z, ni = q4.w;

    float bd[KNB]; int bi[KNB];
    #pragma unroll
    for (int t = 0; t < KNB; t++) { bd[t] = FLT_MAX; bi[t] = 0; }

    const int j0 = h*(NN/8), j1 = j0 + NN/8;
    #pragma unroll 4
    for (int j = j0; j < j1; j++) {
        float4 c4 = sc[j];
        float d2 = ni + c4.w - 2.f*(xi0*c4.x + xi1*c4.y + xi2*c4.z);
        if (d2 < bd[KNB-1]) {
            bd[KNB-1] = d2; bi[KNB-1] = j;
            #pragma unroll
            for (int t = KNB-1; t > 0; t--) {
                if (bd[t] < bd[t-1]) {
                    float td = bd[t]; bd[t] = bd[t-1]; bd[t-1] = td;
                    int   ti = bi[t]; bi[t] = bi[t-1]; bi[t-1] = ti;
                }
            }
        }
    }

    if (h > 0) {
        int s = ((h-1)*128 + ql)*KNB;
        #pragma unroll
        for (int t = 0; t < KNB; t++) { smd[s+t] = bd[t]; smi[s+t] = bi[t]; }
    }
    __syncthreads();

    if (h == 0) {
        #pragma unroll
        for (int hh = 0; hh < 7; hh++) {
            int s = (hh*128 + ql)*KNB;
            #pragma unroll
            for (int t = 0; t < KNB; t++) {
                float d2 = smd[s+t]; int jj = smi[s+t];
                if (d2 < bd[KNB-1]) {
                    bd[KNB-1] = d2; bi[KNB-1] = jj;
                    #pragma unroll
                    for (int u = KNB-1; u > 0; u--) {
                        if (bd[u] < bd[u-1]) {
                            float td = bd[u]; bd[u] = bd[u-1]; bd[u-1] = td;
                            int   ti = bi[u]; bi[u] = bi[u-1]; bi[u-1] = ti;
                        }
                    }
                }
            }
        }
        int p = b*NN + i;
        #pragma unroll
        for (int t = 0; t < KNB; t++) g_idx[p*KNB + t] = bi[t];
    }
}

// ================= kernel 2: feature+suppressor+PQ GEMM (+weight prep) =========
// blocks [0,256): 64 points each, fused pipeline. blocks [256,448): Wf transposes.
#define ASR 36     // u32 per A smem row (64 bf16 = 32 u32 + 4 pad)
#define BSR 36     // u32 per B smem row
__global__ void __launch_bounds__(256)
k_ppq(const float* __restrict__ x,
      const float* __restrict__ W1, const float* __restrict__ b1,
      const float* __restrict__ g1, const float* __restrict__ be1,
      const float* __restrict__ Ws1, const float* __restrict__ bs1,
      const float* __restrict__ Ws2, const float* __restrict__ bs2,
      const float* __restrict__ W2, const float* __restrict__ Wf1,
      const float* __restrict__ Wf2)
{
    if (blockIdx.x >= NP/64) {
        int i = (blockIdx.x - NP/64)*256 + threadIdx.x;
        if (i < H1*192) { int n = i/192, k = i%192; g_Bt1B[i] = __float2bfloat16_rn(Wf1[k*H1 + n]); }
        if (i < H2*H1)  { int n = i>>8,  k = i&255; g_Bt2B[i] = __float2bfloat16_rn(Wf2[k*H2 + n]); }
        return;
    }

    __shared__ uint32_t sA[64*ASR];     // feat tile  [64 rows][64 bf16]
    __shared__ uint32_t sB[128*BSR];    // Btpq       [128 rows][64 bf16]

    const int t = threadIdx.x, lane = t & 31, wid = t >> 5;
    const int gid = lane >> 2, tig = lane & 3;
    const int m0 = blockIdx.x * 64;
    const int pt = t >> 2, q = t & 3, d0 = q*16;
    const int p  = m0 + pt;

    // ---- fill B smem: Btpq[n][k] = n<64 ? W2[k][n] : W2[64+k][n-64], bf16 ----
    bf16* sBh = (bf16*)sB;
    for (int i = t; i < 128*64; i += 256) {
        int k = i >> 7, n = i & 127;
        float w = (n < 64) ? W2[k*DD + n] : W2[(64 + k)*DD + (n - 64)];
        sBh[n*(2*BSR) + k] = __float2bfloat16_rn(w);
    }

    // ---- feature transform into A smem + suppressor ----
    float x0 = x[p*3+0], x1 = x[p*3+1], x2 = x[p*3+2];
    float s0 = 0.f, s1 = 0.f, s2 = 0.f;
    bf16* sAh = (bf16*)sA;
    #pragma unroll
    for (int j = 0; j < 16; j++) {
        int d = d0 + j;
        float f = x0*W1[d] + x1*W1[DD+d] + x2*W1[2*DD+d] + b1[d];
        f = leaky(f*g1[d] + be1[d]);
        sAh[pt*(2*ASR) + d] = __float2bfloat16_rn(f);
        float hh = x0*Ws1[d] + x1*Ws1[DD+d] + x2*Ws1[2*DD+d] + bs1[d];
        hh = hh > 0.f ? hh : 0.f;
        s0 += hh*Ws2[d*LV+0]; s1 += hh*Ws2[d*LV+1]; s2 += hh*Ws2[d*LV+2];
    }
    s0 += __shfl_xor_sync(0xFFFFFFFF, s0, 1); s0 += __shfl_xor_sync(0xFFFFFFFF, s0, 2);
    s1 += __shfl_xor_sync(0xFFFFFFFF, s1, 1); s1 += __shfl_xor_sync(0xFFFFFFFF, s1, 2);
    s2 += __shfl_xor_sync(0xFFFFFFFF, s2, 1); s2 += __shfl_xor_sync(0xFFFFFFFF, s2, 2);
    if (q == 0) {
        g_fw[p*LV+0] = 1.f/(1.f + expf(-s0));
        g_fw[p*LV+1] = 1.f/(1.f + expf(-s1));
        g_fw[p*LV+2] = 1.f/(1.f + expf(-s2));
    }
    __syncthreads();

    // ---- mma 64x128x64 ----
    const int wm = (wid & 1)*32, wn = (wid >> 1)*32;
    float acc[2][4][4] = {};
    #pragma unroll
    for (int ks = 0; ks < 4; ks++) {
        const int ko = ks*8;
        uint32_t af[2][4], bfr[4][2];
        #pragma unroll
        for (int mf = 0; mf < 2; mf++) {
            const uint32_t* ap = sA + (wm + mf*16 + gid)*ASR + ko + tig;
            af[mf][0] = ap[0];
            af[mf][1] = ap[8*ASR];
            af[mf][2] = ap[4];
            af[mf][3] = ap[8*ASR + 4];
        }
        #pragma unroll
        for (int nf = 0; nf < 4; nf++) {
            const uint32_t* bp = sB + (wn + nf*8 + gid)*BSR + ko + tig;
            bfr[nf][0] = bp[0];
            bfr[nf][1] = bp[4];
        }
        #pragma unroll
        for (int mf = 0; mf < 2; mf++)
            #pragma unroll
            for (int nf = 0; nf < 4; nf++)
                mma_bf16(acc[mf][nf], af[mf], bfr[nf]);
    }

    // ---- write PQ bf16 ----
    #pragma unroll
    for (int mf = 0; mf < 2; mf++) {
        const int row = m0 + wm + mf*16 + gid;
        #pragma unroll
        for (int nf = 0; nf < 4; nf++) {
            const int col = wn + nf*8 + tig*2;
            __nv_bfloat162 lo, hi;
            lo.x = __float2bfloat16_rn(acc[mf][nf][0]); lo.y = __float2bfloat16_rn(acc[mf][nf][1]);
            hi.x = __float2bfloat16_rn(acc[mf][nf][2]); hi.y = __float2bfloat16_rn(acc[mf][nf][3]);
            *(__nv_bfloat162*)(g_PQb + (size_t)row*128 + col)     = lo;
            *(__nv_bfloat162*)(g_PQb + (size_t)(row+8)*128 + col) = hi;
        }
    }
}

// ================= kernel 3: fused agg + fusion layer 1 ========================
// CTA: 64 points x 256 cols. Phase1 builds multi tile in smem from PQ gathers;
// Phase2 streams Bt1B in BK=32 slabs (double buffered, prefetched under phase1).
#define F1_ASR 100                      // u32 per A row (192 bf16 = 96 u32 + 4 pad)
#define F1_BSR 20                       // u32 per B slab row (32 bf16 + pad)
#define F1_ABUF (64*F1_ASR)             // 6400 u32
#define F1_BBUF (256*F1_BSR)            // 5120 u32
#define F1_SMEM ((F1_ABUF + 2*F1_BBUF)*4)   // 66560 bytes

__global__ void __launch_bounds__(256)
k_aggf1(const float* __restrict__ b2, const float* __restrict__ g2,
        const float* __restrict__ be2,
        const float* __restrict__ bias, const float* __restrict__ gamma,
        const float* __restrict__ beta)
{
    extern __shared__ uint32_t sm32[];
    uint32_t* sA = sm32;                 // A tile
    uint32_t* sB = sm32 + F1_ABUF;       // 2 B slab buffers

    const int t = threadIdx.x, lane = t & 31, wid = t >> 5;
    const int gid = lane >> 2, tig = lane & 3;
    const int m0 = blockIdx.x * 64;
    const uint32_t sbase = smem_u32(sm32);

    // prefetch B slab 0 and 1 (n rows = t, 64B each)
    {
        const bf16* src0 = g_Bt1B + (size_t)t*192 + 0;
        const bf16* src1 = g_Bt1B + (size_t)t*192 + 32;
        uint32_t d0 = sbase + (F1_ABUF + t*F1_BSR)*4u;
        uint32_t d1 = sbase + (F1_ABUF + F1_BBUF + t*F1_BSR)*4u;
        #pragma unroll
        for (int qq = 0; qq < 4; qq++) CP_ASYNC16(d0 + qq*16, src0 + qq*8);
        CP_COMMIT();
        #pragma unroll
        for (int qq = 0; qq < 4; qq++) CP_ASYNC16(d1 + qq*16, src1 + qq*8);
        CP_COMMIT();
    }

    // ---- phase 1: agg for this CTA's 64 points (4 threads/point, 16 dims) ----
    {
        const int pt = t >> 2, q = t & 3, d0 = q*16;
        const int p = m0 + pt, b = p >> 11;

        float pv[16], gg[16], cc[16], m[16];
        // P segment (bf16) + affine params
        uint4 pv0 = *(const uint4*)(g_PQb + (size_t)p*128 + d0);
        uint4 pv1 = *(const uint4*)(g_PQb + (size_t)p*128 + d0 + 8);
        #pragma unroll
        for (int j = 0; j < 8; j++) {
            pv[j]   = bf2f(((const uint32_t*)&pv0)[j>>1], j&1);
            pv[8+j] = bf2f(((const uint32_t*)&pv1)[j>>1], j&1);
        }
        #pragma unroll
        for (int j = 0; j < 16; j++) {
            gg[j] = g2[d0+j];
            cc[j] = b2[d0+j]*gg[j] + be2[d0+j];
            m[j] = -FLT_MAX;
        }
        int idx[KNB];
        *(int4*)&idx[0] = *(const int4*)(g_idx + p*KNB);
        *(int4*)&idx[4] = *(const int4*)(g_idx + p*KNB + 4);
        #pragma unroll
        for (int k = 0; k < KNB; k++) {
            const bf16* qrow = g_PQb + (size_t)(b*NN + idx[k])*128 + 64 + d0;
            uint4 qv0 = *(const uint4*)(qrow);
            uint4 qv1 = *(const uint4*)(qrow + 8);
            #pragma unroll
            for (int j = 0; j < 8; j++) {
                float qa = bf2f(((const uint32_t*)&qv0)[j>>1], j&1);
                float qb = bf2f(((const uint32_t*)&qv1)[j>>1], j&1);
                m[j]   = fmaxf(m[j],   leaky((pv[j]   + qa)*gg[j]   + cc[j]));
                m[8+j] = fmaxf(m[8+j], leaky((pv[8+j] + qb)*gg[8+j] + cc[8+j]));
            }
        }
        float f0 = g_fw[p*LV+0], f1 = g_fw[p*LV+1], f2 = g_fw[p*LV+2];
        bf16* sAh = (bf16*)sA;
        #pragma unroll
        for (int j = 0; j < 16; j++) {
            int d = d0 + j;
            sAh[pt*(2*F1_ASR) + d]       = __float2bfloat16_rn(m[j]*f0);
            sAh[pt*(2*F1_ASR) + 64 + d]  = __float2bfloat16_rn(m[j]*f1);
            sAh[pt*(2*F1_ASR) + 128 + d] = __float2bfloat16_rn(m[j]*f2);
        }
    }
    __syncthreads();

    // ---- phase 2: GEMM 64x256x192, 8 warps (2M x 4N), BK=32 slabs ----
    const int wm = (wid & 1)*32, wn = (wid >> 1)*64;
    float acc[2][8][4] = {};
    const int nt = 6;
    int buf = 0;
    for (int kt = 0; kt < nt; kt++) {
        if (kt + 1 < nt) {
            if (kt + 2 < nt) {
                // issue slab kt+2 into buf (after this iteration's reads? no —
                // buf is being read now; issue into buf^1's successor = buf after swap)
            }
            CP_WAIT(1);
        } else {
            CP_WAIT(0);
        }
        __syncthreads();

        const uint32_t* bs = sB + buf*F1_BBUF + wn*F1_BSR;
        const int ka = kt*16;     // A col offset (u32) for this slab
        #pragma unroll
        for (int ks = 0; ks < 2; ks++) {
            const int ko = ks*8;
            uint32_t af[2][4], bfr[8][2];
            #pragma unroll
            for (int mf = 0; mf < 2; mf++) {
                const uint32_t* ap = sA + (wm + mf*16 + gid)*F1_ASR + ka + ko + tig;
                af[mf][0] = ap[0];
                af[mf][1] = ap[8*F1_ASR];
                af[mf][2] = ap[4];
                af[mf][3] = ap[8*F1_ASR + 4];
            }
            #pragma unroll
            for (int nf = 0; nf < 8; nf++) {
                const uint32_t* bp = bs + (nf*8 + gid)*F1_BSR + ko + tig;
                bfr[nf][0] = bp[0];
                bfr[nf][1] = bp[4];
            }
            #pragma unroll
            for (int mf = 0; mf < 2; mf++)
                #pragma unroll
                for (int nf = 0; nf < 8; nf++)
                    mma_bf16(acc[mf][nf], af[mf], bfr[nf]);
        }
        __syncthreads();
        // refill the buffer we just finished with slab kt+2
        if (kt + 2 < nt) {
            const bf16* src = g_Bt1B + (size_t)t*192 + (kt+2)*32;
            uint32_t dd = sbase + (F1_ABUF + buf*F1_BBUF + t*F1_BSR)*4u;
            #pragma unroll
            for (int qq = 0; qq < 4; qq++) CP_ASYNC16(dd + qq*16, src + qq*8);
            CP_COMMIT();
        }
        buf ^= 1;
    }

    // ---- epilogue: affine + leaky -> G1B bf16 ----
    #pragma unroll
    for (int mf = 0; mf < 2; mf++) {
        const int row = m0 + wm + mf*16 + gid;
        #pragma unroll
        for (int nf = 0; nf < 8; nf++) {
            const int col = wn + nf*8 + tig*2;
            float e0 = __ldg(bias+col),  e1 = __ldg(bias+col+1);
            float q0 = __ldg(gamma+col), q1 = __ldg(gamma+col+1);
            float h0 = __ldg(beta+col),  h1 = __ldg(beta+col+1);
            float v0 = leaky((acc[mf][nf][0] + e0)*q0 + h0);
            float v1 = leaky((acc[mf][nf][1] + e1)*q1 + h1);
            float v2 = leaky((acc[mf][nf][2] + e0)*q0 + h0);
            float v3 = leaky((acc[mf][nf][3] + e1)*q1 + h1);
            __nv_bfloat162 lo, hi;
            lo.x = __float2bfloat16_rn(v0); lo.y = __float2bfloat16_rn(v1);
            hi.x = __float2bfloat16_rn(v2); hi.y = __float2bfloat16_rn(v3);
            *(__nv_bfloat162*)(g_G1B + (size_t)row*H1 + col)     = lo;
            *(__nv_bfloat162*)(g_G1B + (size_t)(row+8)*H1 + col) = hi;
        }
    }
}

// ================= kernel 4: fusion layer 2 + final projection + residual ======
#define SR32 20
#define ABUF32 (64*SR32)
#define BBUF32 (128*SR32)
#define SMEM_F2 ((2*ABUF32 + 2*BBUF32)*4)   // 30720 bytes

__global__ void __launch_bounds__(256)
k_f2(const bf16* __restrict__ A, const bf16* __restrict__ Bt,
     const float* __restrict__ bias, const float* __restrict__ gamma,
     const float* __restrict__ beta, float* __restrict__ out,
     const float* __restrict__ x, const float* __restrict__ Wf3,
     const float* __restrict__ bf3)
{
    extern __shared__ uint32_t sm32[];
    __shared__ float sAcc[64][3];

    const int t = threadIdx.x, lane = t & 31, wid = t >> 5;
    const int gid = lane >> 2, tig = lane & 3;
    const int wm = (wid & 1) * 32, wn = (wid >> 1) * 32;
    const int m0 = blockIdx.x * 64;
    const int K = H1;

    const int sr = t >> 2, seg = t & 3;
    const bf16* Ag  = A  + (size_t)(m0 + sr)*K + seg*8;
    const bf16* Bg0 = Bt + (size_t)sr*K + seg*8;
    const bf16* Bg1 = Bt + (size_t)(64 + sr)*K + seg*8;

    const uint32_t sbase = smem_u32(sm32);
    const uint32_t sA  = sbase + (uint32_t)(sr*SR32 + seg*4)*4u;
    const uint32_t sB0 = sbase + (uint32_t)(2*ABUF32 + sr*SR32 + seg*4)*4u;
    const uint32_t sB1 = sB0 + 64*SR32*4u;

    const int nt = K >> 5;   // 8

    CP_ASYNC16(sA, Ag);
    CP_ASYNC16(sB0, Bg0);
    CP_ASYNC16(sB1, Bg1);
    CP_COMMIT();

    float acc[2][4][4] = {};
    int buf = 0;
    for (int kt = 0; kt < nt; kt++) {
        if (kt + 1 < nt) {
            uint32_t oa = (uint32_t)((buf ^ 1)*ABUF32)*4u;
            uint32_t ob = (uint32_t)((buf ^ 1)*BBUF32)*4u;
            CP_ASYNC16(sA + oa, Ag + (kt+1)*32);
            CP_ASYNC16(sB0 + ob, Bg0 + (kt+1)*32);
            CP_ASYNC16(sB1 + ob, Bg1 + (kt+1)*32);
            CP_COMMIT();
            CP_WAIT(1);
        } else {
            CP_WAIT(0);
        }
        __syncthreads();

        const uint32_t* as = sm32 + buf*ABUF32 + wm*SR32;
        const uint32_t* bs = sm32 + 2*ABUF32 + buf*BBUF32 + wn*SR32;
        #pragma unroll
        for (int ks = 0; ks < 2; ks++) {
            const int ko = ks*8;
            uint32_t af[2][4], bfr[4][2];
            #pragma unroll
            for (int mf = 0; mf < 2; mf++) {
                const uint32_t* ap = as + (mf*16 + gid)*SR32 + ko + tig;
                af[mf][0] = ap[0];
                af[mf][1] = ap[8*SR32];
                af[mf][2] = ap[4];
                af[mf][3] = ap[8*SR32 + 4];
            }
            #pragma unroll
            for (int nf = 0; nf < 4; nf++) {
                const uint32_t* bp = bs + (nf*8 + gid)*SR32 + ko + tig;
                bfr[nf][0] = bp[0];
                bfr[nf][1] = bp[4];
            }
            #pragma unroll
            for (int mf = 0; mf < 2; mf++)
                #pragma unroll
                for (int nf = 0; nf < 4; nf++)
                    mma_bf16(acc[mf][nf], af[mf], bfr[nf]);
        }
        __syncthreads();
        buf ^= 1;
    }

    if (t < 192) sAcc[t/3][t%3] = 0.f;
    __syncthreads();

    #pragma unroll
    for (int mf = 0; mf < 2; mf++) {
        float sLo[3] = {0.f,0.f,0.f}, sHi[3] = {0.f,0.f,0.f};
        #pragma unroll
        for (int nf = 0; nf < 4; nf++) {
            const int col = wn + nf*8 + tig*2;
            float e0 = __ldg(bias+col),  e1 = __ldg(bias+col+1);
            float q0 = __ldg(gamma+col), q1 = __ldg(gamma+col+1);
            float h0 = __ldg(beta+col),  h1 = __ldg(beta+col+1);
            float v0 = leaky((acc[mf][nf][0] + e0)*q0 + h0);
            float v1 = leaky((acc[mf][nf][1] + e1)*q1 + h1);
            float v2 = leaky((acc[mf][nf][2] + e0)*q0 + h0);
            float v3 = leaky((acc[mf][nf][3] + e1)*q1 + h1);
            #pragma unroll
            for (int j = 0; j < 3; j++) {
                float w0 = __ldg(Wf3 + col*3 + j);
                float w1 = __ldg(Wf3 + (col+1)*3 + j);
                sLo[j] += v0*w0 + v1*w1;
                sHi[j] += v2*w0 + v3*w1;
            }
        }
        #pragma unroll
        for (int j = 0; j < 3; j++) {
            sLo[j] += __shfl_xor_sync(0xFFFFFFFF, sLo[j], 1);
            sLo[j] += __shfl_xor_sync(0xFFFFFFFF, sLo[j], 2);
            sHi[j] += __shfl_xor_sync(0xFFFFFFFF, sHi[j], 1);
            sHi[j] += __shfl_xor_sync(0xFFFFFFFF, sHi[j], 2);
        }
        if (tig == 0) {
            int rl = wm + mf*16 + gid;
            #pragma unroll
            for (int j = 0; j < 3; j++) {
                atomicAdd(&sAcc[rl][j],     sLo[j]);
                atomicAdd(&sAcc[rl + 8][j], sHi[j]);
            }
        }
    }

    __syncthreads();
    if (t < 64) {
        int p = m0 + t;
        #pragma unroll
        for (int j = 0; j < 3; j++)
            out[p*3+j] = x[p*3+j] + 0.1f*(sAcc[t][j] + __ldg(bf3+j));
    }
}

// ---------------- launch -------------------------------------------------------
extern "C" void kernel_launch(void* const* d_in, const int* in_sizes, int n_in,
                              void* d_out, int out_size)
{
    const float* x   = (const float*)d_in[0];
    const float* W1  = (const float*)d_in[1];
    const float* b1  = (const float*)d_in[2];
    const float* g1  = (const float*)d_in[3];
    const float* be1 = (const float*)d_in[4];
    const float* W2  = (const float*)d_in[5];
    const float* b2  = (const float*)d_in[6];
    const float* g2  = (const float*)d_in[7];
    const float* be2 = (const float*)d_in[8];
    const float* Ws1 = (const float*)d_in[9];
    const float* bs1 = (const float*)d_in[10];
    const float* Ws2 = (const float*)d_in[11];
    const float* bs2 = (const float*)d_in[12];
    const float* Wf1 = (const float*)d_in[13];
    const float* bf1 = (const float*)d_in[14];
    const float* gf1 = (const float*)d_in[15];
    const float* bef1= (const float*)d_in[16];
    const float* Wf2 = (const float*)d_in[17];
    const float* bf2 = (const float*)d_in[18];
    const float* gf2 = (const float*)d_in[19];
    const float* bef2= (const float*)d_in[20];
    const float* Wf3 = (const float*)d_in[21];
    const float* bf3 = (const float*)d_in[22];
    float* out = (float*)d_out;

    void *p_G1B, *p_Bt2B;
    cudaGetSymbolAddress(&p_G1B,  g_G1B);
    cudaGetSymbolAddress(&p_Bt2B, g_Bt2B);

    cudaFuncSetAttribute(k_knn,   cudaFuncAttributeMaxDynamicSharedMemorySize, KNN_SMEM);
    cudaFuncSetAttribute(k_aggf1, cudaFuncAttributeMaxDynamicSharedMemorySize, F1_SMEM);
    cudaFuncSetAttribute(k_f2,    cudaFuncAttributeMaxDynamicSharedMemorySize, SMEM_F2);

    // 1. KNN
    k_knn<<<dim3(NN/128, BB), 1024, KNN_SMEM>>>(x);

    // 2. feature + suppressor + PQ GEMM (+ Wf1/Wf2 transposes in extra blocks)
    k_ppq<<<NP/64 + 192, 256>>>(x, W1, b1, g1, be1, Ws1, bs1, Ws2, bs2, W2, Wf1, Wf2);

    // 3. fused gather/max-agg + fusion layer 1
    k_aggf1<<<NP/64, 256, F1_SMEM>>>(b2, g2, be2, bf1, gf1, bef1);

    // 4. fusion layer 2 + 128->3 projection + residual
    k_f2<<<NP/64, 256, SMEM_F2>>>((const bf16*)p_G1B, (const bf16*)p_Bt2B,
                                  bf2, gf2, bef2, out, x, Wf3, bf3);
}

// round 9
// speedup vs baseline: 2.5926x; 1.0784x over previous
#include <cuda_runtime.h>
#include <cuda_bf16.h>
#include <float.h>
#include <math.h>
#include <stdint.h>

// Problem constants
#define BB 8
#define NN 2048
#define NP (BB*NN)        // 16384 points
#define DD 64
#define KNB 8
#define LV 3
#define H1 256
#define H2 128

typedef __nv_bfloat16 bf16;

// ---------------- scratch (device globals; no allocation allowed) --------------
__device__ bf16  g_PQb  [NP*128];      // [16384,128] bf16; cols 0-63 P, 64-127 Q
__device__ float g_fw   [NP*LV];
__device__ int   g_idx  [NP*KNB];
__device__ bf16  g_G1B  [NP*H1];       // [16384,256] bf16
__device__ bf16  g_Bt1B [H1*192];      // Wf1^T bf16 [256][192]
__device__ bf16  g_Bt2B [H2*H1];       // Wf2^T bf16 [128][256]

__device__ __forceinline__ float leaky(float v){ return v > 0.f ? v : 0.2f*v; }

__device__ __forceinline__ uint32_t smem_u32(const void* p) {
    uint32_t a;
    asm("{ .reg .u64 t; cvta.to.shared.u64 t, %1; cvt.u32.u64 %0, t; }" : "=r"(a) : "l"(p));
    return a;
}

#define CP_ASYNC16(d, s) do { \
    size_t _gs = __cvta_generic_to_global(s); \
    asm volatile("cp.async.cg.shared.global [%0], [%1], 16;" :: "r"(d), "l"(_gs) : "memory"); \
} while (0)
#define CP_COMMIT()  asm volatile("cp.async.commit_group;" ::: "memory")
#define CP_WAIT(n)   asm volatile("cp.async.wait_group %0;" :: "n"(n) : "memory")

__device__ __forceinline__ void mma_bf16(float* c, const uint32_t* a, const uint32_t* b) {
    asm volatile(
        "mma.sync.aligned.m16n8k16.row.col.f32.bf16.bf16.f32 "
        "{%0,%1,%2,%3}, {%4,%5,%6,%7}, {%8,%9}, {%0,%1,%2,%3};"
        : "+f"(c[0]), "+f"(c[1]), "+f"(c[2]), "+f"(c[3])
        : "r"(a[0]), "r"(a[1]), "r"(a[2]), "r"(a[3]), "r"(b[0]), "r"(b[1]));
}

__device__ __forceinline__ float bf2f(uint32_t u, int hi) {
    __nv_bfloat162 v = *(__nv_bfloat162*)&u;
    return hi ? __bfloat162float(v.y) : __bfloat162float(v.x);
}

// ================ kernel 1 (front): KNN || feature+PQ GEMM || weight prep ======
// blocks [0,128):   KNN (8-way candidate split, 1024 thr)
// blocks [128,192): feature transform + suppressor + PQ mma, 256 points/block
// blocks [192,240): Wf1/Wf2 transposes to bf16
#define FRONT_SMEM (NN*16 + 7*128*KNB*4 + 7*128*KNB*4)   // 90112 bytes (KNN layout)
#define BSRQ 36     // u32 per Btpq smem row
#define ASRQ 36     // u32 per feat smem row

__global__ void __launch_bounds__(1024)
k_front(const float* __restrict__ x,
        const float* __restrict__ W1, const float* __restrict__ b1,
        const float* __restrict__ g1, const float* __restrict__ be1,
        const float* __restrict__ Ws1, const float* __restrict__ bs1,
        const float* __restrict__ Ws2, const float* __restrict__ bs2,
        const float* __restrict__ W2, const float* __restrict__ Wf1,
        const float* __restrict__ Wf2)
{
    extern __shared__ char fsm[];
    const int bx = blockIdx.x;
    const int tid = threadIdx.x;

    if (bx >= 192) {                 // ---- weight prep ----
        int i = (bx - 192)*1024 + tid;
        if (i < H1*192) { int n = i/192, k = i%192; g_Bt1B[i] = __float2bfloat16_rn(Wf1[k*H1 + n]); }
        if (i < H2*H1)  { int n = i>>8,  k = i&255; g_Bt2B[i] = __float2bfloat16_rn(Wf2[k*H2 + n]); }
        return;
    }

    if (bx >= 128) {                 // ---- feature + suppressor + PQ GEMM ----
        uint32_t* sB = (uint32_t*)fsm;                 // Btpq [128][64bf16]   4608 u32
        uint32_t* sAall = (uint32_t*)fsm + 128*BSRQ;   // 4 tiles x [64][64]   9216 u32

        const int tile = tid >> 8;        // 0..3
        const int t256 = tid & 255;
        const int m0 = (bx - 128)*256 + tile*64;

        // fill shared Btpq (one copy for all 4 tiles)
        bf16* sBh = (bf16*)sB;
        for (int i = tid; i < 128*64; i += 1024) {
            int k = i >> 7, n = i & 127;
            float w = (n < 64) ? W2[k*DD + n] : W2[(64 + k)*DD + (n - 64)];
            sBh[n*(2*BSRQ) + k] = __float2bfloat16_rn(w);
        }

        // feature transform + suppressor (4 thr/point, 16 dims each)
        const int pt = t256 >> 2, q = t256 & 3, d0 = q*16;
        const int p = m0 + pt;
        float x0 = x[p*3+0], x1 = x[p*3+1], x2 = x[p*3+2];
        float s0 = 0.f, s1 = 0.f, s2 = 0.f;
        bf16* sAh = (bf16*)(sAall + tile*64*ASRQ);
        #pragma unroll
        for (int j = 0; j < 16; j++) {
            int d = d0 + j;
            float f = x0*W1[d] + x1*W1[DD+d] + x2*W1[2*DD+d] + b1[d];
            f = leaky(f*g1[d] + be1[d]);
            sAh[pt*(2*ASRQ) + d] = __float2bfloat16_rn(f);
            float hh = x0*Ws1[d] + x1*Ws1[DD+d] + x2*Ws1[2*DD+d] + bs1[d];
            hh = hh > 0.f ? hh : 0.f;
            s0 += hh*Ws2[d*LV+0]; s1 += hh*Ws2[d*LV+1]; s2 += hh*Ws2[d*LV+2];
        }
        s0 += __shfl_xor_sync(0xFFFFFFFF, s0, 1); s0 += __shfl_xor_sync(0xFFFFFFFF, s0, 2);
        s1 += __shfl_xor_sync(0xFFFFFFFF, s1, 1); s1 += __shfl_xor_sync(0xFFFFFFFF, s1, 2);
        s2 += __shfl_xor_sync(0xFFFFFFFF, s2, 1); s2 += __shfl_xor_sync(0xFFFFFFFF, s2, 2);
        if (q == 0) {
            g_fw[p*LV+0] = 1.f/(1.f + expf(-s0));
            g_fw[p*LV+1] = 1.f/(1.f + expf(-s1));
            g_fw[p*LV+2] = 1.f/(1.f + expf(-s2));
        }
        __syncthreads();

        // mma 64x128x64 per tile (8 warps/tile)
        const int w8 = (tid >> 5) & 7;
        const int lane = tid & 31, gid = lane >> 2, tig = lane & 3;
        const int wm = (w8 & 1)*32, wn = (w8 >> 1)*32;
        const uint32_t* sA = sAall + tile*64*ASRQ;
        float acc[2][4][4] = {};
        #pragma unroll
        for (int ks = 0; ks < 4; ks++) {
            const int ko = ks*8;
            uint32_t af[2][4], bfr[4][2];
            #pragma unroll
            for (int mf = 0; mf < 2; mf++) {
                const uint32_t* ap = sA + (wm + mf*16 + gid)*ASRQ + ko + tig;
                af[mf][0] = ap[0];
                af[mf][1] = ap[8*ASRQ];
                af[mf][2] = ap[4];
                af[mf][3] = ap[8*ASRQ + 4];
            }
            #pragma unroll
            for (int nf = 0; nf < 4; nf++) {
                const uint32_t* bp = sB + (wn + nf*8 + gid)*BSRQ + ko + tig;
                bfr[nf][0] = bp[0];
                bfr[nf][1] = bp[4];
            }
            #pragma unroll
            for (int mf = 0; mf < 2; mf++)
                #pragma unroll
                for (int nf = 0; nf < 4; nf++)
                    mma_bf16(acc[mf][nf], af[mf], bfr[nf]);
        }
        #pragma unroll
        for (int mf = 0; mf < 2; mf++) {
            const int row = m0 + wm + mf*16 + gid;
            #pragma unroll
            for (int nf = 0; nf < 4; nf++) {
                const int col = wn + nf*8 + tig*2;
                __nv_bfloat162 lo, hi;
                lo.x = __float2bfloat16_rn(acc[mf][nf][0]); lo.y = __float2bfloat16_rn(acc[mf][nf][1]);
                hi.x = __float2bfloat16_rn(acc[mf][nf][2]); hi.y = __float2bfloat16_rn(acc[mf][nf][3]);
                *(__nv_bfloat162*)(g_PQb + (size_t)row*128 + col)     = lo;
                *(__nv_bfloat162*)(g_PQb + (size_t)(row+8)*128 + col) = hi;
            }
        }
        return;
    }

    // ---- KNN path: blocks [0,128) ----
    {
        float4* sc  = (float4*)fsm;
        float*  smd = (float*)(fsm + NN*16);
        int*    smi = (int*)(fsm + NN*16 + 7*128*KNB*4);

        const int ql = tid & 127;
        const int h  = tid >> 7;          // 0..7
        const int b  = bx >> 4;
        const int i  = (bx & 15)*128 + ql;

        for (int j = tid; j < NN; j += 1024) {
            float a = x[(b*NN + j)*3 + 0];
            float c = x[(b*NN + j)*3 + 1];
            float e = x[(b*NN + j)*3 + 2];
            sc[j] = make_float4(a, c, e, a*a + c*c + e*e);
        }
        __syncthreads();

        float4 q4 = sc[i];
        float xi0 = q4.x, xi1 = q4.y, xi2 = q4.z, ni = q4.w;

        float bd[KNB]; int bi[KNB];
        #pragma unroll
        for (int t = 0; t < KNB; t++) { bd[t] = FLT_MAX; bi[t] = 0; }

        const int j0 = h*(NN/8), j1 = j0 + NN/8;
        #pragma unroll 4
        for (int j = j0; j < j1; j++) {
            float4 c4 = sc[j];
            float d2 = ni + c4.w - 2.f*(xi0*c4.x + xi1*c4.y + xi2*c4.z);
            if (d2 < bd[KNB-1]) {
                bd[KNB-1] = d2; bi[KNB-1] = j;
                #pragma unroll
                for (int t = KNB-1; t > 0; t--) {
                    if (bd[t] < bd[t-1]) {
                        float td = bd[t]; bd[t] = bd[t-1]; bd[t-1] = td;
                        int   ti = bi[t]; bi[t] = bi[t-1]; bi[t-1] = ti;
                    }
                }
            }
        }

        if (h > 0) {
            int s = ((h-1)*128 + ql)*KNB;
            #pragma unroll
            for (int t = 0; t < KNB; t++) { smd[s+t] = bd[t]; smi[s+t] = bi[t]; }
        }
        __syncthreads();

        if (h == 0) {
            #pragma unroll
            for (int hh = 0; hh < 7; hh++) {
                int s = (hh*128 + ql)*KNB;
                #pragma unroll
                for (int t = 0; t < KNB; t++) {
                    float d2 = smd[s+t]; int jj = smi[s+t];
                    if (d2 < bd[KNB-1]) {
                        bd[KNB-1] = d2; bi[KNB-1] = jj;
                        #pragma unroll
                        for (int u = KNB-1; u > 0; u--) {
                            if (bd[u] < bd[u-1]) {
                                float td = bd[u]; bd[u] = bd[u-1]; bd[u-1] = td;
                                int   ti = bi[u]; bi[u] = bi[u-1]; bi[u-1] = ti;
                            }
                        }
                    }
                }
            }
            int p = b*NN + i;
            #pragma unroll
            for (int t = 0; t < KNB; t++) g_idx[p*KNB + t] = bi[t];
        }
    }
}

// ================= kernel 2: fused agg + fusion layer 1 (single-shot B) ========
// grid (NP/64, 2): 64 points x 128 output cols per CTA.
// All B rows cp.async-issued BEFORE gather phase; K loop has no syncs.
#define F1_ASR 100                          // u32/A row (192 bf16 + pad)
#define F1_BSR 100                          // u32/B row
#define F1_ABUF (64*F1_ASR)                 // 6400 u32
#define F1_BBUF (128*F1_BSR)                // 12800 u32
#define F1_SMEM ((F1_ABUF + F1_BBUF)*4)     // 76800 bytes

__global__ void __launch_bounds__(256)
k_aggf1(const float* __restrict__ b2, const float* __restrict__ g2,
        const float* __restrict__ be2,
        const float* __restrict__ bias, const float* __restrict__ gamma,
        const float* __restrict__ beta)
{
    extern __shared__ uint32_t sm32[];
    uint32_t* sA = sm32;
    uint32_t* sB = sm32 + F1_ABUF;

    const int t = threadIdx.x, lane = t & 31, wid = t >> 5;
    const int gid = lane >> 2, tig = lane & 3;
    const int m0 = blockIdx.x * 64;
    const int n0 = blockIdx.y * 128;
    const uint32_t sbase = smem_u32(sm32);

    // issue ALL B loads now (128 rows x 384B = 24 x 16B segs, 12/thread)
    {
        uint32_t bbase = sbase + F1_ABUF*4u;
        #pragma unroll
        for (int it = 0; it < 12; it++) {
            int i = it*256 + t;
            int row = i/24, seg = i%24;
            CP_ASYNC16(bbase + (uint32_t)(row*400 + seg*16),
                       g_Bt1B + (size_t)(n0 + row)*192 + seg*8);
        }
        CP_COMMIT();
    }

    // ---- phase 1: agg for 64 points (4 thr/point, 16 dims each) ----
    {
        const int pt = t >> 2, q = t & 3, d0 = q*16;
        const int p = m0 + pt, b = p >> 11;

        float pv[16], gg[16], cc[16], m[16];
        uint4 pv0 = *(const uint4*)(g_PQb + (size_t)p*128 + d0);
        uint4 pv1 = *(const uint4*)(g_PQb + (size_t)p*128 + d0 + 8);
        #pragma unroll
        for (int j = 0; j < 8; j++) {
            pv[j]   = bf2f(((const uint32_t*)&pv0)[j>>1], j&1);
            pv[8+j] = bf2f(((const uint32_t*)&pv1)[j>>1], j&1);
        }
        #pragma unroll
        for (int j = 0; j < 16; j++) {
            gg[j] = g2[d0+j];
            cc[j] = b2[d0+j]*gg[j] + be2[d0+j];
            m[j] = -FLT_MAX;
        }
        int idx[KNB];
        *(int4*)&idx[0] = *(const int4*)(g_idx + p*KNB);
        *(int4*)&idx[4] = *(const int4*)(g_idx + p*KNB + 4);
        #pragma unroll
        for (int k = 0; k < KNB; k++) {
            const bf16* qrow = g_PQb + (size_t)(b*NN + idx[k])*128 + 64 + d0;
            uint4 qv0 = *(const uint4*)(qrow);
            uint4 qv1 = *(const uint4*)(qrow + 8);
            #pragma unroll
            for (int j = 0; j < 8; j++) {
                float qa = bf2f(((const uint32_t*)&qv0)[j>>1], j&1);
                float qb = bf2f(((const uint32_t*)&qv1)[j>>1], j&1);
                m[j]   = fmaxf(m[j],   leaky((pv[j]   + qa)*gg[j]   + cc[j]));
                m[8+j] = fmaxf(m[8+j], leaky((pv[8+j] + qb)*gg[8+j] + cc[8+j]));
            }
        }
        float f0 = g_fw[p*LV+0], f1 = g_fw[p*LV+1], f2 = g_fw[p*LV+2];
        bf16* sAh = (bf16*)sA;
        #pragma unroll
        for (int j = 0; j < 16; j++) {
            int d = d0 + j;
            sAh[pt*(2*F1_ASR) + d]       = __float2bfloat16_rn(m[j]*f0);
            sAh[pt*(2*F1_ASR) + 64 + d]  = __float2bfloat16_rn(m[j]*f1);
            sAh[pt*(2*F1_ASR) + 128 + d] = __float2bfloat16_rn(m[j]*f2);
        }
    }
    CP_WAIT(0);
    __syncthreads();

    // ---- phase 2: GEMM 64x128x192, zero barriers ----
    const int wm = (wid & 1)*32, wn = (wid >> 1)*32;
    float acc[2][4][4] = {};
    #pragma unroll
    for (int ks = 0; ks < 12; ks++) {
        const int ko = ks*8;
        uint32_t af[2][4], bfr[4][2];
        #pragma unroll
        for (int mf = 0; mf < 2; mf++) {
            const uint32_t* ap = sA + (wm + mf*16 + gid)*F1_ASR + ko + tig;
            af[mf][0] = ap[0];
            af[mf][1] = ap[8*F1_ASR];
            af[mf][2] = ap[4];
            af[mf][3] = ap[8*F1_ASR + 4];
        }
        #pragma unroll
        for (int nf = 0; nf < 4; nf++) {
            const uint32_t* bp = sB + (wn + nf*8 + gid)*F1_BSR + ko + tig;
            bfr[nf][0] = bp[0];
            bfr[nf][1] = bp[4];
        }
        #pragma unroll
        for (int mf = 0; mf < 2; mf++)
            #pragma unroll
            for (int nf = 0; nf < 4; nf++)
                mma_bf16(acc[mf][nf], af[mf], bfr[nf]);
    }

    // ---- epilogue: affine + leaky -> G1B bf16 ----
    #pragma unroll
    for (int mf = 0; mf < 2; mf++) {
        const int row = m0 + wm + mf*16 + gid;
        #pragma unroll
        for (int nf = 0; nf < 4; nf++) {
            const int col = n0 + wn + nf*8 + tig*2;
            float e0 = __ldg(bias+col),  e1 = __ldg(bias+col+1);
            float q0 = __ldg(gamma+col), q1 = __ldg(gamma+col+1);
            float h0 = __ldg(beta+col),  h1 = __ldg(beta+col+1);
            float v0 = leaky((acc[mf][nf][0] + e0)*q0 + h0);
            float v1 = leaky((acc[mf][nf][1] + e1)*q1 + h1);
            float v2 = leaky((acc[mf][nf][2] + e0)*q0 + h0);
            float v3 = leaky((acc[mf][nf][3] + e1)*q1 + h1);
            __nv_bfloat162 lo, hi;
            lo.x = __float2bfloat16_rn(v0); lo.y = __float2bfloat16_rn(v1);
            hi.x = __float2bfloat16_rn(v2); hi.y = __float2bfloat16_rn(v3);
            *(__nv_bfloat162*)(g_G1B + (size_t)row*H1 + col)     = lo;
            *(__nv_bfloat162*)(g_G1B + (size_t)(row+8)*H1 + col) = hi;
        }
    }
}

// ================= kernel 3: fusion layer 2 + projection + residual ============
// Single-shot: whole A (64x256) and B (128x256) staged once, 16 unrolled k-steps.
#define SRF 132                          // u32 per row (256 bf16 + pad)
#define F2_ABUF (64*SRF)                 // 8448 u32
#define F2_BBUF (128*SRF)                // 16896 u32
#define SMEM_F2 ((F2_ABUF + F2_BBUF)*4)  // 101376 bytes

__global__ void __launch_bounds__(256)
k_f2(const bf16* __restrict__ A, const bf16* __restrict__ Bt,
     const float* __restrict__ bias, const float* __restrict__ gamma,
     const float* __restrict__ beta, float* __restrict__ out,
     const float* __restrict__ x, const float* __restrict__ Wf3,
     const float* __restrict__ bf3)
{
    extern __shared__ uint32_t sm32[];
    __shared__ float sAcc[64][3];
    uint32_t* sA = sm32;
    uint32_t* sB = sm32 + F2_ABUF;

    const int t = threadIdx.x, lane = t & 31, wid = t >> 5;
    const int gid = lane >> 2, tig = lane & 3;
    const int wm = (wid & 1) * 32, wn = (wid >> 1) * 32;
    const int m0 = blockIdx.x * 64;
    const uint32_t sbase = smem_u32(sm32);

    // stage A: 64 rows x 512B (32 segs), 8 per thread
    #pragma unroll
    for (int it = 0; it < 8; it++) {
        int i = it*256 + t;
        int row = i >> 5, seg = i & 31;
        CP_ASYNC16(sbase + (uint32_t)(row*528 + seg*16),
                   A + (size_t)(m0 + row)*256 + seg*8);
    }
    // stage B: 128 rows x 512B, 16 per thread
    #pragma unroll
    for (int it = 0; it < 16; it++) {
        int i = it*256 + t;
        int row = i >> 5, seg = i & 31;
        CP_ASYNC16(sbase + F2_ABUF*4u + (uint32_t)(row*528 + seg*16),
                   Bt + (size_t)row*256 + seg*8);
    }
    CP_COMMIT();

    if (t < 192) sAcc[t/3][t%3] = 0.f;

    CP_WAIT(0);
    __syncthreads();

    float acc[2][4][4] = {};
    #pragma unroll
    for (int ks = 0; ks < 16; ks++) {
        const int ko = ks*8;
        uint32_t af[2][4], bfr[4][2];
        #pragma unroll
        for (int mf = 0; mf < 2; mf++) {
            const uint32_t* ap = sA + (wm + mf*16 + gid)*SRF + ko + tig;
            af[mf][0] = ap[0];
            af[mf][1] = ap[8*SRF];
            af[mf][2] = ap[4];
            af[mf][3] = ap[8*SRF + 4];
        }
        #pragma unroll
        for (int nf = 0; nf < 4; nf++) {
            const uint32_t* bp = sB + (wn + nf*8 + gid)*SRF + ko + tig;
            bfr[nf][0] = bp[0];
            bfr[nf][1] = bp[4];
        }
        #pragma unroll
        for (int mf = 0; mf < 2; mf++)
            #pragma unroll
            for (int nf = 0; nf < 4; nf++)
                mma_bf16(acc[mf][nf], af[mf], bfr[nf]);
    }

    #pragma unroll
    for (int mf = 0; mf < 2; mf++) {
        float sLo[3] = {0.f,0.f,0.f}, sHi[3] = {0.f,0.f,0.f};
        #pragma unroll
        for (int nf = 0; nf < 4; nf++) {
            const int col = wn + nf*8 + tig*2;
            float e0 = __ldg(bias+col),  e1 = __ldg(bias+col+1);
            float q0 = __ldg(gamma+col), q1 = __ldg(gamma+col+1);
            float h0 = __ldg(beta+col),  h1 = __ldg(beta+col+1);
            float v0 = leaky((acc[mf][nf][0] + e0)*q0 + h0);
            float v1 = leaky((acc[mf][nf][1] + e1)*q1 + h1);
            float v2 = leaky((acc[mf][nf][2] + e0)*q0 + h0);
            float v3 = leaky((acc[mf][nf][3] + e1)*q1 + h1);
            #pragma unroll
            for (int j = 0; j < 3; j++) {
                float w0 = __ldg(Wf3 + col*3 + j);
                float w1 = __ldg(Wf3 + (col+1)*3 + j);
                sLo[j] += v0*w0 + v1*w1;
                sHi[j] += v2*w0 + v3*w1;
            }
        }
        #pragma unroll
        for (int j = 0; j < 3; j++) {
            sLo[j] += __shfl_xor_sync(0xFFFFFFFF, sLo[j], 1);
            sLo[j] += __shfl_xor_sync(0xFFFFFFFF, sLo[j], 2);
            sHi[j] += __shfl_xor_sync(0xFFFFFFFF, sHi[j], 1);
            sHi[j] += __shfl_xor_sync(0xFFFFFFFF, sHi[j], 2);
        }
        if (tig == 0) {
            int rl = wm + mf*16 + gid;
            #pragma unroll
            for (int j = 0; j < 3; j++) {
                atomicAdd(&sAcc[rl][j],     sLo[j]);
                atomicAdd(&sAcc[rl + 8][j], sHi[j]);
            }
        }
    }

    __syncthreads();
    if (t < 64) {
        int p = m0 + t;
        #pragma unroll
        for (int j = 0; j < 3; j++)
            out[p*3+j] = x[p*3+j] + 0.1f*(sAcc[t][j] + __ldg(bf3+j));
    }
}

// ---------------- launch -------------------------------------------------------
extern "C" void kernel_launch(void* const* d_in, const int* in_sizes, int n_in,
                              void* d_out, int out_size)
{
    const float* x   = (const float*)d_in[0];
    const float* W1  = (const float*)d_in[1];
    const float* b1  = (const float*)d_in[2];
    const float* g1  = (const float*)d_in[3];
    const float* be1 = (const float*)d_in[4];
    const float* W2  = (const float*)d_in[5];
    const float* b2  = (const float*)d_in[6];
    const float* g2  = (const float*)d_in[7];
    const float* be2 = (const float*)d_in[8];
    const float* Ws1 = (const float*)d_in[9];
    const float* bs1 = (const float*)d_in[10];
    const float* Ws2 = (const float*)d_in[11];
    const float* bs2 = (const float*)d_in[12];
    const float* Wf1 = (const float*)d_in[13];
    const float* bf1 = (const float*)d_in[14];
    const float* gf1 = (const float*)d_in[15];
    const float* bef1= (const float*)d_in[16];
    const float* Wf2 = (const float*)d_in[17];
    const float* bf2 = (const float*)d_in[18];
    const float* gf2 = (const float*)d_in[19];
    const float* bef2= (const float*)d_in[20];
    const float* Wf3 = (const float*)d_in[21];
    const float* bf3 = (const float*)d_in[22];
    float* out = (float*)d_out;

    void *p_G1B, *p_Bt2B;
    cudaGetSymbolAddress(&p_G1B,  g_G1B);
    cudaGetSymbolAddress(&p_Bt2B, g_Bt2B);

    cudaFuncSetAttribute(k_front,  cudaFuncAttributeMaxDynamicSharedMemorySize, FRONT_SMEM);
    cudaFuncSetAttribute(k_aggf1,  cudaFuncAttributeMaxDynamicSharedMemorySize, F1_SMEM);
    cudaFuncSetAttribute(k_f2,     cudaFuncAttributeMaxDynamicSharedMemorySize, SMEM_F2);

    // 1. KNN || feature+PQ || weight prep  (240 blocks, co-scheduled)
    k_front<<<128 + 64 + 48, 1024, FRONT_SMEM>>>(
        x, W1, b1, g1, be1, Ws1, bs1, Ws2, bs2, W2, Wf1, Wf2);

    // 2. fused gather/max-agg + fusion layer 1 (512 CTAs)
    k_aggf1<<<dim3(NP/64, 2), 256, F1_SMEM>>>(b2, g2, be2, bf1, gf1, bef1);

    // 3. fusion layer 2 + 128->3 projection + residual
    k_f2<<<NP/64, 256, SMEM_F2>>>((const bf16*)p_G1B, (const bf16*)p_Bt2B,
                                  bf2, gf2, bef2, out, x, Wf3, bf3);
}

// round 10
// speedup vs baseline: 3.2582x; 1.2567x over previous
#include <cuda_runtime.h>
#include <cuda_bf16.h>
#include <float.h>
#include <math.h>
#include <stdint.h>

// Problem constants
#define BB 8
#define NN 2048
#define NP (BB*NN)        // 16384 points
#define DD 64
#define KNB 8
#define LV 3
#define H1 256
#define H2 128

typedef __nv_bfloat16 bf16;

// ---------------- scratch (device globals; no allocation allowed) --------------
__device__ bf16  g_PQb  [NP*128];      // [16384,128] bf16; cols 0-63 P, 64-127 Q
__device__ float g_fw   [NP*LV];
__device__ int   g_idx  [NP*KNB];
__device__ bf16  g_G1B  [NP*H1];       // [16384,256] bf16
__device__ bf16  g_Bt1B [H1*192];      // Wf1^T bf16 [256][192]
__device__ bf16  g_Bt2B [H2*H1];       // Wf2^T bf16 [128][256]

__device__ __forceinline__ float leaky(float v){ return v > 0.f ? v : 0.2f*v; }

__device__ __forceinline__ uint32_t smem_u32(const void* p) {
    uint32_t a;
    asm("{ .reg .u64 t; cvta.to.shared.u64 t, %1; cvt.u32.u64 %0, t; }" : "=r"(a) : "l"(p));
    return a;
}

// monotonic float->u32 map (order-preserving incl. negatives)
__device__ __forceinline__ uint32_t fmap(float f) {
    uint32_t u = __float_as_uint(f);
    return u ^ ((uint32_t)(((int32_t)u) >> 31) | 0x80000000u);
}

#define CP_ASYNC16(d, s) do { \
    size_t _gs = __cvta_generic_to_global(s); \
    asm volatile("cp.async.cg.shared.global [%0], [%1], 16;" :: "r"(d), "l"(_gs) : "memory"); \
} while (0)
#define CP_COMMIT()  asm volatile("cp.async.commit_group;" ::: "memory")
#define CP_WAIT(n)   asm volatile("cp.async.wait_group %0;" :: "n"(n) : "memory")

__device__ __forceinline__ void mma_bf16(float* c, const uint32_t* a, const uint32_t* b) {
    asm volatile(
        "mma.sync.aligned.m16n8k16.row.col.f32.bf16.bf16.f32 "
        "{%0,%1,%2,%3}, {%4,%5,%6,%7}, {%8,%9}, {%0,%1,%2,%3};"
        : "+f"(c[0]), "+f"(c[1]), "+f"(c[2]), "+f"(c[3])
        : "r"(a[0]), "r"(a[1]), "r"(a[2]), "r"(a[3]), "r"(b[0]), "r"(b[1]));
}

__device__ __forceinline__ float bf2f(uint32_t u, int hi) {
    __nv_bfloat162 v = *(__nv_bfloat162*)&u;
    return hi ? __bfloat162float(v.y) : __bfloat162float(v.x);
}

// ================ kernel 1 (front): KNN || feature+PQ GEMM || weight prep ======
// blocks [0,256):   KNN warp-cooperative top-8, 2 queries/warp, 64 queries/block
// blocks [256,320): feature transform + suppressor + PQ mma, 256 points/block
// blocks [320,368): Wf1/Wf2 transposes to bf16
#define BSRQ 36     // u32 per Btpq smem row
#define ASRQ 36     // u32 per feat smem row
#define FRONT_SMEM ((128*BSRQ + 4*64*ASRQ)*4)   // 55296 bytes (>= KNN's 32KB)

__global__ void __launch_bounds__(1024)
k_front(const float* __restrict__ x,
        const float* __restrict__ W1, const float* __restrict__ b1,
        const float* __restrict__ g1, const float* __restrict__ be1,
        const float* __restrict__ Ws1, const float* __restrict__ bs1,
        const float* __restrict__ Ws2, const float* __restrict__ bs2,
        const float* __restrict__ W2, const float* __restrict__ Wf1,
        const float* __restrict__ Wf2)
{
    extern __shared__ char fsm[];
    const int bx = blockIdx.x;
    const int tid = threadIdx.x;

    if (bx >= 320) {                 // ---- weight prep ----
        int i = (bx - 320)*1024 + tid;
        if (i < H1*192) { int n = i/192, k = i%192; g_Bt1B[i] = __float2bfloat16_rn(Wf1[k*H1 + n]); }
        if (i < H2*H1)  { int n = i>>8,  k = i&255; g_Bt2B[i] = __float2bfloat16_rn(Wf2[k*H2 + n]); }
        return;
    }

    if (bx >= 256) {                 // ---- feature + suppressor + PQ GEMM ----
        uint32_t* sB = (uint32_t*)fsm;                 // Btpq [128][64bf16]
        uint32_t* sAall = (uint32_t*)fsm + 128*BSRQ;   // 4 tiles x [64][64]

        const int tile = tid >> 8;        // 0..3
        const int t256 = tid & 255;
        const int m0 = (bx - 256)*256 + tile*64;

        bf16* sBh = (bf16*)sB;
        for (int i = tid; i < 128*64; i += 1024) {
            int k = i >> 7, n = i & 127;
            float w = (n < 64) ? W2[k*DD + n] : W2[(64 + k)*DD + (n - 64)];
            sBh[n*(2*BSRQ) + k] = __float2bfloat16_rn(w);
        }

        const int pt = t256 >> 2, q = t256 & 3, d0 = q*16;
        const int p = m0 + pt;
        float x0 = x[p*3+0], x1 = x[p*3+1], x2 = x[p*3+2];
        float s0 = 0.f, s1 = 0.f, s2 = 0.f;
        bf16* sAh = (bf16*)(sAall + tile*64*ASRQ);
        #pragma unroll
        for (int j = 0; j < 16; j++) {
            int d = d0 + j;
            float f = x0*W1[d] + x1*W1[DD+d] + x2*W1[2*DD+d] + b1[d];
            f = leaky(f*g1[d] + be1[d]);
            sAh[pt*(2*ASRQ) + d] = __float2bfloat16_rn(f);
            float hh = x0*Ws1[d] + x1*Ws1[DD+d] + x2*Ws1[2*DD+d] + bs1[d];
            hh = hh > 0.f ? hh : 0.f;
            s0 += hh*Ws2[d*LV+0]; s1 += hh*Ws2[d*LV+1]; s2 += hh*Ws2[d*LV+2];
        }
        s0 += __shfl_xor_sync(0xFFFFFFFF, s0, 1); s0 += __shfl_xor_sync(0xFFFFFFFF, s0, 2);
        s1 += __shfl_xor_sync(0xFFFFFFFF, s1, 1); s1 += __shfl_xor_sync(0xFFFFFFFF, s1, 2);
        s2 += __shfl_xor_sync(0xFFFFFFFF, s2, 1); s2 += __shfl_xor_sync(0xFFFFFFFF, s2, 2);
        if (q == 0) {
            g_fw[p*LV+0] = 1.f/(1.f + expf(-s0));
            g_fw[p*LV+1] = 1.f/(1.f + expf(-s1));
            g_fw[p*LV+2] = 1.f/(1.f + expf(-s2));
        }
        __syncthreads();

        const int w8 = (tid >> 5) & 7;
        const int lane = tid & 31, gid = lane >> 2, tig = lane & 3;
        const int wm = (w8 & 1)*32, wn = (w8 >> 1)*32;
        const uint32_t* sA = sAall + tile*64*ASRQ;
        float acc[2][4][4] = {};
        #pragma unroll
        for (int ks = 0; ks < 4; ks++) {
            const int ko = ks*8;
            uint32_t af[2][4], bfr[4][2];
            #pragma unroll
            for (int mf = 0; mf < 2; mf++) {
                const uint32_t* ap = sA + (wm + mf*16 + gid)*ASRQ + ko + tig;
                af[mf][0] = ap[0];
                af[mf][1] = ap[8*ASRQ];
                af[mf][2] = ap[4];
                af[mf][3] = ap[8*ASRQ + 4];
            }
            #pragma unroll
            for (int nf = 0; nf < 4; nf++) {
                const uint32_t* bp = sB + (wn + nf*8 + gid)*BSRQ + ko + tig;
                bfr[nf][0] = bp[0];
                bfr[nf][1] = bp[4];
            }
            #pragma unroll
            for (int mf = 0; mf < 2; mf++)
                #pragma unroll
                for (int nf = 0; nf < 4; nf++)
                    mma_bf16(acc[mf][nf], af[mf], bfr[nf]);
        }
        #pragma unroll
        for (int mf = 0; mf < 2; mf++) {
            const int row = m0 + wm + mf*16 + gid;
            #pragma unroll
            for (int nf = 0; nf < 4; nf++) {
                const int col = wn + nf*8 + tig*2;
                __nv_bfloat162 lo, hi;
                lo.x = __float2bfloat16_rn(acc[mf][nf][0]); lo.y = __float2bfloat16_rn(acc[mf][nf][1]);
                hi.x = __float2bfloat16_rn(acc[mf][nf][2]); hi.y = __float2bfloat16_rn(acc[mf][nf][3]);
                *(__nv_bfloat162*)(g_PQb + (size_t)row*128 + col)     = lo;
                *(__nv_bfloat162*)(g_PQb + (size_t)(row+8)*128 + col) = hi;
            }
        }
        return;
    }

    // ---- KNN: warp-cooperative top-8, 2 queries per warp ----
    {
        float4* sc = (float4*)fsm;
        const int b  = bx >> 5;           // 32 blocks per batch
        const int qb = (bx & 31) * 64;    // 64 queries per block
        const int w = tid >> 5, lane = tid & 31;

        for (int j = tid; j < NN; j += 1024) {
            float a = x[(b*NN + j)*3 + 0];
            float c = x[(b*NN + j)*3 + 1];
            float e = x[(b*NN + j)*3 + 2];
            sc[j] = make_float4(a, c, e, a*a + c*c + e*e);
        }
        __syncthreads();

        const int q0 = qb + w*2, q1 = q0 + 1;
        float4 A  = sc[q0];
        float4 Bq = sc[q1];

        uint32_t slot = 0xFFFFFFFFu;      // lanes 0-7: q0 top-8; lanes 8-15: q1 top-8
        int sidx = 0;
        uint32_t t0 = 0xFFFFFFFFu, t1 = 0xFFFFFFFFu;
        const bool gA = (lane < 8);
        const bool gB = (lane >= 8) && (lane < 16);

        for (int ch = 0; ch < NN/32; ch++) {
            float4 c = sc[ch*32 + lane];
            float d20 = A.w  + c.w - 2.f*(A.x*c.x  + A.y*c.y  + A.z*c.z);
            float d21 = Bq.w + c.w - 2.f*(Bq.x*c.x + Bq.y*c.y + Bq.z*c.z);
            uint32_t md0 = fmap(d20), md1 = fmap(d21);
            unsigned m0 = __ballot_sync(0xFFFFFFFFu, md0 < t0);
            unsigned m1 = __ballot_sync(0xFFFFFFFFu, md1 < t1);
            while (m0) {
                int src = __ffs(m0) - 1; m0 &= m0 - 1;
                uint32_t cv = __shfl_sync(0xFFFFFFFFu, md0, src);
                if (cv < t0) {
                    unsigned ball = __ballot_sync(0xFFFFFFFFu, gA && slot == t0);
                    int ml = __ffs(ball) - 1;
                    if (lane == ml) { slot = cv; sidx = ch*32 + src; }
                    t0 = __reduce_max_sync(0xFFFFFFFFu, gA ? slot : 0u);
                }
            }
            while (m1) {
                int src = __ffs(m1) - 1; m1 &= m1 - 1;
                uint32_t cv = __shfl_sync(0xFFFFFFFFu, md1, src);
                if (cv < t1) {
                    unsigned ball = __ballot_sync(0xFFFFFFFFu, gB && slot == t1);
                    int ml = __ffs(ball) - 1;
                    if (lane == ml) { slot = cv; sidx = ch*32 + src; }
                    t1 = __reduce_max_sync(0xFFFFFFFFu, gB ? slot : 0u);
                }
            }
        }
        if (gA)      g_idx[(b*NN + q0)*KNB + lane]       = sidx;
        else if (gB) g_idx[(b*NN + q1)*KNB + (lane - 8)] = sidx;
    }
}

// ================= kernel 2: fused agg + fusion layer 1 (single-shot B) ========
#define F1_ASR 100
#define F1_BSR 100
#define F1_ABUF (64*F1_ASR)
#define F1_BBUF (128*F1_BSR)
#define F1_SMEM ((F1_ABUF + F1_BBUF)*4)     // 76800 bytes

__global__ void __launch_bounds__(256)
k_aggf1(const float* __restrict__ b2, const float* __restrict__ g2,
        const float* __restrict__ be2,
        const float* __restrict__ bias, const float* __restrict__ gamma,
        const float* __restrict__ beta)
{
    extern __shared__ uint32_t sm32[];
    uint32_t* sA = sm32;
    uint32_t* sB = sm32 + F1_ABUF;

    const int t = threadIdx.x, lane = t & 31, wid = t >> 5;
    const int gid = lane >> 2, tig = lane & 3;
    const int m0 = blockIdx.x * 64;
    const int n0 = blockIdx.y * 128;
    const uint32_t sbase = smem_u32(sm32);

    {
        uint32_t bbase = sbase + F1_ABUF*4u;
        #pragma unroll
        for (int it = 0; it < 12; it++) {
            int i = it*256 + t;
            int row = i/24, seg = i%24;
            CP_ASYNC16(bbase + (uint32_t)(row*400 + seg*16),
                       g_Bt1B + (size_t)(n0 + row)*192 + seg*8);
        }
        CP_COMMIT();
    }

    {
        const int pt = t >> 2, q = t & 3, d0 = q*16;
        const int p = m0 + pt, b = p >> 11;

        float pv[16], gg[16], cc[16], m[16];
        uint4 pv0 = *(const uint4*)(g_PQb + (size_t)p*128 + d0);
        uint4 pv1 = *(const uint4*)(g_PQb + (size_t)p*128 + d0 + 8);
        #pragma unroll
        for (int j = 0; j < 8; j++) {
            pv[j]   = bf2f(((const uint32_t*)&pv0)[j>>1], j&1);
            pv[8+j] = bf2f(((const uint32_t*)&pv1)[j>>1], j&1);
        }
        #pragma unroll
        for (int j = 0; j < 16; j++) {
            gg[j] = g2[d0+j];
            cc[j] = b2[d0+j]*gg[j] + be2[d0+j];
            m[j] = -FLT_MAX;
        }
        int idx[KNB];
        *(int4*)&idx[0] = *(const int4*)(g_idx + p*KNB);
        *(int4*)&idx[4] = *(const int4*)(g_idx + p*KNB + 4);
        #pragma unroll
        for (int k = 0; k < KNB; k++) {
            const bf16* qrow = g_PQb + (size_t)(b*NN + idx[k])*128 + 64 + d0;
            uint4 qv0 = *(const uint4*)(qrow);
            uint4 qv1 = *(const uint4*)(qrow + 8);
            #pragma unroll
            for (int j = 0; j < 8; j++) {
                float qa = bf2f(((const uint32_t*)&qv0)[j>>1], j&1);
                float qb = bf2f(((const uint32_t*)&qv1)[j>>1], j&1);
                m[j]   = fmaxf(m[j],   leaky((pv[j]   + qa)*gg[j]   + cc[j]));
                m[8+j] = fmaxf(m[8+j], leaky((pv[8+j] + qb)*gg[8+j] + cc[8+j]));
            }
        }
        float f0 = g_fw[p*LV+0], f1 = g_fw[p*LV+1], f2 = g_fw[p*LV+2];
        bf16* sAh = (bf16*)sA;
        #pragma unroll
        for (int j = 0; j < 16; j++) {
            int d = d0 + j;
            sAh[pt*(2*F1_ASR) + d]       = __float2bfloat16_rn(m[j]*f0);
            sAh[pt*(2*F1_ASR) + 64 + d]  = __float2bfloat16_rn(m[j]*f1);
            sAh[pt*(2*F1_ASR) + 128 + d] = __float2bfloat16_rn(m[j]*f2);
        }
    }
    CP_WAIT(0);
    __syncthreads();

    const int wm = (wid & 1)*32, wn = (wid >> 1)*32;
    float acc[2][4][4] = {};
    #pragma unroll
    for (int ks = 0; ks < 12; ks++) {
        const int ko = ks*8;
        uint32_t af[2][4], bfr[4][2];
        #pragma unroll
        for (int mf = 0; mf < 2; mf++) {
            const uint32_t* ap = sA + (wm + mf*16 + gid)*F1_ASR + ko + tig;
            af[mf][0] = ap[0];
            af[mf][1] = ap[8*F1_ASR];
            af[mf][2] = ap[4];
            af[mf][3] = ap[8*F1_ASR + 4];
        }
        #pragma unroll
        for (int nf = 0; nf < 4; nf++) {
            const uint32_t* bp = sB + (wn + nf*8 + gid)*F1_BSR + ko + tig;
            bfr[nf][0] = bp[0];
            bfr[nf][1] = bp[4];
        }
        #pragma unroll
        for (int mf = 0; mf < 2; mf++)
            #pragma unroll
            for (int nf = 0; nf < 4; nf++)
                mma_bf16(acc[mf][nf], af[mf], bfr[nf]);
    }

    #pragma unroll
    for (int mf = 0; mf < 2; mf++) {
        const int row = m0 + wm + mf*16 + gid;
        #pragma unroll
        for (int nf = 0; nf < 4; nf++) {
            const int col = n0 + wn + nf*8 + tig*2;
            float e0 = __ldg(bias+col),  e1 = __ldg(bias+col+1);
            float q0 = __ldg(gamma+col), q1 = __ldg(gamma+col+1);
            float h0 = __ldg(beta+col),  h1 = __ldg(beta+col+1);
            float v0 = leaky((acc[mf][nf][0] + e0)*q0 + h0);
            float v1 = leaky((acc[mf][nf][1] + e1)*q1 + h1);
            float v2 = leaky((acc[mf][nf][2] + e0)*q0 + h0);
            float v3 = leaky((acc[mf][nf][3] + e1)*q1 + h1);
            __nv_bfloat162 lo, hi;
            lo.x = __float2bfloat16_rn(v0); lo.y = __float2bfloat16_rn(v1);
            hi.x = __float2bfloat16_rn(v2); hi.y = __float2bfloat16_rn(v3);
            *(__nv_bfloat162*)(g_G1B + (size_t)row*H1 + col)     = lo;
            *(__nv_bfloat162*)(g_G1B + (size_t)(row+8)*H1 + col) = hi;
        }
    }
}

// ================= kernel 3: fusion layer 2 + projection + residual ============
#define SRF 132
#define F2_ABUF (64*SRF)
#define F2_BBUF (128*SRF)
#define SMEM_F2 ((F2_ABUF + F2_BBUF)*4)  // 101376 bytes

__global__ void __launch_bounds__(256)
k_f2(const bf16* __restrict__ A, const bf16* __restrict__ Bt,
     const float* __restrict__ bias, const float* __restrict__ gamma,
     const float* __restrict__ beta, float* __restrict__ out,
     const float* __restrict__ x, const float* __restrict__ Wf3,
     const float* __restrict__ bf3)
{
    extern __shared__ uint32_t sm32[];
    __shared__ float sAcc[64][3];
    uint32_t* sA = sm32;
    uint32_t* sB = sm32 + F2_ABUF;

    const int t = threadIdx.x, lane = t & 31, wid = t >> 5;
    const int gid = lane >> 2, tig = lane & 3;
    const int wm = (wid & 1) * 32, wn = (wid >> 1) * 32;
    const int m0 = blockIdx.x * 64;
    const uint32_t sbase = smem_u32(sm32);

    #pragma unroll
    for (int it = 0; it < 8; it++) {
        int i = it*256 + t;
        int row = i >> 5, seg = i & 31;
        CP_ASYNC16(sbase + (uint32_t)(row*528 + seg*16),
                   A + (size_t)(m0 + row)*256 + seg*8);
    }
    #pragma unroll
    for (int it = 0; it < 16; it++) {
        int i = it*256 + t;
        int row = i >> 5, seg = i & 31;
        CP_ASYNC16(sbase + F2_ABUF*4u + (uint32_t)(row*528 + seg*16),
                   Bt + (size_t)row*256 + seg*8);
    }
    CP_COMMIT();

    if (t < 192) sAcc[t/3][t%3] = 0.f;

    CP_WAIT(0);
    __syncthreads();

    float acc[2][4][4] = {};
    #pragma unroll
    for (int ks = 0; ks < 16; ks++) {
        const int ko = ks*8;
        uint32_t af[2][4], bfr[4][2];
        #pragma unroll
        for (int mf = 0; mf < 2; mf++) {
            const uint32_t* ap = sA + (wm + mf*16 + gid)*SRF + ko + tig;
            af[mf][0] = ap[0];
            af[mf][1] = ap[8*SRF];
            af[mf][2] = ap[4];
            af[mf][3] = ap[8*SRF + 4];
        }
        #pragma unroll
        for (int nf = 0; nf < 4; nf++) {
            const uint32_t* bp = sB + (wn + nf*8 + gid)*SRF + ko + tig;
            bfr[nf][0] = bp[0];
            bfr[nf][1] = bp[4];
        }
        #pragma unroll
        for (int mf = 0; mf < 2; mf++)
            #pragma unroll
            for (int nf = 0; nf < 4; nf++)
                mma_bf16(acc[mf][nf], af[mf], bfr[nf]);
    }

    #pragma unroll
    for (int mf = 0; mf < 2; mf++) {
        float sLo[3] = {0.f,0.f,0.f}, sHi[3] = {0.f,0.f,0.f};
        #pragma unroll
        for (int nf = 0; nf < 4; nf++) {
            const int col = wn + nf*8 + tig*2;
            float e0 = __ldg(bias+col),  e1 = __ldg(bias+col+1);
            float q0 = __ldg(gamma+col), q1 = __ldg(gamma+col+1);
            float h0 = __ldg(beta+col),  h1 = __ldg(beta+col+1);
            float v0 = leaky((acc[mf][nf][0] + e0)*q0 + h0);
            float v1 = leaky((acc[mf][nf][1] + e1)*q1 + h1);
            float v2 = leaky((acc[mf][nf][2] + e0)*q0 + h0);
            float v3 = leaky((acc[mf][nf][3] + e1)*q1 + h1);
            #pragma unroll
            for (int j = 0; j < 3; j++) {
                float w0 = __ldg(Wf3 + col*3 + j);
                float w1 = __ldg(Wf3 + (col+1)*3 + j);
                sLo[j] += v0*w0 + v1*w1;
                sHi[j] += v2*w0 + v3*w1;
            }
        }
        #pragma unroll
        for (int j = 0; j < 3; j++) {
            sLo[j] += __shfl_xor_sync(0xFFFFFFFF, sLo[j], 1);
            sLo[j] += __shfl_xor_sync(0xFFFFFFFF, sLo[j], 2);
            sHi[j] += __shfl_xor_sync(0xFFFFFFFF, sHi[j], 1);
            sHi[j] += __shfl_xor_sync(0xFFFFFFFF, sHi[j], 2);
        }
        if (tig == 0) {
            int rl = wm + mf*16 + gid;
            #pragma unroll
            for (int j = 0; j < 3; j++) {
                atomicAdd(&sAcc[rl][j],     sLo[j]);
                atomicAdd(&sAcc[rl + 8][j], sHi[j]);
            }
        }
    }

    __syncthreads();
    if (t < 64) {
        int p = m0 + t;
        #pragma unroll
        for (int j = 0; j < 3; j++)
            out[p*3+j] = x[p*3+j] + 0.1f*(sAcc[t][j] + __ldg(bf3+j));
    }
}

// ---------------- launch -------------------------------------------------------
extern "C" void kernel_launch(void* const* d_in, const int* in_sizes, int n_in,
                              void* d_out, int out_size)
{
    const float* x   = (const float*)d_in[0];
    const float* W1  = (const float*)d_in[1];
    const float* b1  = (const float*)d_in[2];
    const float* g1  = (const float*)d_in[3];
    const float* be1 = (const float*)d_in[4];
    const float* W2  = (const float*)d_in[5];
    const float* b2  = (const float*)d_in[6];
    const float* g2  = (const float*)d_in[7];
    const float* be2 = (const float*)d_in[8];
    const float* Ws1 = (const float*)d_in[9];
    const float* bs1 = (const float*)d_in[10];
    const float* Ws2 = (const float*)d_in[11];
    const float* bs2 = (const float*)d_in[12];
    const float* Wf1 = (const float*)d_in[13];
    const float* bf1 = (const float*)d_in[14];
    const float* gf1 = (const float*)d_in[15];
    const float* bef1= (const float*)d_in[16];
    const float* Wf2 = (const float*)d_in[17];
    const float* bf2 = (const float*)d_in[18];
    const float* gf2 = (const float*)d_in[19];
    const float* bef2= (const float*)d_in[20];
    const float* Wf3 = (const float*)d_in[21];
    const float* bf3 = (const float*)d_in[22];
    float* out = (float*)d_out;

    void *p_G1B, *p_Bt2B;
    cudaGetSymbolAddress(&p_G1B,  g_G1B);
    cudaGetSymbolAddress(&p_Bt2B, g_Bt2B);

    cudaFuncSetAttribute(k_front,  cudaFuncAttributeMaxDynamicSharedMemorySize, FRONT_SMEM);
    cudaFuncSetAttribute(k_aggf1,  cudaFuncAttributeMaxDynamicSharedMemorySize, F1_SMEM);
    cudaFuncSetAttribute(k_f2,     cudaFuncAttributeMaxDynamicSharedMemorySize, SMEM_F2);

    // 1. KNN (256 blk) || feature+PQ (64 blk) || weight prep (48 blk)
    k_front<<<256 + 64 + 48, 1024, FRONT_SMEM>>>(
        x, W1, b1, g1, be1, Ws1, bs1, Ws2, bs2, W2, Wf1, Wf2);

    // 2. fused gather/max-agg + fusion layer 1 (512 CTAs)
    k_aggf1<<<dim3(NP/64, 2), 256, F1_SMEM>>>(b2, g2, be2, bf1, gf1, bef1);

    // 3. fusion layer 2 + 128->3 projection + residual
    k_f2<<<NP/64, 256, SMEM_F2>>>((const bf16*)p_G1B, (const bf16*)p_Bt2B,
                                  bf2, gf2, bef2, out, x, Wf3, bf3);
}

// round 11
// speedup vs baseline: 3.4504x; 1.0590x over previous
#include <cuda_runtime.h>
#include <cuda_bf16.h>
#include <float.h>
#include <math.h>
#include <stdint.h>

// Problem constants
#define BB 8
#define NN 2048
#define NP (BB*NN)        // 16384 points
#define DD 64
#define KNB 8
#define LV 3
#define H1 256
#define H2 128

typedef __nv_bfloat16 bf16;

// ---------------- scratch (device globals; no allocation allowed) --------------
__device__ bf16  g_PQb  [NP*128];      // [16384,128] bf16; cols 0-63 P, 64-127 Q
__device__ float g_fw   [NP*LV];
__device__ int   g_idx  [NP*KNB];
__device__ bf16  g_Bt1B [H1*192];      // Wf1^T bf16 [256][192]
__device__ bf16  g_Bt2B [H2*H1];       // Wf2^T bf16 [128][256]

__device__ __forceinline__ float leaky(float v){ return v > 0.f ? v : 0.2f*v; }

__device__ __forceinline__ uint32_t smem_u32(const void* p) {
    uint32_t a;
    asm("{ .reg .u64 t; cvta.to.shared.u64 t, %1; cvt.u32.u64 %0, t; }" : "=r"(a) : "l"(p));
    return a;
}

#define CP_ASYNC16(d, s) do { \
    size_t _gs = __cvta_generic_to_global(s); \
    asm volatile("cp.async.cg.shared.global [%0], [%1], 16;" :: "r"(d), "l"(_gs) : "memory"); \
} while (0)
#define CP_COMMIT()  asm volatile("cp.async.commit_group;" ::: "memory")
#define CP_WAIT(n)   asm volatile("cp.async.wait_group %0;" :: "n"(n) : "memory")

__device__ __forceinline__ void mma_bf16(float* c, const uint32_t* a, const uint32_t* b) {
    asm volatile(
        "mma.sync.aligned.m16n8k16.row.col.f32.bf16.bf16.f32 "
        "{%0,%1,%2,%3}, {%4,%5,%6,%7}, {%8,%9}, {%0,%1,%2,%3};"
        : "+f"(c[0]), "+f"(c[1]), "+f"(c[2]), "+f"(c[3])
        : "r"(a[0]), "r"(a[1]), "r"(a[2]), "r"(a[3]), "r"(b[0]), "r"(b[1]));
}

__device__ __forceinline__ float bf2f(uint32_t u, int hi) {
    __nv_bfloat162 v = *(__nv_bfloat162*)&u;
    return hi ? __bfloat162float(v.y) : __bfloat162float(v.x);
}

// ================ kernel 1 (front): KNN || feature+PQ GEMM || weight prep ======
// blocks [0,128):   KNN, 4 queries/warp (8-lane sorted sublists), 128 q/block
// blocks [128,192): feature transform + suppressor + PQ mma, 256 points/block
// blocks [192,240): Wf1/Wf2 transposes to bf16
#define BSRQ 36
#define ASRQ 36
#define FRONT_SMEM ((128*BSRQ + 4*64*ASRQ)*4)   // 55296 bytes (>= KNN's 32KB)

__global__ void __launch_bounds__(1024)
k_front(const float* __restrict__ x,
        const float* __restrict__ W1, const float* __restrict__ b1,
        const float* __restrict__ g1, const float* __restrict__ be1,
        const float* __restrict__ Ws1, const float* __restrict__ bs1,
        const float* __restrict__ Ws2, const float* __restrict__ bs2,
        const float* __restrict__ W2, const float* __restrict__ Wf1,
        const float* __restrict__ Wf2)
{
    extern __shared__ char fsm[];
    const int bx = blockIdx.x;
    const int tid = threadIdx.x;

    if (bx >= 192) {                 // ---- weight prep ----
        int i = (bx - 192)*1024 + tid;
        if (i < H1*192) { int n = i/192, k = i%192; g_Bt1B[i] = __float2bfloat16_rn(Wf1[k*H1 + n]); }
        if (i < H2*H1)  { int n = i>>8,  k = i&255; g_Bt2B[i] = __float2bfloat16_rn(Wf2[k*H2 + n]); }
        return;
    }

    if (bx >= 128) {                 // ---- feature + suppressor + PQ GEMM ----
        uint32_t* sB = (uint32_t*)fsm;
        uint32_t* sAall = (uint32_t*)fsm + 128*BSRQ;

        const int tile = tid >> 8;
        const int t256 = tid & 255;
        const int m0 = (bx - 128)*256 + tile*64;

        bf16* sBh = (bf16*)sB;
        for (int i = tid; i < 128*64; i += 1024) {
            int k = i >> 7, n = i & 127;
            float w = (n < 64) ? W2[k*DD + n] : W2[(64 + k)*DD + (n - 64)];
            sBh[n*(2*BSRQ) + k] = __float2bfloat16_rn(w);
        }

        const int pt = t256 >> 2, q = t256 & 3, d0 = q*16;
        const int p = m0 + pt;
        float x0 = x[p*3+0], x1 = x[p*3+1], x2 = x[p*3+2];
        float s0 = 0.f, s1 = 0.f, s2 = 0.f;
        bf16* sAh = (bf16*)(sAall + tile*64*ASRQ);
        #pragma unroll
        for (int j = 0; j < 16; j++) {
            int d = d0 + j;
            float f = x0*W1[d] + x1*W1[DD+d] + x2*W1[2*DD+d] + b1[d];
            f = leaky(f*g1[d] + be1[d]);
            sAh[pt*(2*ASRQ) + d] = __float2bfloat16_rn(f);
            float hh = x0*Ws1[d] + x1*Ws1[DD+d] + x2*Ws1[2*DD+d] + bs1[d];
            hh = hh > 0.f ? hh : 0.f;
            s0 += hh*Ws2[d*LV+0]; s1 += hh*Ws2[d*LV+1]; s2 += hh*Ws2[d*LV+2];
        }
        s0 += __shfl_xor_sync(0xFFFFFFFF, s0, 1); s0 += __shfl_xor_sync(0xFFFFFFFF, s0, 2);
        s1 += __shfl_xor_sync(0xFFFFFFFF, s1, 1); s1 += __shfl_xor_sync(0xFFFFFFFF, s1, 2);
        s2 += __shfl_xor_sync(0xFFFFFFFF, s2, 1); s2 += __shfl_xor_sync(0xFFFFFFFF, s2, 2);
        if (q == 0) {
            g_fw[p*LV+0] = 1.f/(1.f + expf(-s0));
            g_fw[p*LV+1] = 1.f/(1.f + expf(-s1));
            g_fw[p*LV+2] = 1.f/(1.f + expf(-s2));
        }
        __syncthreads();

        const int w8 = (tid >> 5) & 7;
        const int lane = tid & 31, gid = lane >> 2, tig = lane & 3;
        const int wm = (w8 & 1)*32, wn = (w8 >> 1)*32;
        const uint32_t* sA = sAall + tile*64*ASRQ;
        float acc[2][4][4] = {};
        #pragma unroll
        for (int ks = 0; ks < 4; ks++) {
            const int ko = ks*8;
            uint32_t af[2][4], bfr[4][2];
            #pragma unroll
            for (int mf = 0; mf < 2; mf++) {
                const uint32_t* ap = sA + (wm + mf*16 + gid)*ASRQ + ko + tig;
                af[mf][0] = ap[0];
                af[mf][1] = ap[8*ASRQ];
                af[mf][2] = ap[4];
                af[mf][3] = ap[8*ASRQ + 4];
            }
            #pragma unroll
            for (int nf = 0; nf < 4; nf++) {
                const uint32_t* bp = sB + (wn + nf*8 + gid)*BSRQ + ko + tig;
                bfr[nf][0] = bp[0];
                bfr[nf][1] = bp[4];
            }
            #pragma unroll
            for (int mf = 0; mf < 2; mf++)
                #pragma unroll
                for (int nf = 0; nf < 4; nf++)
                    mma_bf16(acc[mf][nf], af[mf], bfr[nf]);
        }
        #pragma unroll
        for (int mf = 0; mf < 2; mf++) {
            const int row = m0 + wm + mf*16 + gid;
            #pragma unroll
            for (int nf = 0; nf < 4; nf++) {
                const int col = wn + nf*8 + tig*2;
                __nv_bfloat162 lo, hi;
                lo.x = __float2bfloat16_rn(acc[mf][nf][0]); lo.y = __float2bfloat16_rn(acc[mf][nf][1]);
                hi.x = __float2bfloat16_rn(acc[mf][nf][2]); hi.y = __float2bfloat16_rn(acc[mf][nf][3]);
                *(__nv_bfloat162*)(g_PQb + (size_t)row*128 + col)     = lo;
                *(__nv_bfloat162*)(g_PQb + (size_t)(row+8)*128 + col) = hi;
            }
        }
        return;
    }

    // ---- KNN: 4 queries/warp, 8-lane sorted sublist per query ----
    {
        float4* sc = (float4*)fsm;
        const int b  = bx >> 4;            // 16 blocks per batch
        const int qb = (bx & 15) * 128;
        const int w = tid >> 5, lane = tid & 31;

        for (int j = tid; j < NN; j += 1024) {
            float a = x[(b*NN + j)*3 + 0];
            float c = x[(b*NN + j)*3 + 1];
            float e = x[(b*NN + j)*3 + 2];
            sc[j] = make_float4(a, c, e, 0.5f*(a*a + c*c + e*e));
        }
        __syncthreads();

        const int q0 = qb + w*4;
        float4 A0 = sc[q0+0], A1 = sc[q0+1], A2 = sc[q0+2], A3 = sc[q0+3];
        A0.x = -A0.x; A0.y = -A0.y; A0.z = -A0.z;
        A1.x = -A1.x; A1.y = -A1.y; A1.z = -A1.z;
        A2.x = -A2.x; A2.y = -A2.y; A2.z = -A2.z;
        A3.x = -A3.x; A3.y = -A3.y; A3.z = -A3.z;

        const int grp = lane >> 3, gl = lane & 7;
        float slotD = FLT_MAX; int slotI = 0;
        float tau[4] = {FLT_MAX, FLT_MAX, FLT_MAX, FLT_MAX};

        for (int ch = 0; ch < NN/32; ch++) {
            float4 cd = sc[ch*32 + lane];
            float d[4];
            d[0] = fmaf(A0.x, cd.x, fmaf(A0.y, cd.y, fmaf(A0.z, cd.z, A0.w + cd.w)));
            d[1] = fmaf(A1.x, cd.x, fmaf(A1.y, cd.y, fmaf(A1.z, cd.z, A1.w + cd.w)));
            d[2] = fmaf(A2.x, cd.x, fmaf(A2.y, cd.y, fmaf(A2.z, cd.z, A2.w + cd.w)));
            d[3] = fmaf(A3.x, cd.x, fmaf(A3.y, cd.y, fmaf(A3.z, cd.z, A3.w + cd.w)));
            unsigned m[4];
            m[0] = __ballot_sync(0xFFFFFFFFu, d[0] < tau[0]);
            m[1] = __ballot_sync(0xFFFFFFFFu, d[1] < tau[1]);
            m[2] = __ballot_sync(0xFFFFFFFFu, d[2] < tau[2]);
            m[3] = __ballot_sync(0xFFFFFFFFu, d[3] < tau[3]);
            #pragma unroll
            for (int q = 0; q < 4; q++) {
                while (m[q]) {
                    int src = __ffs(m[q]) - 1; m[q] &= m[q] - 1;
                    float cvf = __shfl_sync(0xFFFFFFFFu, d[q], src);
                    if (cvf < tau[q]) {
                        int cidx = ch*32 + src;
                        float prevD = __shfl_up_sync(0xFFFFFFFFu, slotD, 1);
                        int   prevI = __shfl_up_sync(0xFFFFFFFFu, slotI, 1);
                        if (grp == q) {
                            if (gl == 0) { prevD = cvf; prevI = cidx; }
                            if (slotD > cvf) {
                                bool pb = prevD > cvf;
                                slotD = pb ? prevD : cvf;
                                slotI = pb ? prevI : cidx;
                            }
                        }
                        tau[q] = __shfl_sync(0xFFFFFFFFu, slotD, q*8 + 7);
                    }
                }
            }
        }
        g_idx[(b*NN + q0 + grp)*KNB + gl] = slotI;
    }
}

// ================= kernel 2 (tail): gather + GEMM1 + GEMM2 + out ==============
// One CTA = 64 points, full pipeline. smem (u32 offsets):
//   A1 (multi 64x192):   [0, 6400)         stride 100
//   B1 (Wf1^T 256x192):  [6400, 32000)     stride 100; later overlaid by B2
//   G1 (64x256 bf16):    [32000, 40448)    stride 132
//   B2 (Wf2^T 128x256):  [6400, 23296)     stride 132
#define T_ASR 100
#define T_G1SR 132
#define T_A1 0
#define T_B1 6400
#define T_G1 32000
#define T_SMEM (40448*4)   // 161792 bytes

__global__ void __launch_bounds__(256)
k_tail(const float* __restrict__ b2, const float* __restrict__ g2,
       const float* __restrict__ be2,
       const float* __restrict__ bf1, const float* __restrict__ gf1,
       const float* __restrict__ bef1,
       const float* __restrict__ bf2, const float* __restrict__ gf2,
       const float* __restrict__ bef2,
       float* __restrict__ out, const float* __restrict__ x,
       const float* __restrict__ Wf3, const float* __restrict__ bf3)
{
    extern __shared__ uint32_t sm32[];
    __shared__ float sAcc[64][3];

    const int t = threadIdx.x, lane = t & 31, wid = t >> 5;
    const int gid = lane >> 2, tig = lane & 3;
    const int m0 = blockIdx.x * 64;
    const uint32_t sbase = smem_u32(sm32);

    // stage B1: row = t (256 rows x 384B = 24 segs each)
    {
        uint32_t dst = sbase + (uint32_t)(T_B1*4 + t*400);
        const bf16* src = g_Bt1B + (size_t)t*192;
        #pragma unroll
        for (int s = 0; s < 24; s++) CP_ASYNC16(dst + s*16, src + s*8);
        CP_COMMIT();
    }

    // ---- phase 0: gather/max/multi into A1 smem ----
    {
        const int pt = t >> 2, q = t & 3, d0 = q*16;
        const int p = m0 + pt, b = p >> 11;

        float pv[16], gg[16], cc[16], m[16];
        uint4 pv0 = *(const uint4*)(g_PQb + (size_t)p*128 + d0);
        uint4 pv1 = *(const uint4*)(g_PQb + (size_t)p*128 + d0 + 8);
        #pragma unroll
        for (int j = 0; j < 8; j++) {
            pv[j]   = bf2f(((const uint32_t*)&pv0)[j>>1], j&1);
            pv[8+j] = bf2f(((const uint32_t*)&pv1)[j>>1], j&1);
        }
        #pragma unroll
        for (int j = 0; j < 16; j++) {
            gg[j] = g2[d0+j];
            cc[j] = b2[d0+j]*gg[j] + be2[d0+j];
            m[j] = -FLT_MAX;
        }
        int idx[KNB];
        *(int4*)&idx[0] = *(const int4*)(g_idx + p*KNB);
        *(int4*)&idx[4] = *(const int4*)(g_idx + p*KNB + 4);
        #pragma unroll
        for (int k = 0; k < KNB; k++) {
            const bf16* qrow = g_PQb + (size_t)(b*NN + idx[k])*128 + 64 + d0;
            uint4 qv0 = *(const uint4*)(qrow);
            uint4 qv1 = *(const uint4*)(qrow + 8);
            #pragma unroll
            for (int j = 0; j < 8; j++) {
                float qa = bf2f(((const uint32_t*)&qv0)[j>>1], j&1);
                float qb = bf2f(((const uint32_t*)&qv1)[j>>1], j&1);
                m[j]   = fmaxf(m[j],   leaky((pv[j]   + qa)*gg[j]   + cc[j]));
                m[8+j] = fmaxf(m[8+j], leaky((pv[8+j] + qb)*gg[8+j] + cc[8+j]));
            }
        }
        float f0 = g_fw[p*LV+0], f1 = g_fw[p*LV+1], f2 = g_fw[p*LV+2];
        bf16* sAh = (bf16*)(sm32 + T_A1);
        #pragma unroll
        for (int j = 0; j < 16; j++) {
            int d = d0 + j;
            sAh[pt*(2*T_ASR) + d]       = __float2bfloat16_rn(m[j]*f0);
            sAh[pt*(2*T_ASR) + 64 + d]  = __float2bfloat16_rn(m[j]*f1);
            sAh[pt*(2*T_ASR) + 128 + d] = __float2bfloat16_rn(m[j]*f2);
        }
    }
    if (t < 192) sAcc[t/3][t%3] = 0.f;
    CP_WAIT(0);
    __syncthreads();

    // ---- phase 1: GEMM1 64x256x192, epilogue into G1 smem ----
    const int wm = (wid & 1)*32;
    {
        const int wn1 = (wid >> 1)*64;
        float acc1[2][8][4] = {};
        #pragma unroll
        for (int ks = 0; ks < 12; ks++) {
            const int ko = ks*8;
            uint32_t af[2][4], bfr[8][2];
            #pragma unroll
            for (int mf = 0; mf < 2; mf++) {
                const uint32_t* ap = sm32 + T_A1 + (wm + mf*16 + gid)*T_ASR + ko + tig;
                af[mf][0] = ap[0];
                af[mf][1] = ap[8*T_ASR];
                af[mf][2] = ap[4];
                af[mf][3] = ap[8*T_ASR + 4];
            }
            #pragma unroll
            for (int nf = 0; nf < 8; nf++) {
                const uint32_t* bp = sm32 + T_B1 + (wn1 + nf*8 + gid)*T_ASR + ko + tig;
                bfr[nf][0] = bp[0];
                bfr[nf][1] = bp[4];
            }
            #pragma unroll
            for (int mf = 0; mf < 2; mf++)
                #pragma unroll
                for (int nf = 0; nf < 8; nf++)
                    mma_bf16(acc1[mf][nf], af[mf], bfr[nf]);
        }
        #pragma unroll
        for (int mf = 0; mf < 2; mf++) {
            const int rl = wm + mf*16 + gid;
            #pragma unroll
            for (int nf = 0; nf < 8; nf++) {
                const int col = wn1 + nf*8 + tig*2;
                float e0 = __ldg(bf1+col),  e1 = __ldg(bf1+col+1);
                float q0 = __ldg(gf1+col),  q1 = __ldg(gf1+col+1);
                float h0 = __ldg(bef1+col), h1 = __ldg(bef1+col+1);
                float v0 = leaky((acc1[mf][nf][0] + e0)*q0 + h0);
                float v1 = leaky((acc1[mf][nf][1] + e1)*q1 + h1);
                float v2 = leaky((acc1[mf][nf][2] + e0)*q0 + h0);
                float v3 = leaky((acc1[mf][nf][3] + e1)*q1 + h1);
                __nv_bfloat162 lo, hi;
                lo.x = __float2bfloat16_rn(v0); lo.y = __float2bfloat16_rn(v1);
                hi.x = __float2bfloat16_rn(v2); hi.y = __float2bfloat16_rn(v3);
                sm32[T_G1 + rl*T_G1SR + (col>>1)]     = *(uint32_t*)&lo;
                sm32[T_G1 + (rl+8)*T_G1SR + (col>>1)] = *(uint32_t*)&hi;
            }
        }
    }
    __syncthreads();

    // ---- stage B2 over B1 region ----
    #pragma unroll
    for (int it = 0; it < 16; it++) {
        int i = it*256 + t;
        int row = i >> 5, seg = i & 31;
        CP_ASYNC16(sbase + (uint32_t)(T_B1*4 + row*528 + seg*16),
                   g_Bt2B + (size_t)row*256 + seg*8);
    }
    CP_COMMIT();
    CP_WAIT(0);
    __syncthreads();

    // ---- phase 2: GEMM2 64x128x256 + projection + residual ----
    {
        const int wn2 = (wid >> 1)*32;
        float acc2[2][4][4] = {};
        #pragma unroll
        for (int ks = 0; ks < 16; ks++) {
            const int ko = ks*8;
            uint32_t af[2][4], bfr[4][2];
            #pragma unroll
            for (int mf = 0; mf < 2; mf++) {
                const uint32_t* ap = sm32 + T_G1 + (wm + mf*16 + gid)*T_G1SR + ko + tig;
                af[mf][0] = ap[0];
                af[mf][1] = ap[8*T_G1SR];
                af[mf][2] = ap[4];
                af[mf][3] = ap[8*T_G1SR + 4];
            }
            #pragma unroll
            for (int nf = 0; nf < 4; nf++) {
                const uint32_t* bp = sm32 + T_B1 + (wn2 + nf*8 + gid)*T_G1SR + ko + tig;
                bfr[nf][0] = bp[0];
                bfr[nf][1] = bp[4];
            }
            #pragma unroll
            for (int mf = 0; mf < 2; mf++)
                #pragma unroll
                for (int nf = 0; nf < 4; nf++)
                    mma_bf16(acc2[mf][nf], af[mf], bfr[nf]);
        }

        #pragma unroll
        for (int mf = 0; mf < 2; mf++) {
            float sLo[3] = {0.f,0.f,0.f}, sHi[3] = {0.f,0.f,0.f};
            #pragma unroll
            for (int nf = 0; nf < 4; nf++) {
                const int col = wn2 + nf*8 + tig*2;
                float e0 = __ldg(bf2+col),  e1 = __ldg(bf2+col+1);
                float q0 = __ldg(gf2+col),  q1 = __ldg(gf2+col+1);
                float h0 = __ldg(bef2+col), h1 = __ldg(bef2+col+1);
                float v0 = leaky((acc2[mf][nf][0] + e0)*q0 + h0);
                float v1 = leaky((acc2[mf][nf][1] + e1)*q1 + h1);
                float v2 = leaky((acc2[mf][nf][2] + e0)*q0 + h0);
                float v3 = leaky((acc2[mf][nf][3] + e1)*q1 + h1);
                #pragma unroll
                for (int j = 0; j < 3; j++) {
                    float w0 = __ldg(Wf3 + col*3 + j);
                    float w1 = __ldg(Wf3 + (col+1)*3 + j);
                    sLo[j] += v0*w0 + v1*w1;
                    sHi[j] += v2*w0 + v3*w1;
                }
            }
            #pragma unroll
            for (int j = 0; j < 3; j++) {
                sLo[j] += __shfl_xor_sync(0xFFFFFFFF, sLo[j], 1);
                sLo[j] += __shfl_xor_sync(0xFFFFFFFF, sLo[j], 2);
                sHi[j] += __shfl_xor_sync(0xFFFFFFFF, sHi[j], 1);
                sHi[j] += __shfl_xor_sync(0xFFFFFFFF, sHi[j], 2);
            }
            if (tig == 0) {
                int rl = wm + mf*16 + gid;
                #pragma unroll
                for (int j = 0; j < 3; j++) {
                    atomicAdd(&sAcc[rl][j],     sLo[j]);
                    atomicAdd(&sAcc[rl + 8][j], sHi[j]);
                }
            }
        }
    }

    __syncthreads();
    if (t < 64) {
        int p = m0 + t;
        #pragma unroll
        for (int j = 0; j < 3; j++)
            out[p*3+j] = x[p*3+j] + 0.1f*(sAcc[t][j] + __ldg(bf3+j));
    }
}

// ---------------- launch -------------------------------------------------------
extern "C" void kernel_launch(void* const* d_in, const int* in_sizes, int n_in,
                              void* d_out, int out_size)
{
    const float* x   = (const float*)d_in[0];
    const float* W1  = (const float*)d_in[1];
    const float* b1  = (const float*)d_in[2];
    const float* g1  = (const float*)d_in[3];
    const float* be1 = (const float*)d_in[4];
    const float* W2  = (const float*)d_in[5];
    const float* b2  = (const float*)d_in[6];
    const float* g2  = (const float*)d_in[7];
    const float* be2 = (const float*)d_in[8];
    const float* Ws1 = (const float*)d_in[9];
    const float* bs1 = (const float*)d_in[10];
    const float* Ws2 = (const float*)d_in[11];
    const float* bs2 = (const float*)d_in[12];
    const float* Wf1 = (const float*)d_in[13];
    const float* bf1 = (const float*)d_in[14];
    const float* gf1 = (const float*)d_in[15];
    const float* bef1= (const float*)d_in[16];
    const float* Wf2 = (const float*)d_in[17];
    const float* bf2 = (const float*)d_in[18];
    const float* gf2 = (const float*)d_in[19];
    const float* bef2= (const float*)d_in[20];
    const float* Wf3 = (const float*)d_in[21];
    const float* bf3 = (const float*)d_in[22];
    float* out = (float*)d_out;

    cudaFuncSetAttribute(k_front, cudaFuncAttributeMaxDynamicSharedMemorySize, FRONT_SMEM);
    cudaFuncSetAttribute(k_tail,  cudaFuncAttributeMaxDynamicSharedMemorySize, T_SMEM);

    // 1. KNN (128 blk) || feature+PQ (64 blk) || weight prep (48 blk)
    k_front<<<128 + 64 + 48, 1024, FRONT_SMEM>>>(
        x, W1, b1, g1, be1, Ws1, bs1, Ws2, bs2, W2, Wf1, Wf2);

    // 2. gather + fusion1 + fusion2 + projection + residual, fully fused
    k_tail<<<NP/64, 256, T_SMEM>>>(b2, g2, be2, bf1, gf1, bef1,
                                   bf2, gf2, bef2, out, x, Wf3, bf3);
}

// round 12
// speedup vs baseline: 3.7051x; 1.0738x over previous
#include <cuda_runtime.h>
#include <cuda_bf16.h>
#include <float.h>
#include <math.h>
#include <stdint.h>

// Problem constants
#define BB 8
#define NN 2048
#define NP (BB*NN)        // 16384 points
#define DD 64
#define KNB 8
#define LV 3
#define H1 256
#define H2 128

typedef __nv_bfloat16 bf16;

// ---------------- scratch (device globals; no allocation allowed) --------------
__device__ bf16  g_PQb  [NP*128];      // [16384,128] bf16; cols 0-63 P, 64-127 Q
__device__ float g_fw   [NP*LV];
__device__ int   g_idx  [NP*KNB];
__device__ bf16  g_Bt1B [H1*192];      // Wf1^T bf16 [256][192]
__device__ bf16  g_Bt2B [H2*H1];       // Wf2^T bf16 [128][256]

__device__ __forceinline__ float leaky(float v){ return v > 0.f ? v : 0.2f*v; }

__device__ __forceinline__ uint32_t smem_u32(const void* p) {
    uint32_t a;
    asm("{ .reg .u64 t; cvta.to.shared.u64 t, %1; cvt.u32.u64 %0, t; }" : "=r"(a) : "l"(p));
    return a;
}

#define CP_ASYNC16(d, s) do { \
    size_t _gs = __cvta_generic_to_global(s); \
    asm volatile("cp.async.cg.shared.global [%0], [%1], 16;" :: "r"(d), "l"(_gs) : "memory"); \
} while (0)
#define CP_COMMIT()  asm volatile("cp.async.commit_group;" ::: "memory")
#define CP_WAIT(n)   asm volatile("cp.async.wait_group %0;" :: "n"(n) : "memory")

__device__ __forceinline__ void mma_bf16(float* c, const uint32_t* a, const uint32_t* b) {
    asm volatile(
        "mma.sync.aligned.m16n8k16.row.col.f32.bf16.bf16.f32 "
        "{%0,%1,%2,%3}, {%4,%5,%6,%7}, {%8,%9}, {%0,%1,%2,%3};"
        : "+f"(c[0]), "+f"(c[1]), "+f"(c[2]), "+f"(c[3])
        : "r"(a[0]), "r"(a[1]), "r"(a[2]), "r"(a[3]), "r"(b[0]), "r"(b[1]));
}

__device__ __forceinline__ float bf2f(uint32_t u, int hi) {
    __nv_bfloat162 v = *(__nv_bfloat162*)&u;
    return hi ? __bfloat162float(v.y) : __bfloat162float(v.x);
}

// ================ kernel 1 (front): KNN || feature+PQ GEMM || weight prep ======
// 512-thread blocks, 2 resident per SM.
// blocks [0,256):   KNN, 64 queries/block (4/warp x 16 warps)
// blocks [256,384): feature+suppressor+PQ mma, 128 points/block (2 tiles)
// blocks [384,408): Wf1/Wf2 transposes to bf16
#define BSRQ 36
#define ASRQ 36
#define FRONT_SMEM ((128*BSRQ + 2*64*ASRQ)*4)   // 36864 bytes (>= KNN's 32KB)

__global__ void __launch_bounds__(512)
k_front(const float* __restrict__ x,
        const float* __restrict__ W1, const float* __restrict__ b1,
        const float* __restrict__ g1, const float* __restrict__ be1,
        const float* __restrict__ Ws1, const float* __restrict__ bs1,
        const float* __restrict__ Ws2, const float* __restrict__ bs2,
        const float* __restrict__ W2, const float* __restrict__ Wf1,
        const float* __restrict__ Wf2)
{
    extern __shared__ char fsm[];
    const int bx = blockIdx.x;
    const int tid = threadIdx.x;

    if (bx >= 384) {                 // ---- weight prep ----
        int base = (bx - 384)*2048;
        for (int i = base + tid; i < base + 2048; i += 512) {
            if (i < H1*192) { int n = i/192, k = i%192; g_Bt1B[i] = __float2bfloat16_rn(Wf1[k*H1 + n]); }
            if (i < H2*H1)  { int n = i>>8,  k = i&255; g_Bt2B[i] = __float2bfloat16_rn(Wf2[k*H2 + n]); }
        }
        return;
    }

    if (bx >= 256) {                 // ---- feature + suppressor + PQ GEMM ----
        uint32_t* sB = (uint32_t*)fsm;                 // Btpq [128][64bf16]
        uint32_t* sAall = (uint32_t*)fsm + 128*BSRQ;   // 2 tiles x [64][64]

        const int tile = tid >> 8;        // 0..1
        const int t256 = tid & 255;
        const int m0 = (bx - 256)*128 + tile*64;

        bf16* sBh = (bf16*)sB;
        for (int i = tid; i < 128*64; i += 512) {
            int k = i >> 7, n = i & 127;
            float w = (n < 64) ? W2[k*DD + n] : W2[(64 + k)*DD + (n - 64)];
            sBh[n*(2*BSRQ) + k] = __float2bfloat16_rn(w);
        }

        const int pt = t256 >> 2, q = t256 & 3, d0 = q*16;
        const int p = m0 + pt;
        float x0 = x[p*3+0], x1 = x[p*3+1], x2 = x[p*3+2];
        float s0 = 0.f, s1 = 0.f, s2 = 0.f;
        bf16* sAh = (bf16*)(sAall + tile*64*ASRQ);
        #pragma unroll
        for (int j = 0; j < 16; j++) {
            int d = d0 + j;
            float f = x0*W1[d] + x1*W1[DD+d] + x2*W1[2*DD+d] + b1[d];
            f = leaky(f*g1[d] + be1[d]);
            sAh[pt*(2*ASRQ) + d] = __float2bfloat16_rn(f);
            float hh = x0*Ws1[d] + x1*Ws1[DD+d] + x2*Ws1[2*DD+d] + bs1[d];
            hh = hh > 0.f ? hh : 0.f;
            s0 += hh*Ws2[d*LV+0]; s1 += hh*Ws2[d*LV+1]; s2 += hh*Ws2[d*LV+2];
        }
        s0 += __shfl_xor_sync(0xFFFFFFFF, s0, 1); s0 += __shfl_xor_sync(0xFFFFFFFF, s0, 2);
        s1 += __shfl_xor_sync(0xFFFFFFFF, s1, 1); s1 += __shfl_xor_sync(0xFFFFFFFF, s1, 2);
        s2 += __shfl_xor_sync(0xFFFFFFFF, s2, 1); s2 += __shfl_xor_sync(0xFFFFFFFF, s2, 2);
        if (q == 0) {
            g_fw[p*LV+0] = 1.f/(1.f + expf(-s0));
            g_fw[p*LV+1] = 1.f/(1.f + expf(-s1));
            g_fw[p*LV+2] = 1.f/(1.f + expf(-s2));
        }
        __syncthreads();

        const int w8 = (tid >> 5) & 7;
        const int lane = tid & 31, gid = lane >> 2, tig = lane & 3;
        const int wm = (w8 & 1)*32, wn = (w8 >> 1)*32;
        const uint32_t* sA = sAall + tile*64*ASRQ;
        float acc[2][4][4] = {};
        #pragma unroll
        for (int ks = 0; ks < 4; ks++) {
            const int ko = ks*8;
            uint32_t af[2][4], bfr[4][2];
            #pragma unroll
            for (int mf = 0; mf < 2; mf++) {
                const uint32_t* ap = sA + (wm + mf*16 + gid)*ASRQ + ko + tig;
                af[mf][0] = ap[0];
                af[mf][1] = ap[8*ASRQ];
                af[mf][2] = ap[4];
                af[mf][3] = ap[8*ASRQ + 4];
            }
            #pragma unroll
            for (int nf = 0; nf < 4; nf++) {
                const uint32_t* bp = sB + (wn + nf*8 + gid)*BSRQ + ko + tig;
                bfr[nf][0] = bp[0];
                bfr[nf][1] = bp[4];
            }
            #pragma unroll
            for (int mf = 0; mf < 2; mf++)
                #pragma unroll
                for (int nf = 0; nf < 4; nf++)
                    mma_bf16(acc[mf][nf], af[mf], bfr[nf]);
        }
        #pragma unroll
        for (int mf = 0; mf < 2; mf++) {
            const int row = m0 + wm + mf*16 + gid;
            #pragma unroll
            for (int nf = 0; nf < 4; nf++) {
                const int col = wn + nf*8 + tig*2;
                __nv_bfloat162 lo, hi;
                lo.x = __float2bfloat16_rn(acc[mf][nf][0]); lo.y = __float2bfloat16_rn(acc[mf][nf][1]);
                hi.x = __float2bfloat16_rn(acc[mf][nf][2]); hi.y = __float2bfloat16_rn(acc[mf][nf][3]);
                *(__nv_bfloat162*)(g_PQb + (size_t)row*128 + col)     = lo;
                *(__nv_bfloat162*)(g_PQb + (size_t)(row+8)*128 + col) = hi;
            }
        }
        return;
    }

    // ---- KNN: 4 queries/warp, 8-lane sorted sublist per query ----
    {
        float4* sc = (float4*)fsm;
        const int b  = bx >> 5;            // 32 blocks per batch
        const int qb = (bx & 31) * 64;
        const int w = tid >> 5, lane = tid & 31;

        for (int j = tid; j < NN; j += 512) {
            float a = x[(b*NN + j)*3 + 0];
            float c = x[(b*NN + j)*3 + 1];
            float e = x[(b*NN + j)*3 + 2];
            sc[j] = make_float4(a, c, e, 0.5f*(a*a + c*c + e*e));
        }
        __syncthreads();

        const int q0 = qb + w*4;
        float4 A0 = sc[q0+0], A1 = sc[q0+1], A2 = sc[q0+2], A3 = sc[q0+3];
        A0.x = -A0.x; A0.y = -A0.y; A0.z = -A0.z;
        A1.x = -A1.x; A1.y = -A1.y; A1.z = -A1.z;
        A2.x = -A2.x; A2.y = -A2.y; A2.z = -A2.z;
        A3.x = -A3.x; A3.y = -A3.y; A3.z = -A3.z;

        const int grp = lane >> 3, gl = lane & 7;
        float slotD = FLT_MAX; int slotI = 0;
        float tau[4] = {FLT_MAX, FLT_MAX, FLT_MAX, FLT_MAX};

        for (int ch = 0; ch < NN/32; ch++) {
            float4 cd = sc[ch*32 + lane];
            float d[4];
            d[0] = fmaf(A0.x, cd.x, fmaf(A0.y, cd.y, fmaf(A0.z, cd.z, A0.w + cd.w)));
            d[1] = fmaf(A1.x, cd.x, fmaf(A1.y, cd.y, fmaf(A1.z, cd.z, A1.w + cd.w)));
            d[2] = fmaf(A2.x, cd.x, fmaf(A2.y, cd.y, fmaf(A2.z, cd.z, A2.w + cd.w)));
            d[3] = fmaf(A3.x, cd.x, fmaf(A3.y, cd.y, fmaf(A3.z, cd.z, A3.w + cd.w)));
            unsigned m[4];
            m[0] = __ballot_sync(0xFFFFFFFFu, d[0] < tau[0]);
            m[1] = __ballot_sync(0xFFFFFFFFu, d[1] < tau[1]);
            m[2] = __ballot_sync(0xFFFFFFFFu, d[2] < tau[2]);
            m[3] = __ballot_sync(0xFFFFFFFFu, d[3] < tau[3]);
            #pragma unroll
            for (int q = 0; q < 4; q++) {
                while (m[q]) {
                    int src = __ffs(m[q]) - 1; m[q] &= m[q] - 1;
                    float cvf = __shfl_sync(0xFFFFFFFFu, d[q], src);
                    if (cvf < tau[q]) {
                        int cidx = ch*32 + src;
                        float prevD = __shfl_up_sync(0xFFFFFFFFu, slotD, 1);
                        int   prevI = __shfl_up_sync(0xFFFFFFFFu, slotI, 1);
                        if (grp == q) {
                            if (gl == 0) { prevD = cvf; prevI = cidx; }
                            if (slotD > cvf) {
                                bool pb = prevD > cvf;
                                slotD = pb ? prevD : cvf;
                                slotI = pb ? prevI : cidx;
                            }
                        }
                        tau[q] = __shfl_sync(0xFFFFFFFFu, slotD, q*8 + 7);
                    }
                }
            }
        }
        g_idx[(b*NN + q0 + grp)*KNB + gl] = slotI;
    }
}

// ================= kernel 2 (tail): gather + GEMM1 + GEMM2 + out ==============
// 512 threads, 128 points/CTA, 128 CTAs (single wave). smem (u32 offsets):
//   A1 (multi 128x192):  [0, 12800)        stride 100
//   B1 (Wf1^T 256x192):  [12800, 38400)    stride 100; later overlaid by B2
//   G1 (128x256 bf16):   [38400, 55296)    stride 132
//   B2 (Wf2^T 128x256):  [12800, 29696)    stride 132
#define T_ASR 100
#define T_G1SR 132
#define T_A1 0
#define T_B1 12800
#define T_G1 38400
#define T_SMEM (55296*4)   // 221184 bytes

__global__ void __launch_bounds__(512)
k_tail(const float* __restrict__ b2, const float* __restrict__ g2,
       const float* __restrict__ be2,
       const float* __restrict__ bf1, const float* __restrict__ gf1,
       const float* __restrict__ bef1,
       const float* __restrict__ bf2, const float* __restrict__ gf2,
       const float* __restrict__ bef2,
       float* __restrict__ out, const float* __restrict__ x,
       const float* __restrict__ Wf3, const float* __restrict__ bf3)
{
    extern __shared__ uint32_t sm32[];
    __shared__ float sAcc[128][3];

    const int t = threadIdx.x, lane = t & 31, wid = t >> 5;
    const int gid = lane >> 2, tig = lane & 3;
    const int m0 = blockIdx.x * 128;
    const uint32_t sbase = smem_u32(sm32);

    // stage B1: 256 rows x 384B = 6144 segs, 12 per thread
    #pragma unroll
    for (int it = 0; it < 12; it++) {
        int i = it*512 + t;
        int row = i/24, seg = i%24;
        CP_ASYNC16(sbase + (uint32_t)(T_B1*4 + row*400 + seg*16),
                   g_Bt1B + (size_t)row*192 + seg*8);
    }
    CP_COMMIT();

    // ---- phase 0: gather/max/multi into A1 smem (4 thr/point) ----
    {
        const int pt = t >> 2, q = t & 3, d0 = q*16;
        const int p = m0 + pt, b = p >> 11;

        float pv[16], gg[16], cc[16], m[16];
        uint4 pv0 = *(const uint4*)(g_PQb + (size_t)p*128 + d0);
        uint4 pv1 = *(const uint4*)(g_PQb + (size_t)p*128 + d0 + 8);
        #pragma unroll
        for (int j = 0; j < 8; j++) {
            pv[j]   = bf2f(((const uint32_t*)&pv0)[j>>1], j&1);
            pv[8+j] = bf2f(((const uint32_t*)&pv1)[j>>1], j&1);
        }
        #pragma unroll
        for (int j = 0; j < 16; j++) {
            gg[j] = g2[d0+j];
            cc[j] = b2[d0+j]*gg[j] + be2[d0+j];
            m[j] = -FLT_MAX;
        }
        int idx[KNB];
        *(int4*)&idx[0] = *(const int4*)(g_idx + p*KNB);
        *(int4*)&idx[4] = *(const int4*)(g_idx + p*KNB + 4);
        #pragma unroll
        for (int k = 0; k < KNB; k++) {
            const bf16* qrow = g_PQb + (size_t)(b*NN + idx[k])*128 + 64 + d0;
            uint4 qv0 = *(const uint4*)(qrow);
            uint4 qv1 = *(const uint4*)(qrow + 8);
            #pragma unroll
            for (int j = 0; j < 8; j++) {
                float qa = bf2f(((const uint32_t*)&qv0)[j>>1], j&1);
                float qb = bf2f(((const uint32_t*)&qv1)[j>>1], j&1);
                m[j]   = fmaxf(m[j],   leaky((pv[j]   + qa)*gg[j]   + cc[j]));
                m[8+j] = fmaxf(m[8+j], leaky((pv[8+j] + qb)*gg[8+j] + cc[8+j]));
            }
        }
        float f0 = g_fw[p*LV+0], f1 = g_fw[p*LV+1], f2 = g_fw[p*LV+2];
        bf16* sAh = (bf16*)(sm32 + T_A1);
        #pragma unroll
        for (int j = 0; j < 16; j++) {
            int d = d0 + j;
            sAh[pt*(2*T_ASR) + d]       = __float2bfloat16_rn(m[j]*f0);
            sAh[pt*(2*T_ASR) + 64 + d]  = __float2bfloat16_rn(m[j]*f1);
            sAh[pt*(2*T_ASR) + 128 + d] = __float2bfloat16_rn(m[j]*f2);
        }
    }
    if (t < 384) sAcc[t/3][t%3] = 0.f;
    CP_WAIT(0);
    __syncthreads();

    // ---- phase 1: GEMM1 128x256x192 (16 warps: 4M x 4N) -> G1 smem ----
    const int wm = (wid & 3)*32;
    {
        const int wn1 = (wid >> 2)*64;
        float acc1[2][8][4] = {};
        #pragma unroll
        for (int ks = 0; ks < 12; ks++) {
            const int ko = ks*8;
            uint32_t af[2][4], bfr[8][2];
            #pragma unroll
            for (int mf = 0; mf < 2; mf++) {
                const uint32_t* ap = sm32 + T_A1 + (wm + mf*16 + gid)*T_ASR + ko + tig;
                af[mf][0] = ap[0];
                af[mf][1] = ap[8*T_ASR];
                af[mf][2] = ap[4];
                af[mf][3] = ap[8*T_ASR + 4];
            }
            #pragma unroll
            for (int nf = 0; nf < 8; nf++) {
                const uint32_t* bp = sm32 + T_B1 + (wn1 + nf*8 + gid)*T_ASR + ko + tig;
                bfr[nf][0] = bp[0];
                bfr[nf][1] = bp[4];
            }
            #pragma unroll
            for (int mf = 0; mf < 2; mf++)
                #pragma unroll
                for (int nf = 0; nf < 8; nf++)
                    mma_bf16(acc1[mf][nf], af[mf], bfr[nf]);
        }
        #pragma unroll
        for (int mf = 0; mf < 2; mf++) {
            const int rl = wm + mf*16 + gid;
            #pragma unroll
            for (int nf = 0; nf < 8; nf++) {
                const int col = wn1 + nf*8 + tig*2;
                float e0 = __ldg(bf1+col),  e1 = __ldg(bf1+col+1);
                float q0 = __ldg(gf1+col),  q1 = __ldg(gf1+col+1);
                float h0 = __ldg(bef1+col), h1 = __ldg(bef1+col+1);
                float v0 = leaky((acc1[mf][nf][0] + e0)*q0 + h0);
                float v1 = leaky((acc1[mf][nf][1] + e1)*q1 + h1);
                float v2 = leaky((acc1[mf][nf][2] + e0)*q0 + h0);
                float v3 = leaky((acc1[mf][nf][3] + e1)*q1 + h1);
                __nv_bfloat162 lo, hi;
                lo.x = __float2bfloat16_rn(v0); lo.y = __float2bfloat16_rn(v1);
                hi.x = __float2bfloat16_rn(v2); hi.y = __float2bfloat16_rn(v3);
                sm32[T_G1 + rl*T_G1SR + (col>>1)]     = *(uint32_t*)&lo;
                sm32[T_G1 + (rl+8)*T_G1SR + (col>>1)] = *(uint32_t*)&hi;
            }
        }
    }
    __syncthreads();

    // ---- stage B2 over B1 region (128 rows x 512B = 4096 segs, 8/thread) ----
    #pragma unroll
    for (int it = 0; it < 8; it++) {
        int i = it*512 + t;
        int row = i >> 5, seg = i & 31;
        CP_ASYNC16(sbase + (uint32_t)(T_B1*4 + row*528 + seg*16),
                   g_Bt2B + (size_t)row*256 + seg*8);
    }
    CP_COMMIT();
    CP_WAIT(0);
    __syncthreads();

    // ---- phase 2: GEMM2 128x128x256 + projection + residual ----
    {
        const int wn2 = (wid >> 2)*32;
        float acc2[2][4][4] = {};
        #pragma unroll
        for (int ks = 0; ks < 16; ks++) {
            const int ko = ks*8;
            uint32_t af[2][4], bfr[4][2];
            #pragma unroll
            for (int mf = 0; mf < 2; mf++) {
                const uint32_t* ap = sm32 + T_G1 + (wm + mf*16 + gid)*T_G1SR + ko + tig;
                af[mf][0] = ap[0];
                af[mf][1] = ap[8*T_G1SR];
                af[mf][2] = ap[4];
                af[mf][3] = ap[8*T_G1SR + 4];
            }
            #pragma unroll
            for (int nf = 0; nf < 4; nf++) {
                const uint32_t* bp = sm32 + T_B1 + (wn2 + nf*8 + gid)*T_G1SR + ko + tig;
                bfr[nf][0] = bp[0];
                bfr[nf][1] = bp[4];
            }
            #pragma unroll
            for (int mf = 0; mf < 2; mf++)
                #pragma unroll
                for (int nf = 0; nf < 4; nf++)
                    mma_bf16(acc2[mf][nf], af[mf], bfr[nf]);
        }

        #pragma unroll
        for (int mf = 0; mf < 2; mf++) {
            float sLo[3] = {0.f,0.f,0.f}, sHi[3] = {0.f,0.f,0.f};
            #pragma unroll
            for (int nf = 0; nf < 4; nf++) {
                const int col = wn2 + nf*8 + tig*2;
                float e0 = __ldg(bf2+col),  e1 = __ldg(bf2+col+1);
                float q0 = __ldg(gf2+col),  q1 = __ldg(gf2+col+1);
                float h0 = __ldg(bef2+col), h1 = __ldg(bef2+col+1);
                float v0 = leaky((acc2[mf][nf][0] + e0)*q0 + h0);
                float v1 = leaky((acc2[mf][nf][1] + e1)*q1 + h1);
                float v2 = leaky((acc2[mf][nf][2] + e0)*q0 + h0);
                float v3 = leaky((acc2[mf][nf][3] + e1)*q1 + h1);
                #pragma unroll
                for (int j = 0; j < 3; j++) {
                    float w0 = __ldg(Wf3 + col*3 + j);
                    float w1 = __ldg(Wf3 + (col+1)*3 + j);
                    sLo[j] += v0*w0 + v1*w1;
                    sHi[j] += v2*w0 + v3*w1;
                }
            }
            #pragma unroll
            for (int j = 0; j < 3; j++) {
                sLo[j] += __shfl_xor_sync(0xFFFFFFFF, sLo[j], 1);
                sLo[j] += __shfl_xor_sync(0xFFFFFFFF, sLo[j], 2);
                sHi[j] += __shfl_xor_sync(0xFFFFFFFF, sHi[j], 1);
                sHi[j] += __shfl_xor_sync(0xFFFFFFFF, sHi[j], 2);
            }
            if (tig == 0) {
                int rl = wm + mf*16 + gid;
                #pragma unroll
                for (int j = 0; j < 3; j++) {
                    atomicAdd(&sAcc[rl][j],     sLo[j]);
                    atomicAdd(&sAcc[rl + 8][j], sHi[j]);
                }
            }
        }
    }

    __syncthreads();
    if (t < 128) {
        int p = m0 + t;
        #pragma unroll
        for (int j = 0; j < 3; j++)
            out[p*3+j] = x[p*3+j] + 0.1f*(sAcc[t][j] + __ldg(bf3+j));
    }
}

// ---------------- launch -------------------------------------------------------
extern "C" void kernel_launch(void* const* d_in, const int* in_sizes, int n_in,
                              void* d_out, int out_size)
{
    const float* x   = (const float*)d_in[0];
    const float* W1  = (const float*)d_in[1];
    const float* b1  = (const float*)d_in[2];
    const float* g1  = (const float*)d_in[3];
    const float* be1 = (const float*)d_in[4];
    const float* W2  = (const float*)d_in[5];
    const float* b2  = (const float*)d_in[6];
    const float* g2  = (const float*)d_in[7];
    const float* be2 = (const float*)d_in[8];
    const float* Ws1 = (const float*)d_in[9];
    const float* bs1 = (const float*)d_in[10];
    const float* Ws2 = (const float*)d_in[11];
    const float* bs2 = (const float*)d_in[12];
    const float* Wf1 = (const float*)d_in[13];
    const float* bf1 = (const float*)d_in[14];
    const float* gf1 = (const float*)d_in[15];
    const float* bef1= (const float*)d_in[16];
    const float* Wf2 = (const float*)d_in[17];
    const float* bf2 = (const float*)d_in[18];
    const float* gf2 = (const float*)d_in[19];
    const float* bef2= (const float*)d_in[20];
    const float* Wf3 = (const float*)d_in[21];
    const float* bf3 = (const float*)d_in[22];
    float* out = (float*)d_out;

    cudaFuncSetAttribute(k_front, cudaFuncAttributeMaxDynamicSharedMemorySize, FRONT_SMEM);
    cudaFuncSetAttribute(k_tail,  cudaFuncAttributeMaxDynamicSharedMemorySize, T_SMEM);

    // 1. KNN (256 blk) || feature+PQ (128 blk) || weight prep (24 blk)
    k_front<<<256 + 128 + 24, 512, FRONT_SMEM>>>(
        x, W1, b1, g1, be1, Ws1, bs1, Ws2, bs2, W2, Wf1, Wf2);

    // 2. gather + fusion1 + fusion2 + projection + residual, fully fused
    k_tail<<<NP/128, 512, T_SMEM>>>(b2, g2, be2, bf1, gf1, bef1,
                                    bf2, gf2, bef2, out, x, Wf3, bf3);
}

// round 13
// speedup vs baseline: 3.7286x; 1.0063x over previous
#include <cuda_runtime.h>
#include <cuda_bf16.h>
#include <float.h>
#include <math.h>
#include <stdint.h>

// Problem constants
#define BB 8
#define NN 2048
#define NP (BB*NN)        // 16384 points
#define DD 64
#define KNB 8
#define LV 3
#define H1 256
#define H2 128

typedef __nv_bfloat16 bf16;

// ---------------- scratch (device globals; no allocation allowed) --------------
__device__ bf16  g_PQb  [NP*128];      // [16384,128] bf16; cols 0-63 P, 64-127 Q
__device__ float g_fw   [NP*LV];
__device__ int   g_idx  [NP*KNB];
__device__ bf16  g_Bt1B [H1*192];      // Wf1^T bf16 [256][192]
__device__ bf16  g_Bt2B [H2*H1];       // Wf2^T bf16 [128][256]

__device__ __forceinline__ float leaky(float v){ return v > 0.f ? v : 0.2f*v; }

__device__ __forceinline__ uint32_t smem_u32(const void* p) {
    uint32_t a;
    asm("{ .reg .u64 t; cvta.to.shared.u64 t, %1; cvt.u32.u64 %0, t; }" : "=r"(a) : "l"(p));
    return a;
}

#define CP_ASYNC16(d, s) do { \
    size_t _gs = __cvta_generic_to_global(s); \
    asm volatile("cp.async.cg.shared.global [%0], [%1], 16;" :: "r"(d), "l"(_gs) : "memory"); \
} while (0)
#define CP_COMMIT()  asm volatile("cp.async.commit_group;" ::: "memory")
#define CP_WAIT(n)   asm volatile("cp.async.wait_group %0;" :: "n"(n) : "memory")

__device__ __forceinline__ void mma_bf16(float* c, const uint32_t* a, const uint32_t* b) {
    asm volatile(
        "mma.sync.aligned.m16n8k16.row.col.f32.bf16.bf16.f32 "
        "{%0,%1,%2,%3}, {%4,%5,%6,%7}, {%8,%9}, {%0,%1,%2,%3};"
        : "+f"(c[0]), "+f"(c[1]), "+f"(c[2]), "+f"(c[3])
        : "r"(a[0]), "r"(a[1]), "r"(a[2]), "r"(a[3]), "r"(b[0]), "r"(b[1]));
}

__device__ __forceinline__ float bf2f(uint32_t u, int hi) {
    __nv_bfloat162 v = *(__nv_bfloat162*)&u;
    return hi ? __bfloat162float(v.y) : __bfloat162float(v.x);
}

// ================ kernel 1 (front): KNN || feature+PQ GEMM || weight prep ======
// 512-thread blocks, forced 2 resident/SM.
// blocks [0,256):   KNN, 64 queries/block (4/warp x 16 warps)
// blocks [256,384): feature+suppressor+PQ mma, 128 points/block (2 tiles)
// blocks [384,408): Wf1/Wf2 transposes to bf16
#define BSRQ 36
#define ASRQ 36
#define FRONT_SMEM ((128*BSRQ + 2*64*ASRQ)*4)   // 36864 bytes (>= KNN's 32KB)

__global__ void __launch_bounds__(512, 2)
k_front(const float* __restrict__ x,
        const float* __restrict__ W1, const float* __restrict__ b1,
        const float* __restrict__ g1, const float* __restrict__ be1,
        const float* __restrict__ Ws1, const float* __restrict__ bs1,
        const float* __restrict__ Ws2, const float* __restrict__ bs2,
        const float* __restrict__ W2, const float* __restrict__ Wf1,
        const float* __restrict__ Wf2)
{
    extern __shared__ char fsm[];
    const int bx = blockIdx.x;
    const int tid = threadIdx.x;

    if (bx >= 384) {                 // ---- weight prep ----
        int base = (bx - 384)*2048;
        for (int i = base + tid; i < base + 2048; i += 512) {
            if (i < H1*192) { int n = i/192, k = i%192; g_Bt1B[i] = __float2bfloat16_rn(Wf1[k*H1 + n]); }
            if (i < H2*H1)  { int n = i>>8,  k = i&255; g_Bt2B[i] = __float2bfloat16_rn(Wf2[k*H2 + n]); }
        }
        return;
    }

    if (bx >= 256) {                 // ---- feature + suppressor + PQ GEMM ----
        uint32_t* sB = (uint32_t*)fsm;                 // Btpq [128][64bf16]
        uint32_t* sAall = (uint32_t*)fsm + 128*BSRQ;   // 2 tiles x [64][64]

        const int tile = tid >> 8;        // 0..1
        const int t256 = tid & 255;
        const int m0 = (bx - 256)*128 + tile*64;

        bf16* sBh = (bf16*)sB;
        for (int i = tid; i < 128*64; i += 512) {
            int k = i >> 7, n = i & 127;
            float w = (n < 64) ? W2[k*DD + n] : W2[(64 + k)*DD + (n - 64)];
            sBh[n*(2*BSRQ) + k] = __float2bfloat16_rn(w);
        }

        const int pt = t256 >> 2, q = t256 & 3, d0 = q*16;
        const int p = m0 + pt;
        float x0 = x[p*3+0], x1 = x[p*3+1], x2 = x[p*3+2];
        float s0 = 0.f, s1 = 0.f, s2 = 0.f;
        bf16* sAh = (bf16*)(sAall + tile*64*ASRQ);
        #pragma unroll
        for (int j = 0; j < 16; j++) {
            int d = d0 + j;
            float f = x0*W1[d] + x1*W1[DD+d] + x2*W1[2*DD+d] + b1[d];
            f = leaky(f*g1[d] + be1[d]);
            sAh[pt*(2*ASRQ) + d] = __float2bfloat16_rn(f);
            float hh = x0*Ws1[d] + x1*Ws1[DD+d] + x2*Ws1[2*DD+d] + bs1[d];
            hh = hh > 0.f ? hh : 0.f;
            s0 += hh*Ws2[d*LV+0]; s1 += hh*Ws2[d*LV+1]; s2 += hh*Ws2[d*LV+2];
        }
        s0 += __shfl_xor_sync(0xFFFFFFFF, s0, 1); s0 += __shfl_xor_sync(0xFFFFFFFF, s0, 2);
        s1 += __shfl_xor_sync(0xFFFFFFFF, s1, 1); s1 += __shfl_xor_sync(0xFFFFFFFF, s1, 2);
        s2 += __shfl_xor_sync(0xFFFFFFFF, s2, 1); s2 += __shfl_xor_sync(0xFFFFFFFF, s2, 2);
        if (q == 0) {
            g_fw[p*LV+0] = 1.f/(1.f + expf(-s0));
            g_fw[p*LV+1] = 1.f/(1.f + expf(-s1));
            g_fw[p*LV+2] = 1.f/(1.f + expf(-s2));
        }
        __syncthreads();

        const int w8 = (tid >> 5) & 7;
        const int lane = tid & 31, gid = lane >> 2, tig = lane & 3;
        const int wm = (w8 & 1)*32, wn = (w8 >> 1)*32;
        const uint32_t* sA = sAall + tile*64*ASRQ;
        float acc[2][4][4] = {};
        #pragma unroll
        for (int ks = 0; ks < 4; ks++) {
            const int ko = ks*8;
            uint32_t af[2][4], bfr[4][2];
            #pragma unroll
            for (int mf = 0; mf < 2; mf++) {
                const uint32_t* ap = sA + (wm + mf*16 + gid)*ASRQ + ko + tig;
                af[mf][0] = ap[0];
                af[mf][1] = ap[8*ASRQ];
                af[mf][2] = ap[4];
                af[mf][3] = ap[8*ASRQ + 4];
            }
            #pragma unroll
            for (int nf = 0; nf < 4; nf++) {
                const uint32_t* bp = sB + (wn + nf*8 + gid)*BSRQ + ko + tig;
                bfr[nf][0] = bp[0];
                bfr[nf][1] = bp[4];
            }
            #pragma unroll
            for (int mf = 0; mf < 2; mf++)
                #pragma unroll
                for (int nf = 0; nf < 4; nf++)
                    mma_bf16(acc[mf][nf], af[mf], bfr[nf]);
        }
        #pragma unroll
        for (int mf = 0; mf < 2; mf++) {
            const int row = m0 + wm + mf*16 + gid;
            #pragma unroll
            for (int nf = 0; nf < 4; nf++) {
                const int col = wn + nf*8 + tig*2;
                __nv_bfloat162 lo, hi;
                lo.x = __float2bfloat16_rn(acc[mf][nf][0]); lo.y = __float2bfloat16_rn(acc[mf][nf][1]);
                hi.x = __float2bfloat16_rn(acc[mf][nf][2]); hi.y = __float2bfloat16_rn(acc[mf][nf][3]);
                *(__nv_bfloat162*)(g_PQb + (size_t)row*128 + col)     = lo;
                *(__nv_bfloat162*)(g_PQb + (size_t)(row+8)*128 + col) = hi;
            }
        }
        return;
    }

    // ---- KNN: 4 queries/warp, 8-lane sorted sublist per query ----
    // v4: combined any-survivor ballot gate; tau refresh deferred to once per
    //     chunk per query (pops use stale tau; harmless, provably exact).
    {
        float4* sc = (float4*)fsm;
        const int b  = bx >> 5;            // 32 blocks per batch
        const int qb = (bx & 31) * 64;
        const int w = tid >> 5, lane = tid & 31;

        for (int j = tid; j < NN; j += 512) {
            float a = x[(b*NN + j)*3 + 0];
            float c = x[(b*NN + j)*3 + 1];
            float e = x[(b*NN + j)*3 + 2];
            sc[j] = make_float4(a, c, e, 0.5f*(a*a + c*c + e*e));
        }
        __syncthreads();

        const int q0 = qb + w*4;
        float4 A0 = sc[q0+0], A1 = sc[q0+1], A2 = sc[q0+2], A3 = sc[q0+3];
        A0.x = -A0.x; A0.y = -A0.y; A0.z = -A0.z;
        A1.x = -A1.x; A1.y = -A1.y; A1.z = -A1.z;
        A2.x = -A2.x; A2.y = -A2.y; A2.z = -A2.z;
        A3.x = -A3.x; A3.y = -A3.y; A3.z = -A3.z;

        const int grp = lane >> 3, gl = lane & 7;
        float slotD = FLT_MAX; int slotI = 0;
        float tau[4] = {FLT_MAX, FLT_MAX, FLT_MAX, FLT_MAX};

        for (int ch = 0; ch < NN/32; ch++) {
            float4 cd = sc[ch*32 + lane];
            float d[4];
            d[0] = fmaf(A0.x, cd.x, fmaf(A0.y, cd.y, fmaf(A0.z, cd.z, A0.w + cd.w)));
            d[1] = fmaf(A1.x, cd.x, fmaf(A1.y, cd.y, fmaf(A1.z, cd.z, A1.w + cd.w)));
            d[2] = fmaf(A2.x, cd.x, fmaf(A2.y, cd.y, fmaf(A2.z, cd.z, A2.w + cd.w)));
            d[3] = fmaf(A3.x, cd.x, fmaf(A3.y, cd.y, fmaf(A3.z, cd.z, A3.w + cd.w)));
            bool p0 = d[0] < tau[0], p1 = d[1] < tau[1];
            bool p2 = d[2] < tau[2], p3 = d[3] < tau[3];
            unsigned mAny = __ballot_sync(0xFFFFFFFFu, p0 | p1 | p2 | p3);
            if (!mAny) continue;     // warp-uniform

            unsigned m[4];
            m[0] = __ballot_sync(0xFFFFFFFFu, p0);
            m[1] = __ballot_sync(0xFFFFFFFFu, p1);
            m[2] = __ballot_sync(0xFFFFFFFFu, p2);
            m[3] = __ballot_sync(0xFFFFFFFFu, p3);
            #pragma unroll
            for (int q = 0; q < 4; q++) {
                unsigned mm = m[q];
                if (!mm) continue;   // warp-uniform
                while (mm) {
                    int src = __ffs(mm) - 1; mm &= mm - 1;
                    float cvf = __shfl_sync(0xFFFFFFFFu, d[q], src);
                    int cidx = ch*32 + src;
                    float prevD = __shfl_up_sync(0xFFFFFFFFu, slotD, 1);
                    int   prevI = __shfl_up_sync(0xFFFFFFFFu, slotI, 1);
                    if (grp == q) {
                        if (gl == 0) { prevD = cvf; prevI = cidx; }
                        if (slotD > cvf) {
                            bool pb = prevD > cvf;
                            slotD = pb ? prevD : cvf;
                            slotI = pb ? prevI : cidx;
                        }
                    }
                }
                tau[q] = __shfl_sync(0xFFFFFFFFu, slotD, q*8 + 7);
            }
        }
        g_idx[(b*NN + q0 + grp)*KNB + gl] = slotI;
    }
}

// ================= kernel 2 (tail): gather + GEMM1 + GEMM2 + out ==============
// 512 threads, 128 points/CTA, 128 CTAs (single wave). smem (u32 offsets):
//   A1 (multi 128x192):  [0, 12800)        stride 100
//   B1 (Wf1^T 256x192):  [12800, 38400)    stride 100; later overlaid by B2
//   G1 (128x256 bf16):   [38400, 55296)    stride 132
//   B2 (Wf2^T 128x256):  [12800, 29696)    stride 132
#define T_ASR 100
#define T_G1SR 132
#define T_A1 0
#define T_B1 12800
#define T_G1 38400
#define T_SMEM (55296*4)   // 221184 bytes

__global__ void __launch_bounds__(512)
k_tail(const float* __restrict__ b2, const float* __restrict__ g2,
       const float* __restrict__ be2,
       const float* __restrict__ bf1, const float* __restrict__ gf1,
       const float* __restrict__ bef1,
       const float* __restrict__ bf2, const float* __restrict__ gf2,
       const float* __restrict__ bef2,
       float* __restrict__ out, const float* __restrict__ x,
       const float* __restrict__ Wf3, const float* __restrict__ bf3)
{
    extern __shared__ uint32_t sm32[];
    __shared__ float sAcc[128][3];

    const int t = threadIdx.x, lane = t & 31, wid = t >> 5;
    const int gid = lane >> 2, tig = lane & 3;
    const int m0 = blockIdx.x * 128;
    const uint32_t sbase = smem_u32(sm32);

    // stage B1: 256 rows x 384B = 6144 segs, 12 per thread
    #pragma unroll
    for (int it = 0; it < 12; it++) {
        int i = it*512 + t;
        int row = i/24, seg = i%24;
        CP_ASYNC16(sbase + (uint32_t)(T_B1*4 + row*400 + seg*16),
                   g_Bt1B + (size_t)row*192 + seg*8);
    }
    CP_COMMIT();

    // ---- phase 0: gather/max/multi into A1 smem (4 thr/point) ----
    {
        const int pt = t >> 2, q = t & 3, d0 = q*16;
        const int p = m0 + pt, b = p >> 11;

        float pv[16], gg[16], cc[16], m[16];
        uint4 pv0 = *(const uint4*)(g_PQb + (size_t)p*128 + d0);
        uint4 pv1 = *(const uint4*)(g_PQb + (size_t)p*128 + d0 + 8);
        #pragma unroll
        for (int j = 0; j < 8; j++) {
            pv[j]   = bf2f(((const uint32_t*)&pv0)[j>>1], j&1);
            pv[8+j] = bf2f(((const uint32_t*)&pv1)[j>>1], j&1);
        }
        #pragma unroll
        for (int j = 0; j < 16; j++) {
            gg[j] = g2[d0+j];
            cc[j] = b2[d0+j]*gg[j] + be2[d0+j];
            m[j] = -FLT_MAX;
        }
        int idx[KNB];
        *(int4*)&idx[0] = *(const int4*)(g_idx + p*KNB);
        *(int4*)&idx[4] = *(const int4*)(g_idx + p*KNB + 4);
        #pragma unroll
        for (int k = 0; k < KNB; k++) {
            const bf16* qrow = g_PQb + (size_t)(b*NN + idx[k])*128 + 64 + d0;
            uint4 qv0 = *(const uint4*)(qrow);
            uint4 qv1 = *(const uint4*)(qrow + 8);
            #pragma unroll
            for (int j = 0; j < 8; j++) {
                float qa = bf2f(((const uint32_t*)&qv0)[j>>1], j&1);
                float qb = bf2f(((const uint32_t*)&qv1)[j>>1], j&1);
                m[j]   = fmaxf(m[j],   leaky((pv[j]   + qa)*gg[j]   + cc[j]));
                m[8+j] = fmaxf(m[8+j], leaky((pv[8+j] + qb)*gg[8+j] + cc[8+j]));
            }
        }
        float f0 = g_fw[p*LV+0], f1 = g_fw[p*LV+1], f2 = g_fw[p*LV+2];
        bf16* sAh = (bf16*)(sm32 + T_A1);
        #pragma unroll
        for (int j = 0; j < 16; j++) {
            int d = d0 + j;
            sAh[pt*(2*T_ASR) + d]       = __float2bfloat16_rn(m[j]*f0);
            sAh[pt*(2*T_ASR) + 64 + d]  = __float2bfloat16_rn(m[j]*f1);
            sAh[pt*(2*T_ASR) + 128 + d] = __float2bfloat16_rn(m[j]*f2);
        }
    }
    if (t < 384) sAcc[t/3][t%3] = 0.f;
    CP_WAIT(0);
    __syncthreads();

    // ---- phase 1: GEMM1 128x256x192 (16 warps: 4M x 4N) -> G1 smem ----
    const int wm = (wid & 3)*32;
    {
        const int wn1 = (wid >> 2)*64;
        float acc1[2][8][4] = {};
        #pragma unroll
        for (int ks = 0; ks < 12; ks++) {
            const int ko = ks*8;
            uint32_t af[2][4], bfr[8][2];
            #pragma unroll
            for (int mf = 0; mf < 2; mf++) {
                const uint32_t* ap = sm32 + T_A1 + (wm + mf*16 + gid)*T_ASR + ko + tig;
                af[mf][0] = ap[0];
                af[mf][1] = ap[8*T_ASR];
                af[mf][2] = ap[4];
                af[mf][3] = ap[8*T_ASR + 4];
            }
            #pragma unroll
            for (int nf = 0; nf < 8; nf++) {
                const uint32_t* bp = sm32 + T_B1 + (wn1 + nf*8 + gid)*T_ASR + ko + tig;
                bfr[nf][0] = bp[0];
                bfr[nf][1] = bp[4];
            }
            #pragma unroll
            for (int mf = 0; mf < 2; mf++)
                #pragma unroll
                for (int nf = 0; nf < 8; nf++)
                    mma_bf16(acc1[mf][nf], af[mf], bfr[nf]);
        }
        #pragma unroll
        for (int mf = 0; mf < 2; mf++) {
            const int rl = wm + mf*16 + gid;
            #pragma unroll
            for (int nf = 0; nf < 8; nf++) {
                const int col = wn1 + nf*8 + tig*2;
                float e0 = __ldg(bf1+col),  e1 = __ldg(bf1+col+1);
                float q0 = __ldg(gf1+col),  q1 = __ldg(gf1+col+1);
                float h0 = __ldg(bef1+col), h1 = __ldg(bef1+col+1);
                float v0 = leaky((acc1[mf][nf][0] + e0)*q0 + h0);
                float v1 = leaky((acc1[mf][nf][1] + e1)*q1 + h1);
                float v2 = leaky((acc1[mf][nf][2] + e0)*q0 + h0);
                float v3 = leaky((acc1[mf][nf][3] + e1)*q1 + h1);
                __nv_bfloat162 lo, hi;
                lo.x = __float2bfloat16_rn(v0); lo.y = __float2bfloat16_rn(v1);
                hi.x = __float2bfloat16_rn(v2); hi.y = __float2bfloat16_rn(v3);
                sm32[T_G1 + rl*T_G1SR + (col>>1)]     = *(uint32_t*)&lo;
                sm32[T_G1 + (rl+8)*T_G1SR + (col>>1)] = *(uint32_t*)&hi;
            }
        }
    }
    __syncthreads();

    // ---- stage B2 over B1 region (128 rows x 512B = 4096 segs, 8/thread) ----
    #pragma unroll
    for (int it = 0; it < 8; it++) {
        int i = it*512 + t;
        int row = i >> 5, seg = i & 31;
        CP_ASYNC16(sbase + (uint32_t)(T_B1*4 + row*528 + seg*16),
                   g_Bt2B + (size_t)row*256 + seg*8);
    }
    CP_COMMIT();
    CP_WAIT(0);
    __syncthreads();

    // ---- phase 2: GEMM2 128x128x256 + projection + residual ----
    {
        const int wn2 = (wid >> 2)*32;
        float acc2[2][4][4] = {};
        #pragma unroll
        for (int ks = 0; ks < 16; ks++) {
            const int ko = ks*8;
            uint32_t af[2][4], bfr[4][2];
            #pragma unroll
            for (int mf = 0; mf < 2; mf++) {
                const uint32_t* ap = sm32 + T_G1 + (wm + mf*16 + gid)*T_G1SR + ko + tig;
                af[mf][0] = ap[0];
                af[mf][1] = ap[8*T_G1SR];
                af[mf][2] = ap[4];
                af[mf][3] = ap[8*T_G1SR + 4];
            }
            #pragma unroll
            for (int nf = 0; nf < 4; nf++) {
                const uint32_t* bp = sm32 + T_B1 + (wn2 + nf*8 + gid)*T_G1SR + ko + tig;
                bfr[nf][0] = bp[0];
                bfr[nf][1] = bp[4];
            }
            #pragma unroll
            for (int mf = 0; mf < 2; mf++)
                #pragma unroll
                for (int nf = 0; nf < 4; nf++)
                    mma_bf16(acc2[mf][nf], af[mf], bfr[nf]);
        }

        #pragma unroll
        for (int mf = 0; mf < 2; mf++) {
            float sLo[3] = {0.f,0.f,0.f}, sHi[3] = {0.f,0.f,0.f};
            #pragma unroll
            for (int nf = 0; nf < 4; nf++) {
                const int col = wn2 + nf*8 + tig*2;
                float e0 = __ldg(bf2+col),  e1 = __ldg(bf2+col+1);
                float q0 = __ldg(gf2+col),  q1 = __ldg(gf2+col+1);
                float h0 = __ldg(bef2+col), h1 = __ldg(bef2+col+1);
                float v0 = leaky((acc2[mf][nf][0] + e0)*q0 + h0);
                float v1 = leaky((acc2[mf][nf][1] + e1)*q1 + h1);
                float v2 = leaky((acc2[mf][nf][2] + e0)*q0 + h0);
                float v3 = leaky((acc2[mf][nf][3] + e1)*q1 + h1);
                #pragma unroll
                for (int j = 0; j < 3; j++) {
                    float w0 = __ldg(Wf3 + col*3 + j);
                    float w1 = __ldg(Wf3 + (col+1)*3 + j);
                    sLo[j] += v0*w0 + v1*w1;
                    sHi[j] += v2*w0 + v3*w1;
                }
            }
            #pragma unroll
            for (int j = 0; j < 3; j++) {
                sLo[j] += __shfl_xor_sync(0xFFFFFFFF, sLo[j], 1);
                sLo[j] += __shfl_xor_sync(0xFFFFFFFF, sLo[j], 2);
                sHi[j] += __shfl_xor_sync(0xFFFFFFFF, sHi[j], 1);
                sHi[j] += __shfl_xor_sync(0xFFFFFFFF, sHi[j], 2);
            }
            if (tig == 0) {
                int rl = wm + mf*16 + gid;
                #pragma unroll
                for (int j = 0; j < 3; j++) {
                    atomicAdd(&sAcc[rl][j],     sLo[j]);
                    atomicAdd(&sAcc[rl + 8][j], sHi[j]);
                }
            }
        }
    }

    __syncthreads();
    if (t < 128) {
        int p = m0 + t;
        #pragma unroll
        for (int j = 0; j < 3; j++)
            out[p*3+j] = x[p*3+j] + 0.1f*(sAcc[t][j] + __ldg(bf3+j));
    }
}

// ---------------- launch -------------------------------------------------------
extern "C" void kernel_launch(void* const* d_in, const int* in_sizes, int n_in,
                              void* d_out, int out_size)
{
    const float* x   = (const float*)d_in[0];
    const float* W1  = (const float*)d_in[1];
    const float* b1  = (const float*)d_in[2];
    const float* g1  = (const float*)d_in[3];
    const float* be1 = (const float*)d_in[4];
    const float* W2  = (const float*)d_in[5];
    const float* b2  = (const float*)d_in[6];
    const float* g2  = (const float*)d_in[7];
    const float* be2 = (const float*)d_in[8];
    const float* Ws1 = (const float*)d_in[9];
    const float* bs1 = (const float*)d_in[10];
    const float* Ws2 = (const float*)d_in[11];
    const float* bs2 = (const float*)d_in[12];
    const float* Wf1 = (const float*)d_in[13];
    const float* bf1 = (const float*)d_in[14];
    const float* gf1 = (const float*)d_in[15];
    const float* bef1= (const float*)d_in[16];
    const float* Wf2 = (const float*)d_in[17];
    const float* bf2 = (const float*)d_in[18];
    const float* gf2 = (const float*)d_in[19];
    const float* bef2= (const float*)d_in[20];
    const float* Wf3 = (const float*)d_in[21];
    const float* bf3 = (const float*)d_in[22];
    float* out = (float*)d_out;

    cudaFuncSetAttribute(k_front, cudaFuncAttributeMaxDynamicSharedMemorySize, FRONT_SMEM);
    cudaFuncSetAttribute(k_tail,  cudaFuncAttributeMaxDynamicSharedMemorySize, T_SMEM);

    // 1. KNN (256 blk) || feature+PQ (128 blk) || weight prep (24 blk)
    k_front<<<256 + 128 + 24, 512, FRONT_SMEM>>>(
        x, W1, b1, g1, be1, Ws1, bs1, Ws2, bs2, W2, Wf1, Wf2);

    // 2. gather + fusion1 + fusion2 + projection + residual, fully fused
    k_tail<<<NP/128, 512, T_SMEM>>>(b2, g2, be2, bf1, gf1, bef1,
                                    bf2, gf2, bef2, out, x, Wf3, bf3);
}